// round 8
// baseline (speedup 1.0000x reference)
#include <cuda_runtime.h>
#include <cuda_bf16.h>
#include <math.h>
#include <stdint.h>

// ---------------- consolidated scratch (single symbol, ~393MB) -------------
#define OFF_LN      0ull
#define OFF_QKV     6297600ull
#define OFF_ATT     25190400ull
#define OFF_RES     31488000ull
#define OFF_XT      37785600ull
#define OFF_BIAS    44077056ull
#define OFF_H       56684560ull
#define OFF_WBF     69270544ull
#define OFF_QB      79297552ull               // qkv bf16 hi/lo: 2*18,892,800 bf16
#define SCRATCH_TOTAL 98190352ull
__device__ float g_scratch[SCRATCH_TOTAL];

#define WO_TQKV  0u
#define WO_QKV   3538944u
#define WO_TPROJ 7077888u
#define WO_PROJ  8257536u
#define WO_TFC   9437184u
#define WO_FC1   10616832u
#define WO_FC2   15335424u

__device__ __forceinline__ float gelu_exact(float x){
    return 0.5f*x*(1.0f+erff(x*0.70710678118654752440f));
}

// ---------------- weight fp32 -> bf16 hi/lo conversion ---------------------
__global__ __launch_bounds__(256) void wconv_kernel(
    const float* __restrict__ w, __nv_bfloat16* __restrict__ hi,
    __nv_bfloat16* __restrict__ lo, int n)
{
    for (int i = blockIdx.x*256 + threadIdx.x; i < n; i += gridDim.x*256){
        float v = w[i];
        __nv_bfloat16 h = __float2bfloat16(v);
        hi[i] = h;
        lo[i] = __float2bfloat16(v - __bfloat162float(h));
    }
}

// ---------------- qkv fp32 -> bf16 hi/lo (0.125 folded into Q cols) --------
__global__ __launch_bounds__(256) void qkvconv_kernel(
    const float* __restrict__ q, __nv_bfloat16* __restrict__ hi,
    __nv_bfloat16* __restrict__ lo, int n)
{
    for (int i = blockIdx.x*256 + threadIdx.x; i < n; i += gridDim.x*256){
        int col = i % 2304;
        float v = q[i];
        if (col < 768) v *= 0.125f;
        __nv_bfloat16 h = __float2bfloat16(v);
        hi[i] = h;
        lo[i] = __float2bfloat16(v - __bfloat162float(h));
    }
}

// ---------------- HMMA (mma.sync) split-bf16 GEMM --------------------------
__device__ __forceinline__ void mma_bf16(float* d, const uint32_t* a, const uint32_t* b){
    asm volatile("mma.sync.aligned.m16n8k16.row.col.f32.bf16.bf16.f32 "
        "{%0,%1,%2,%3}, {%4,%5,%6,%7}, {%8,%9}, {%0,%1,%2,%3};"
        : "+f"(d[0]), "+f"(d[1]), "+f"(d[2]), "+f"(d[3])
        : "r"(a[0]), "r"(a[1]), "r"(a[2]), "r"(a[3]), "r"(b[0]), "r"(b[1]));
}

#define TG_SMEM (4*128*40*2)   // 40960 bytes

__global__ __launch_bounds__(256) void tgemm_nt(
    const float* __restrict__ A,
    const __nv_bfloat16* __restrict__ Whi, const __nv_bfloat16* __restrict__ Wlo,
    const float* __restrict__ bias, float* __restrict__ C,
    int M, int N, int K,
    const float* __restrict__ res, int resMode, int doGelu)
{
    extern __shared__ __nv_bfloat16 smem[];
    __nv_bfloat16* Ah = smem;               // [128][40]
    __nv_bfloat16* Al = smem + 5120;
    __nv_bfloat16* Bh = smem + 10240;
    __nv_bfloat16* Bl = smem + 15360;

    int tid = threadIdx.x;
    int wid = tid >> 5, lane = tid & 31;
    int warpM = wid >> 2, warpN = wid & 3;
    int g = lane >> 2, tg = lane & 3;
    int bm = blockIdx.y*128, bn = blockIdx.x*128;

    float acc[4][4][4];
    #pragma unroll
    for (int i=0;i<4;++i)
        #pragma unroll
        for (int j=0;j<4;++j)
            #pragma unroll
            for (int q=0;q<4;++q) acc[i][j][q]=0.f;

    int NC = K >> 5;
    for (int c = 0; c < NC; ++c){
        int k0 = c << 5;
        __syncthreads();
        #pragma unroll
        for (int u = 0; u < 4; ++u){
            int idx = u*256 + tid;
            int row = idx >> 3;
            int cq  = (idx & 7) << 2;
            int gm = bm + row;
            float4 v = (gm < M) ? *(const float4*)(A + (size_t)gm*K + k0 + cq)
                                : make_float4(0.f,0.f,0.f,0.f);
            __nv_bfloat16 hx=__float2bfloat16(v.x), hy=__float2bfloat16(v.y),
                          hz=__float2bfloat16(v.z), hw=__float2bfloat16(v.w);
            __nv_bfloat16 lx=__float2bfloat16(v.x-__bfloat162float(hx)),
                          ly=__float2bfloat16(v.y-__bfloat162float(hy)),
                          lz=__float2bfloat16(v.z-__bfloat162float(hz)),
                          lw=__float2bfloat16(v.w-__bfloat162float(hw));
            __nv_bfloat162 h01=__halves2bfloat162(hx,hy), h23=__halves2bfloat162(hz,hw);
            __nv_bfloat162 l01=__halves2bfloat162(lx,ly), l23=__halves2bfloat162(lz,lw);
            int e = row*40 + cq;
            *(__nv_bfloat162*)&Ah[e]   = h01;
            *(__nv_bfloat162*)&Ah[e+2] = h23;
            *(__nv_bfloat162*)&Al[e]   = l01;
            *(__nv_bfloat162*)&Al[e+2] = l23;
        }
        #pragma unroll
        for (int u = 0; u < 4; ++u){
            int idx = u*256 + tid;
            int sel = idx >> 9;
            int rem = idx & 511;
            int row = rem >> 2;
            int q = rem & 3;
            int gn = bn + row;
            const __nv_bfloat16* src = sel ? Wlo : Whi;
            uint4 v = *(const uint4*)(src + (size_t)gn*K + k0 + q*8);
            __nv_bfloat16* dst = sel ? Bl : Bh;
            *(uint4*)&dst[row*40 + q*8] = v;
        }
        __syncthreads();
        #pragma unroll
        for (int ks = 0; ks < 2; ++ks){
            int kb = ks*16 + tg*2;
            uint32_t ahi[4][4], alo[4][4];
            #pragma unroll
            for (int i=0;i<4;++i){
                int r0 = warpM*64 + i*16 + g;
                ahi[i][0] = *(const uint32_t*)&Ah[r0*40 + kb];
                ahi[i][1] = *(const uint32_t*)&Ah[(r0+8)*40 + kb];
                ahi[i][2] = *(const uint32_t*)&Ah[r0*40 + kb + 8];
                ahi[i][3] = *(const uint32_t*)&Ah[(r0+8)*40 + kb + 8];
                alo[i][0] = *(const uint32_t*)&Al[r0*40 + kb];
                alo[i][1] = *(const uint32_t*)&Al[(r0+8)*40 + kb];
                alo[i][2] = *(const uint32_t*)&Al[r0*40 + kb + 8];
                alo[i][3] = *(const uint32_t*)&Al[(r0+8)*40 + kb + 8];
            }
            uint32_t bhi[4][2], blo[4][2];
            #pragma unroll
            for (int j=0;j<4;++j){
                int n0 = warpN*32 + j*8 + g;
                bhi[j][0] = *(const uint32_t*)&Bh[n0*40 + kb];
                bhi[j][1] = *(const uint32_t*)&Bh[n0*40 + kb + 8];
                blo[j][0] = *(const uint32_t*)&Bl[n0*40 + kb];
                blo[j][1] = *(const uint32_t*)&Bl[n0*40 + kb + 8];
            }
            #pragma unroll
            for (int i=0;i<4;++i)
                #pragma unroll
                for (int j=0;j<4;++j){
                    mma_bf16(acc[i][j], ahi[i], bhi[j]);
                    mma_bf16(acc[i][j], ahi[i], blo[j]);
                    mma_bf16(acc[i][j], alo[i], bhi[j]);
                }
        }
    }

    #pragma unroll
    for (int i=0;i<4;++i){
        #pragma unroll
        for (int half=0; half<2; ++half){
            int m = bm + warpM*64 + i*16 + g + half*8;
            if (m >= M) continue;
            const float* rrow = nullptr;
            if (resMode == 1) rrow = res + (size_t)m*N;
            else if (resMode == 2){ int bb = m>>12, jj = m&4095; rrow = res + (size_t)(bb*4097+1+jj)*N; }
            float* crow = C + (size_t)m*N;
            #pragma unroll
            for (int j=0;j<4;++j){
                int n0 = bn + warpN*32 + j*8 + tg*2;
                float v0 = acc[i][j][half*2+0];
                float v1 = acc[i][j][half*2+1];
                if (bias){ float2 bv = *(const float2*)&bias[n0]; v0 += bv.x; v1 += bv.y; }
                if (doGelu){ v0 = gelu_exact(v0); v1 = gelu_exact(v1); }
                if (rrow){ float2 rv = *(const float2*)&rrow[n0]; v0 += rv.x; v1 += rv.y; }
                *(float2*)&crow[n0] = make_float2(v0, v1);
            }
        }
    }
}

// ---------------- HMMA flash attention -------------------------------------
// grid (9, 96): i-tile 128 rows, 8 warps each owning a 16-row m16 band.
// j-tiles of 64.  QK^T and P@V via m16n8k16 bf16, 3-product hi/lo split.
#define FP 72   // padded row length (bf16) -> 144B, conflict-free frags
#define FL_SMEM ((2*128*FP + 4*64*FP)*2)

__global__ __launch_bounds__(256) void flash_mma_kernel(
    const __nv_bfloat16* __restrict__ qh, const __nv_bfloat16* __restrict__ ql,
    const float* __restrict__ bias, float* __restrict__ out)
{
    extern __shared__ __nv_bfloat16 fsm[];
    __nv_bfloat16* Qh = fsm;                 // [128][FP]
    __nv_bfloat16* Ql = Qh + 128*FP;
    __nv_bfloat16* Kh = Ql + 128*FP;         // [64][FP]  (j rows, d cols)
    __nv_bfloat16* Kl = Kh + 64*FP;
    __nv_bfloat16* Vh = Kl + 64*FP;          // [64][FP]  transposed: d rows, j cols
    __nv_bfloat16* Vl = Vh + 64*FP;

    int bh = blockIdx.y; int bt = bh/12, h = bh - bt*12;
    int i0 = blockIdx.x*128;
    int tid = threadIdx.x;
    int w = tid >> 5, lane = tid & 31;
    int g = lane >> 2, tg = lane & 3;
    size_t qkvbase = (size_t)(bt*1025)*2304u + h*64;

    // ---- stage Q (hi & lo), guarded ----
    {
        int r = tid >> 1, d0 = (tid & 1)*32;
        int gi = i0 + r;
        __nv_bfloat16* dh = &Qh[r*FP + d0];
        __nv_bfloat16* dl = &Ql[r*FP + d0];
        if (gi < 1025){
            const __nv_bfloat16* sh = qh + qkvbase + (size_t)gi*2304u + d0;
            const __nv_bfloat16* sl = ql + qkvbase + (size_t)gi*2304u + d0;
            #pragma unroll
            for (int q=0;q<4;++q){
                *(uint4*)(dh + q*8) = *(const uint4*)(sh + q*8);
                *(uint4*)(dl + q*8) = *(const uint4*)(sl + q*8);
            }
        } else {
            uint4 z = make_uint4(0,0,0,0);
            #pragma unroll
            for (int q=0;q<4;++q){ *(uint4*)(dh + q*8) = z; *(uint4*)(dl + q*8) = z; }
        }
    }

    float m0=-1e30f, m1=-1e30f, l0=0.f, l1=0.f;
    float o[8][4];
    #pragma unroll
    for (int d=0;d<8;++d){ o[d][0]=0.f;o[d][1]=0.f;o[d][2]=0.f;o[d][3]=0.f; }

    int gi_g = i0 + w*16 + g;
    int gi_h = gi_g + 8;
    const float* brow0 = bias + ((size_t)h*1025u + gi_g)*1025u;
    const float* brow1 = bias + ((size_t)h*1025u + gi_h)*1025u;

    for (int j0 = 0; j0 < 1025; j0 += 64){
        __syncthreads();
        // ---- stage K [j][d] (hi/lo) ----
        {
            int j = tid >> 2, d0 = (tid & 3)*16;
            int gj = j0 + j;
            __nv_bfloat16* dh = &Kh[j*FP + d0];
            __nv_bfloat16* dl = &Kl[j*FP + d0];
            if (gj < 1025){
                const __nv_bfloat16* sh = qh + qkvbase + (size_t)gj*2304u + 768u + d0;
                const __nv_bfloat16* sl = ql + qkvbase + (size_t)gj*2304u + 768u + d0;
                *(uint4*)(dh)   = *(const uint4*)(sh);
                *(uint4*)(dh+8) = *(const uint4*)(sh+8);
                *(uint4*)(dl)   = *(const uint4*)(sl);
                *(uint4*)(dl+8) = *(const uint4*)(sl+8);
            } else {
                uint4 z = make_uint4(0,0,0,0);
                *(uint4*)(dh)=z; *(uint4*)(dh+8)=z; *(uint4*)(dl)=z; *(uint4*)(dl+8)=z;
            }
        }
        // ---- stage V transposed [d][j] (hi/lo) ----
        {
            int j = tid & 63, dblk = (tid >> 6)*16;
            int gj = j0 + j;
            if (gj < 1025){
                const __nv_bfloat16* sh = qh + qkvbase + (size_t)gj*2304u + 1536u + dblk;
                const __nv_bfloat16* sl = ql + qkvbase + (size_t)gj*2304u + 1536u + dblk;
                __nv_bfloat16 th[16], tl[16];
                *(uint4*)&th[0] = *(const uint4*)(sh);
                *(uint4*)&th[8] = *(const uint4*)(sh+8);
                *(uint4*)&tl[0] = *(const uint4*)(sl);
                *(uint4*)&tl[8] = *(const uint4*)(sl+8);
                #pragma unroll
                for (int q=0;q<16;++q){
                    Vh[(dblk+q)*FP + j] = th[q];
                    Vl[(dblk+q)*FP + j] = tl[q];
                }
            } else {
                __nv_bfloat16 z = __float2bfloat16(0.f);
                #pragma unroll
                for (int q=0;q<16;++q){
                    Vh[(dblk+q)*FP + j] = z;
                    Vl[(dblk+q)*FP + j] = z;
                }
            }
        }
        __syncthreads();

        // ---- S = Q @ K^T (3-product split) ----
        float s[8][4];
        #pragma unroll
        for (int nf=0;nf<8;++nf){ s[nf][0]=0.f;s[nf][1]=0.f;s[nf][2]=0.f;s[nf][3]=0.f; }
        #pragma unroll
        for (int kf=0; kf<4; ++kf){
            int kb = kf*16 + tg*2;
            const __nv_bfloat16* qr = &Qh[(w*16+g)*FP + kb];
            uint32_t ah[4], al[4];
            ah[0] = *(const uint32_t*)(qr);
            ah[1] = *(const uint32_t*)(qr + 8*FP);
            ah[2] = *(const uint32_t*)(qr + 8);
            ah[3] = *(const uint32_t*)(qr + 8*FP + 8);
            al[0] = *(const uint32_t*)(qr + 128*FP);
            al[1] = *(const uint32_t*)(qr + 136*FP);
            al[2] = *(const uint32_t*)(qr + 128*FP + 8);
            al[3] = *(const uint32_t*)(qr + 136*FP + 8);
            #pragma unroll
            for (int nf=0;nf<8;++nf){
                const __nv_bfloat16* kr = &Kh[(nf*8+g)*FP + kb];
                uint32_t bhv[2], blv[2];
                bhv[0] = *(const uint32_t*)(kr);
                bhv[1] = *(const uint32_t*)(kr + 8);
                blv[0] = *(const uint32_t*)(kr + 64*FP);
                blv[1] = *(const uint32_t*)(kr + 64*FP + 8);
                mma_bf16(s[nf], ah, bhv);
                mma_bf16(s[nf], ah, blv);
                mma_bf16(s[nf], al, bhv);
            }
        }
        // ---- bias + mask ----
        #pragma unroll
        for (int nf=0;nf<8;++nf){
            int gj = j0 + nf*8 + tg*2;
            if (gi_g < 1025 && gj   < 1025) s[nf][0] += brow0[gj];   else s[nf][0] = -1e30f;
            if (gi_g < 1025 && gj+1 < 1025) s[nf][1] += brow0[gj+1]; else s[nf][1] = -1e30f;
            if (gi_h < 1025 && gj   < 1025) s[nf][2] += brow1[gj];   else s[nf][2] = -1e30f;
            if (gi_h < 1025 && gj+1 < 1025) s[nf][3] += brow1[gj+1]; else s[nf][3] = -1e30f;
        }
        // ---- online softmax (warp-local; rows g and g+8) ----
        float rm0 = -1e30f, rm1 = -1e30f;
        #pragma unroll
        for (int nf=0;nf<8;++nf){
            rm0 = fmaxf(rm0, fmaxf(s[nf][0], s[nf][1]));
            rm1 = fmaxf(rm1, fmaxf(s[nf][2], s[nf][3]));
        }
        rm0 = fmaxf(rm0, __shfl_xor_sync(0xffffffffu, rm0, 1));
        rm0 = fmaxf(rm0, __shfl_xor_sync(0xffffffffu, rm0, 2));
        rm1 = fmaxf(rm1, __shfl_xor_sync(0xffffffffu, rm1, 1));
        rm1 = fmaxf(rm1, __shfl_xor_sync(0xffffffffu, rm1, 2));
        float mn0 = fmaxf(m0, rm0), mn1 = fmaxf(m1, rm1);
        float c0 = __expf(m0 - mn0), c1 = __expf(m1 - mn1);
        m0 = mn0; m1 = mn1;
        float sum0 = 0.f, sum1 = 0.f;
        #pragma unroll
        for (int nf=0;nf<8;++nf){
            s[nf][0] = __expf(s[nf][0]-mn0);
            s[nf][1] = __expf(s[nf][1]-mn0);
            s[nf][2] = __expf(s[nf][2]-mn1);
            s[nf][3] = __expf(s[nf][3]-mn1);
            sum0 += s[nf][0] + s[nf][1];
            sum1 += s[nf][2] + s[nf][3];
        }
        sum0 += __shfl_xor_sync(0xffffffffu, sum0, 1);
        sum0 += __shfl_xor_sync(0xffffffffu, sum0, 2);
        sum1 += __shfl_xor_sync(0xffffffffu, sum1, 1);
        sum1 += __shfl_xor_sync(0xffffffffu, sum1, 2);
        l0 = l0*c0 + sum0;
        l1 = l1*c1 + sum1;
        #pragma unroll
        for (int d=0;d<8;++d){ o[d][0]*=c0; o[d][1]*=c0; o[d][2]*=c1; o[d][3]*=c1; }

        // ---- O += P @ V (3-product split; P fragments direct from S) ----
        #pragma unroll
        for (int kk=0; kk<4; ++kk){
            uint32_t pah[4], pal[4];
            #pragma unroll
            for (int half=0; half<2; ++half){
                int nf = kk*2 + half;
                float p0 = s[nf][0], p1 = s[nf][1], p2 = s[nf][2], p3 = s[nf][3];
                __nv_bfloat16 h0=__float2bfloat16(p0), h1=__float2bfloat16(p1),
                              h2=__float2bfloat16(p2), h3=__float2bfloat16(p3);
                __nv_bfloat162 ph01=__halves2bfloat162(h0,h1);
                __nv_bfloat162 ph23=__halves2bfloat162(h2,h3);
                __nv_bfloat162 pl01=__halves2bfloat162(
                    __float2bfloat16(p0-__bfloat162float(h0)),
                    __float2bfloat16(p1-__bfloat162float(h1)));
                __nv_bfloat162 pl23=__halves2bfloat162(
                    __float2bfloat16(p2-__bfloat162float(h2)),
                    __float2bfloat16(p3-__bfloat162float(h3)));
                pah[half*2+0] = *(uint32_t*)&ph01;
                pah[half*2+1] = *(uint32_t*)&ph23;
                pal[half*2+0] = *(uint32_t*)&pl01;
                pal[half*2+1] = *(uint32_t*)&pl23;
            }
            // reorder: a = {nf0.c01, nf0.c23, nf1.c01, nf1.c23}
            int kb = kk*16 + tg*2;
            #pragma unroll
            for (int df=0; df<8; ++df){
                const __nv_bfloat16* vr = &Vh[(df*8+g)*FP + kb];
                uint32_t bhv[2], blv[2];
                bhv[0] = *(const uint32_t*)(vr);
                bhv[1] = *(const uint32_t*)(vr + 8);
                blv[0] = *(const uint32_t*)(vr + 64*FP);
                blv[1] = *(const uint32_t*)(vr + 64*FP + 8);
                mma_bf16(o[df], pah, bhv);
                mma_bf16(o[df], pah, blv);
                mma_bf16(o[df], pal, bhv);
            }
        }
    }

    // ---- store ----
    float inv0 = 1.0f/l0, inv1 = 1.0f/l1;
    #pragma unroll
    for (int df=0; df<8; ++df){
        int d0 = df*8 + tg*2;
        if (gi_g < 1025)
            *(float2*)&out[(size_t)(bt*1025+gi_g)*768u + h*64 + d0]
                = make_float2(o[df][0]*inv0, o[df][1]*inv0);
        if (gi_h < 1025)
            *(float2*)&out[(size_t)(bt*1025+gi_h)*768u + h*64 + d0]
                = make_float2(o[df][2]*inv1, o[df][3]*inv1);
    }
}

// ---------------- layernorm with gather modes ------------------------------
__global__ __launch_bounds__(256) void ln_kernel(
    const float* __restrict__ src, const float* __restrict__ xsrc,
    float* __restrict__ dst, const float* __restrict__ g, const float* __restrict__ b,
    int mode)
{
    __shared__ float red[8];
    int r = blockIdx.x;
    int t = threadIdx.x;
    int lane = t & 31, warp = t >> 5;
    const float* in; size_t base;
    if (mode == 0){ in = src; base = (size_t)r*768u; }
    else if (mode == 1){ int bb = r>>12; int j = r & 4095; in = xsrc; base = (size_t)(bb*4097 + 1 + j)*768u; }
    else {
        int bt = r/1025, pos = r - bt*1025;
        int bb = bt>>2, tt = bt&3;
        if (pos == 0){ in = xsrc; base = (size_t)(bb*4097)*768u; }
        else { int n = pos-1; in = src; base = (size_t)(bb*4096 + n*4 + tt)*768u; }
    }
    float v0 = in[base+t], v1 = in[base+t+256], v2 = in[base+t+512];
    float s = v0+v1+v2;
    #pragma unroll
    for (int o=16;o>0;o>>=1) s += __shfl_xor_sync(0xffffffffu, s, o);
    if (lane==0) red[warp]=s;
    __syncthreads();
    if (warp==0){
        float w = red[lane&7];
        #pragma unroll
        for (int o=4;o>0;o>>=1) w += __shfl_xor_sync(0xffffffffu, w, o);
        if (lane==0) red[0]=w;
    }
    __syncthreads();
    float mean = red[0]*(1.0f/768.0f);
    float d0=v0-mean, d1=v1-mean, d2=v2-mean;
    float q = d0*d0+d1*d1+d2*d2;
    #pragma unroll
    for (int o=16;o>0;o>>=1) q += __shfl_xor_sync(0xffffffffu, q, o);
    __syncthreads();
    if (lane==0) red[warp]=q;
    __syncthreads();
    if (warp==0){
        float w = red[lane&7];
        #pragma unroll
        for (int o=4;o>0;o>>=1) w += __shfl_xor_sync(0xffffffffu, w, o);
        if (lane==0) red[0]=w;
    }
    __syncthreads();
    float var = red[0]*(1.0f/768.0f);
    float rstd = rsqrtf(var + 1e-5f);
    size_t ob = (size_t)r*768u;
    dst[ob+t]     = d0*rstd*g[t]     + b[t];
    dst[ob+t+256] = d1*rstd*g[t+256] + b[t+256];
    dst[ob+t+512] = d2*rstd*g[t+512] + b[t+512];
}

// ---------------- geometry bias -------------------------------------------
__global__ __launch_bounds__(256) void bias_kernel(
    const float* __restrict__ wg_w, const float* __restrict__ wg_b,
    float* __restrict__ bias)
{
    __shared__ float sw[768];
    __shared__ float sc[12];
    int t = threadIdx.x;
    for (int i=t;i<768;i+=256) sw[i]=wg_w[i];
    __syncthreads();
    if (t < 12){
        float s = wg_b[t];
        #pragma unroll
        for (int k=48;k<64;++k) s += sw[t*64+k];
        sc[t] = s;
    }
    __syncthreads();
    size_t idx = (size_t)blockIdx.x*256u + t;
    if (idx >= (size_t)1025u*1025u) return;
    int i = (int)(idx/1025u), j = (int)(idx - (size_t)i*1025u);
    if (i==0 || j==0){
        #pragma unroll
        for (int h=0;h<12;++h) bias[(size_t)h*1025u*1025u + idx] = 0.f;
        return;
    }
    int a = i-1, b2 = j-1;
    float fx = (float)((a>>5)-(b2>>5)) * (1.0f/32.0f);
    float fy = (float)((a&31)-(b2&31)) * (1.0f/32.0f);
    const float inv_wbox = 1.0f/1.03125f;
    float dx = logf(fmaxf(fabsf(fx*inv_wbox), 0.001f));
    float dy = logf(fmaxf(fabsf(fy*inv_wbox), 0.001f));
    const float dm[8] = {1.0f, 0.42169650342f, 0.1778279410f, 0.074989420933f,
                         0.03162277660f, 0.013335214322f, 0.0056234132519f, 0.0023713737057f};
    float sx[8], cx[8], sy[8], cy[8];
    #pragma unroll
    for (int k=0;k<8;++k){
        sincosf(100.0f*dx*dm[k], &sx[k], &cx[k]);
        sincosf(100.0f*dy*dm[k], &sy[k], &cy[k]);
    }
    #pragma unroll
    for (int h=0;h<12;++h){
        const float* w = sw + h*64;
        float acc = sc[h];
        #pragma unroll
        for (int k=0;k<8;++k)
            acc += sx[k]*w[k] + sy[k]*w[8+k] + cx[k]*w[32+k] + cy[k]*w[40+k];
        float wv = fmaxf(acc, 0.0f);
        bias[(size_t)h*1025u*1025u + idx] = logf(fmaxf(wv, 1e-6f));
    }
}

// ---------------- temporal attention (T=4) ---------------------------------
__global__ __launch_bounds__(256) void temporal_attn_kernel(
    const float* __restrict__ qkv, float* __restrict__ out)
{
    int gw = (blockIdx.x*256 + threadIdx.x) >> 5;
    int lane = threadIdx.x & 31;
    if (gw >= 2048*12) return;
    int s = gw/12, h = gw - s*12;
    size_t base = (size_t)(s*4)*2304u + h*64 + lane*2;
    float2 q[4],k[4],v[4];
    #pragma unroll
    for (int i=0;i<4;++i){
        q[i] = *(const float2*)(qkv + base + (size_t)i*2304u);
        k[i] = *(const float2*)(qkv + base + (size_t)i*2304u + 768u);
        v[i] = *(const float2*)(qkv + base + (size_t)i*2304u + 1536u);
    }
    float sc[16];
    #pragma unroll
    for (int i=0;i<4;++i)
        #pragma unroll
        for (int j=0;j<4;++j)
            sc[i*4+j] = q[i].x*k[j].x + q[i].y*k[j].y;
    #pragma unroll
    for (int t2=0;t2<16;++t2)
        #pragma unroll
        for (int off=16; off>0; off>>=1)
            sc[t2] += __shfl_xor_sync(0xffffffffu, sc[t2], off);
    #pragma unroll
    for (int i=0;i<4;++i){
        float s0=sc[i*4+0]*0.125f, s1=sc[i*4+1]*0.125f, s2=sc[i*4+2]*0.125f, s3=sc[i*4+3]*0.125f;
        float m = fmaxf(fmaxf(s0,s1),fmaxf(s2,s3));
        float e0=expf(s0-m), e1=expf(s1-m), e2=expf(s2-m), e3=expf(s3-m);
        float inv = 1.0f/(e0+e1+e2+e3);
        float ox = (e0*v[0].x + e1*v[1].x + e2*v[2].x + e3*v[3].x)*inv;
        float oy = (e0*v[0].y + e1*v[1].y + e2*v[2].y + e3*v[3].y)*inv;
        float2 o; o.x = ox; o.y = oy;
        *(float2*)(out + (size_t)(s*4+i)*768u + h*64 + lane*2) = o;
    }
}

// ---------------- combine -------------------------------------------------
__global__ __launch_bounds__(256) void combine_kernel(
    const float* __restrict__ x, const float* __restrict__ xt,
    const float* __restrict__ res_s, float* __restrict__ out)
{
    size_t idx = (size_t)blockIdx.x*256u + threadIdx.x;
    if (idx >= (size_t)2u*4097u*768u) return;
    int c = (int)(idx % 768u);
    size_t row = idx / 768u;
    int b = (int)(row / 4097u);
    int rr = (int)(row - (size_t)b*4097u);
    float v;
    if (rr == 0){
        float s = 0.f;
        #pragma unroll
        for (int t2=0;t2<4;++t2)
            s += res_s[((size_t)((b*4+t2)*1025))*768u + c];
        v = x[row*768u + c] + 0.25f*s;
    } else {
        int qq = rr-1; int n = qq>>2, t2 = qq&3;
        v = xt[((size_t)(b*4096 + qq))*768u + c]
          + res_s[((size_t)((b*4+t2)*1025 + 1 + n))*768u + c];
    }
    out[row*768u + c] = v;
}

// ---------------- launcher -------------------------------------------------
extern "C" void kernel_launch(void* const* d_in, const int* in_sizes, int n_in,
                              void* d_out, int out_size)
{
    const float* x       = (const float*)d_in[0];
    const float* norm1_g = (const float*)d_in[1];
    const float* norm1_b = (const float*)d_in[2];
    const float* qkv_w   = (const float*)d_in[3];
    const float* proj_w  = (const float*)d_in[4];
    const float* proj_b  = (const float*)d_in[5];
    const float* wg_w    = (const float*)d_in[6];
    const float* wg_b    = (const float*)d_in[7];
    const float* tnorm1_g= (const float*)d_in[8];
    const float* tnorm1_b= (const float*)d_in[9];
    const float* tqkv_w  = (const float*)d_in[10];
    const float* tproj_w = (const float*)d_in[11];
    const float* tproj_b = (const float*)d_in[12];
    const float* tfc_w   = (const float*)d_in[13];
    const float* tfc_b   = (const float*)d_in[14];
    const float* norm2_g = (const float*)d_in[15];
    const float* norm2_b = (const float*)d_in[16];
    const float* fc1_w   = (const float*)d_in[17];
    const float* fc1_b   = (const float*)d_in[18];
    const float* fc2_w   = (const float*)d_in[19];
    const float* fc2_b   = (const float*)d_in[20];
    float* out = (float*)d_out;

    float* base = nullptr;
    cudaGetSymbolAddress((void**)&base, g_scratch);
    float* p_ln   = base + OFF_LN;
    float* p_qkv  = base + OFF_QKV;
    float* p_att  = base + OFF_ATT;
    float* p_res  = base + OFF_RES;
    float* p_xt   = base + OFF_XT;
    float* p_bias = base + OFF_BIAS;
    float* p_h    = base + OFF_H;
    __nv_bfloat16* wb  = (__nv_bfloat16*)(base + OFF_WBF);
    __nv_bfloat16* qbh = (__nv_bfloat16*)(base + OFF_QB);
    __nv_bfloat16* qbl = qbh + 18892800u;

    cudaFuncSetAttribute(flash_mma_kernel,
                         cudaFuncAttributeMaxDynamicSharedMemorySize, FL_SMEM);

    // ---- weight bf16 hi/lo conversion ----
    wconv_kernel<<<1024,256>>>(tqkv_w, wb+WO_TQKV, wb+WO_TQKV+1769472u, 1769472);
    wconv_kernel<<<1024,256>>>(qkv_w,  wb+WO_QKV,  wb+WO_QKV +1769472u, 1769472);
    wconv_kernel<<<512,256>>>(tproj_w, wb+WO_TPROJ,wb+WO_TPROJ+589824u, 589824);
    wconv_kernel<<<512,256>>>(proj_w,  wb+WO_PROJ, wb+WO_PROJ +589824u, 589824);
    wconv_kernel<<<512,256>>>(tfc_w,   wb+WO_TFC,  wb+WO_TFC  +589824u, 589824);
    wconv_kernel<<<1024,256>>>(fc1_w,  wb+WO_FC1,  wb+WO_FC1 +2359296u, 2359296);
    wconv_kernel<<<1024,256>>>(fc2_w,  wb+WO_FC2,  wb+WO_FC2 +2359296u, 2359296);

    // ---- temporal branch ----
    ln_kernel<<<8192,256>>>(nullptr, x, p_ln, tnorm1_g, tnorm1_b, 1);
    tgemm_nt<<<dim3(18,64),256,TG_SMEM>>>(p_ln, wb+WO_TQKV, wb+WO_TQKV+1769472u, nullptr, p_qkv, 8192, 2304, 768, nullptr, 0, 0);
    temporal_attn_kernel<<<3072,256>>>(p_qkv, p_att);
    tgemm_nt<<<dim3(6,64),256,TG_SMEM>>>(p_att, wb+WO_TPROJ, wb+WO_TPROJ+589824u, tproj_b, p_res, 8192, 768, 768, nullptr, 0, 0);
    tgemm_nt<<<dim3(6,64),256,TG_SMEM>>>(p_res, wb+WO_TFC, wb+WO_TFC+589824u, tfc_b, p_xt, 8192, 768, 768, x, 2, 0);

    // ---- spatial branch ----
    ln_kernel<<<8200,256>>>(p_xt, x, p_ln, norm1_g, norm1_b, 2);
    tgemm_nt<<<dim3(18,65),256,TG_SMEM>>>(p_ln, wb+WO_QKV, wb+WO_QKV+1769472u, nullptr, p_qkv, 8200, 2304, 768, nullptr, 0, 0);
    bias_kernel<<<4105,256>>>(wg_w, wg_b, p_bias);
    qkvconv_kernel<<<4096,256>>>(p_qkv, qbh, qbl, 18892800);
    flash_mma_kernel<<<dim3(9,96),256,FL_SMEM>>>(qbh, qbl, p_bias, p_att);
    tgemm_nt<<<dim3(6,65),256,TG_SMEM>>>(p_att, wb+WO_PROJ, wb+WO_PROJ+589824u, proj_b, p_res, 8200, 768, 768, nullptr, 0, 0);
    combine_kernel<<<24582,256>>>(x, p_xt, p_res, out);

    // ---- MLP (chunked over 2x4097 rows) ----
    ln_kernel<<<8194,256>>>(out, nullptr, p_ln, norm2_g, norm2_b, 0);
    for (int ch=0; ch<2; ++ch){
        size_t ro = (size_t)ch*4097u;
        tgemm_nt<<<dim3(24,33),256,TG_SMEM>>>(p_ln + ro*768u, wb+WO_FC1, wb+WO_FC1+2359296u, fc1_b, p_h, 4097, 3072, 768, nullptr, 0, 1);
        tgemm_nt<<<dim3(6,33),256,TG_SMEM>>>(p_h, wb+WO_FC2, wb+WO_FC2+2359296u, fc2_b, out + ro*768u, 4097, 768, 3072, out + ro*768u, 1, 0);
    }
}

// round 9
// speedup vs baseline: 1.4055x; 1.4055x over previous
#include <cuda_runtime.h>
#include <cuda_bf16.h>
#include <math.h>
#include <stdint.h>

// ---------------- consolidated scratch (single symbol, ~342MB) -------------
#define OFF_QKV   0ull                       // 18,892,800 f32
#define OFF_XT    18892800ull                // 6,291,456 f32
#define OFF_RES   25184256ull                // 6,297,600 f32
#define OFF_BIAS  31481856ull                // 12,607,504 f32
#define OFF_WBF   44089360ull                // 10,027,008 f32 (weights bf16 h/l)
#define OFF_BF    54116368ull                // activation bf16 region
#define SCRATCH_TOTAL 85589008ull
__device__ float g_scratch[SCRATCH_TOTAL];

// bf16 activation offsets (in bf16 elements within OFF_BF region)
#define BO_LNH   0u
#define BO_LNL   6297600u
#define BO_ATTH  12595200u
#define BO_ATTL  18892800u
#define BO_R2H   25190400u
#define BO_R2L   31481856u
#define BO_HH    37773312u
#define BO_HL    50359296u

// weight offsets (bf16 elements; hi then lo contiguous)
#define WO_TQKV  0u
#define WO_QKV   3538944u
#define WO_TPROJ 7077888u
#define WO_PROJ  8257536u
#define WO_TFC   9437184u
#define WO_FC1   10616832u
#define WO_FC2   15335424u

__device__ __forceinline__ float gelu_exact(float x){
    return 0.5f*x*(1.0f+erff(x*0.70710678118654752440f));
}
__device__ __forceinline__ void split2(float a, float b, uint32_t &h, uint32_t &l){
    __nv_bfloat16 ha=__float2bfloat16(a), hb=__float2bfloat16(b);
    __nv_bfloat162 hh=__halves2bfloat162(ha,hb);
    __nv_bfloat162 ll=__halves2bfloat162(
        __float2bfloat16(a-__bfloat162float(ha)),
        __float2bfloat16(b-__bfloat162float(hb)));
    h=*(uint32_t*)&hh; l=*(uint32_t*)&ll;
}
__device__ __forceinline__ uint32_t smem_u32(const void* p){
    uint32_t a;
    asm("{ .reg .u64 t; cvta.to.shared.u64 t, %1; cvt.u32.u64 %0, t; }" : "=r"(a) : "l"(p));
    return a;
}
__device__ __forceinline__ void cp16(uint32_t dst, const void* src, int valid){
    int sz = valid ? 16 : 0;
    asm volatile("cp.async.ca.shared.global [%0], [%1], 16, %2;"
                 :: "r"(dst), "l"(src), "r"(sz) : "memory");
}
__device__ __forceinline__ void cp_commit(){ asm volatile("cp.async.commit_group;" ::: "memory"); }
__device__ __forceinline__ void cp_wait1(){ asm volatile("cp.async.wait_group 1;" ::: "memory"); }
__device__ __forceinline__ void cp_wait0(){ asm volatile("cp.async.wait_group 0;" ::: "memory"); }

// ---------------- weight fp32 -> bf16 hi/lo conversion ---------------------
__global__ __launch_bounds__(256) void wconv_kernel(
    const float* __restrict__ w, __nv_bfloat16* __restrict__ hi,
    __nv_bfloat16* __restrict__ lo, int n)
{
    for (int i = blockIdx.x*256 + threadIdx.x; i < n; i += gridDim.x*256){
        float v = w[i];
        __nv_bfloat16 h = __float2bfloat16(v);
        hi[i] = h;
        lo[i] = __float2bfloat16(v - __bfloat162float(h));
    }
}

// ---------------- HMMA (mma.sync) split-bf16 GEMM, cp.async pipelined ------
__device__ __forceinline__ void mma_bf16(float* d, const uint32_t* a, const uint32_t* b){
    asm volatile("mma.sync.aligned.m16n8k16.row.col.f32.bf16.bf16.f32 "
        "{%0,%1,%2,%3}, {%4,%5,%6,%7}, {%8,%9}, {%0,%1,%2,%3};"
        : "+f"(d[0]), "+f"(d[1]), "+f"(d[2]), "+f"(d[3])
        : "r"(a[0]), "r"(a[1]), "r"(a[2]), "r"(a[3]), "r"(b[0]), "r"(b[1]));
}

#define TG_BUF   40960               // one buffer: Ah|Al|Bh|Bl, each 128x40 bf16
#define TG_SMEM  (2*TG_BUF)          // 81920 bytes, double buffered

__global__ __launch_bounds__(256) void tgemm_nt(
    const __nv_bfloat16* __restrict__ Ahi, const __nv_bfloat16* __restrict__ Alo,
    const __nv_bfloat16* __restrict__ Whi, const __nv_bfloat16* __restrict__ Wlo,
    const float* __restrict__ bias,
    float* __restrict__ C, __nv_bfloat16* __restrict__ Chi, __nv_bfloat16* __restrict__ Clo,
    int M, int N, int K,
    const float* __restrict__ res, int resMode, int doGelu)
{
    extern __shared__ char smem[];
    uint32_t sb = smem_u32(smem);
    int tid = threadIdx.x;
    int wid = tid >> 5, lane = tid & 31;
    int warpM = wid >> 2, warpN = wid & 3;
    int g = lane >> 2, tg = lane & 3;
    int bm = blockIdx.y*128, bn = blockIdx.x*128;

    // staging map: 2048 cp16 per chunk, 8 per thread
    // idx: arr(2b) | row(7b) | q(2b);  arr: 0=Ah 1=Al 2=Bh 3=Bl
    int NC = K >> 5;

    auto stage = [&](int c, int buf){
        int k0 = c << 5;
        uint32_t bufb = sb + buf*TG_BUF;
        #pragma unroll
        for (int u = 0; u < 8; ++u){
            int idx = u*256 + tid;
            int arr = idx >> 9;
            int rem = idx & 511;
            int row = rem >> 2;
            int q = rem & 3;
            uint32_t dst = bufb + arr*10240 + row*80 + q*16;
            const __nv_bfloat16* src;
            int valid = 1;
            if (arr < 2){
                int gm = bm + row;
                valid = (gm < M);
                const __nv_bfloat16* base = (arr == 0) ? Ahi : Alo;
                src = base + (size_t)(valid ? gm : 0)*K + k0 + q*8;
            } else {
                int gn = bn + row;
                const __nv_bfloat16* base = (arr == 2) ? Whi : Wlo;
                src = base + (size_t)gn*K + k0 + q*8;
            }
            cp16(dst, src, valid);
        }
        cp_commit();
    };

    float acc[4][4][4];
    #pragma unroll
    for (int i=0;i<4;++i)
        #pragma unroll
        for (int j=0;j<4;++j)
            #pragma unroll
            for (int q=0;q<4;++q) acc[i][j][q]=0.f;

    stage(0, 0);
    for (int c = 0; c < NC; ++c){
        int buf = c & 1;
        if (c+1 < NC){ stage(c+1, buf^1); cp_wait1(); }
        else cp_wait0();
        __syncthreads();

        const __nv_bfloat16* Ah = (const __nv_bfloat16*)(smem + buf*TG_BUF);
        const __nv_bfloat16* Al = Ah + 5120;
        const __nv_bfloat16* Bh = Ah + 10240;
        const __nv_bfloat16* Bl = Ah + 15360;

        #pragma unroll
        for (int ks = 0; ks < 2; ++ks){
            int kb = ks*16 + tg*2;
            uint32_t ahi[4][4], alo[4][4];
            #pragma unroll
            for (int i=0;i<4;++i){
                int r0 = warpM*64 + i*16 + g;
                ahi[i][0] = *(const uint32_t*)&Ah[r0*40 + kb];
                ahi[i][1] = *(const uint32_t*)&Ah[(r0+8)*40 + kb];
                ahi[i][2] = *(const uint32_t*)&Ah[r0*40 + kb + 8];
                ahi[i][3] = *(const uint32_t*)&Ah[(r0+8)*40 + kb + 8];
                alo[i][0] = *(const uint32_t*)&Al[r0*40 + kb];
                alo[i][1] = *(const uint32_t*)&Al[(r0+8)*40 + kb];
                alo[i][2] = *(const uint32_t*)&Al[r0*40 + kb + 8];
                alo[i][3] = *(const uint32_t*)&Al[(r0+8)*40 + kb + 8];
            }
            uint32_t bhi[4][2], blo[4][2];
            #pragma unroll
            for (int j=0;j<4;++j){
                int n0 = warpN*32 + j*8 + g;
                bhi[j][0] = *(const uint32_t*)&Bh[n0*40 + kb];
                bhi[j][1] = *(const uint32_t*)&Bh[n0*40 + kb + 8];
                blo[j][0] = *(const uint32_t*)&Bl[n0*40 + kb];
                blo[j][1] = *(const uint32_t*)&Bl[n0*40 + kb + 8];
            }
            #pragma unroll
            for (int i=0;i<4;++i)
                #pragma unroll
                for (int j=0;j<4;++j){
                    mma_bf16(acc[i][j], ahi[i], bhi[j]);
                    mma_bf16(acc[i][j], ahi[i], blo[j]);
                    mma_bf16(acc[i][j], alo[i], bhi[j]);
                }
        }
        __syncthreads();
    }

    // ---- epilogue ----
    #pragma unroll
    for (int i=0;i<4;++i){
        #pragma unroll
        for (int half=0; half<2; ++half){
            int m = bm + warpM*64 + i*16 + g + half*8;
            if (m >= M) continue;
            const float* rrow = nullptr;
            if (resMode == 1) rrow = res + (size_t)m*N;
            else if (resMode == 2){ int bb = m>>12, jj = m&4095; rrow = res + (size_t)(bb*4097+1+jj)*N; }
            #pragma unroll
            for (int j=0;j<4;++j){
                int n0 = bn + warpN*32 + j*8 + tg*2;
                float v0 = acc[i][j][half*2+0];
                float v1 = acc[i][j][half*2+1];
                if (bias){ float2 bv = *(const float2*)&bias[n0]; v0 += bv.x; v1 += bv.y; }
                if (doGelu){ v0 = gelu_exact(v0); v1 = gelu_exact(v1); }
                if (rrow){ float2 rv = *(const float2*)&rrow[n0]; v0 += rv.x; v1 += rv.y; }
                if (Chi){
                    uint32_t hh, ll;
                    split2(v0, v1, hh, ll);
                    *(uint32_t*)&Chi[(size_t)m*N + n0] = hh;
                    *(uint32_t*)&Clo[(size_t)m*N + n0] = ll;
                } else {
                    *(float2*)&C[(size_t)m*N + n0] = make_float2(v0, v1);
                }
            }
        }
    }
}

// ---------------- layernorm (bf16 hi/lo output) ----------------------------
__global__ __launch_bounds__(256) void ln_kernel(
    const float* __restrict__ src, const float* __restrict__ xsrc,
    __nv_bfloat16* __restrict__ dstH, __nv_bfloat16* __restrict__ dstL,
    const float* __restrict__ g, const float* __restrict__ b, int mode)
{
    __shared__ float red[8];
    int r = blockIdx.x;
    int t = threadIdx.x;
    int lane = t & 31, warp = t >> 5;
    const float* in; size_t base;
    if (mode == 0){ in = src; base = (size_t)r*768u; }
    else if (mode == 1){ int bb = r>>12; int j = r & 4095; in = xsrc; base = (size_t)(bb*4097 + 1 + j)*768u; }
    else {
        int bt = r/1025, pos = r - bt*1025;
        int bb = bt>>2, tt = bt&3;
        if (pos == 0){ in = xsrc; base = (size_t)(bb*4097)*768u; }
        else { int n = pos-1; in = src; base = (size_t)(bb*4096 + n*4 + tt)*768u; }
    }
    float v0 = in[base+t], v1 = in[base+t+256], v2 = in[base+t+512];
    float s = v0+v1+v2;
    #pragma unroll
    for (int o=16;o>0;o>>=1) s += __shfl_xor_sync(0xffffffffu, s, o);
    if (lane==0) red[warp]=s;
    __syncthreads();
    if (warp==0){
        float w = red[lane&7];
        #pragma unroll
        for (int o=4;o>0;o>>=1) w += __shfl_xor_sync(0xffffffffu, w, o);
        if (lane==0) red[0]=w;
    }
    __syncthreads();
    float mean = red[0]*(1.0f/768.0f);
    float d0=v0-mean, d1=v1-mean, d2=v2-mean;
    float q = d0*d0+d1*d1+d2*d2;
    #pragma unroll
    for (int o=16;o>0;o>>=1) q += __shfl_xor_sync(0xffffffffu, q, o);
    __syncthreads();
    if (lane==0) red[warp]=q;
    __syncthreads();
    if (warp==0){
        float w = red[lane&7];
        #pragma unroll
        for (int o=4;o>0;o>>=1) w += __shfl_xor_sync(0xffffffffu, w, o);
        if (lane==0) red[0]=w;
    }
    __syncthreads();
    float var = red[0]*(1.0f/768.0f);
    float rstd = rsqrtf(var + 1e-5f);
    size_t ob = (size_t)r*768u;
    #pragma unroll
    for (int p=0;p<3;++p){
        int col = t + p*256;
        float d = (p==0)?d0:((p==1)?d1:d2);
        float val = d*rstd*g[col] + b[col];
        __nv_bfloat16 h = __float2bfloat16(val);
        dstH[ob+col] = h;
        dstL[ob+col] = __float2bfloat16(val - __bfloat162float(h));
    }
}

// ---------------- geometry bias -------------------------------------------
__global__ __launch_bounds__(256) void bias_kernel(
    const float* __restrict__ wg_w, const float* __restrict__ wg_b,
    float* __restrict__ bias)
{
    __shared__ float sw[768];
    __shared__ float sc[12];
    int t = threadIdx.x;
    for (int i=t;i<768;i+=256) sw[i]=wg_w[i];
    __syncthreads();
    if (t < 12){
        float s = wg_b[t];
        #pragma unroll
        for (int k=48;k<64;++k) s += sw[t*64+k];
        sc[t] = s;
    }
    __syncthreads();
    size_t idx = (size_t)blockIdx.x*256u + t;
    if (idx >= (size_t)1025u*1025u) return;
    int i = (int)(idx/1025u), j = (int)(idx - (size_t)i*1025u);
    if (i==0 || j==0){
        #pragma unroll
        for (int h=0;h<12;++h) bias[(size_t)h*1025u*1025u + idx] = 0.f;
        return;
    }
    int a = i-1, b2 = j-1;
    float fx = (float)((a>>5)-(b2>>5)) * (1.0f/32.0f);
    float fy = (float)((a&31)-(b2&31)) * (1.0f/32.0f);
    const float inv_wbox = 1.0f/1.03125f;
    float dx = logf(fmaxf(fabsf(fx*inv_wbox), 0.001f));
    float dy = logf(fmaxf(fabsf(fy*inv_wbox), 0.001f));
    const float dm[8] = {1.0f, 0.42169650342f, 0.1778279410f, 0.074989420933f,
                         0.03162277660f, 0.013335214322f, 0.0056234132519f, 0.0023713737057f};
    float sx[8], cx[8], sy[8], cy[8];
    #pragma unroll
    for (int k=0;k<8;++k){
        sincosf(100.0f*dx*dm[k], &sx[k], &cx[k]);
        sincosf(100.0f*dy*dm[k], &sy[k], &cy[k]);
    }
    #pragma unroll
    for (int h=0;h<12;++h){
        const float* w = sw + h*64;
        float acc = sc[h];
        #pragma unroll
        for (int k=0;k<8;++k)
            acc += sx[k]*w[k] + sy[k]*w[8+k] + cx[k]*w[32+k] + cy[k]*w[40+k];
        float wv = fmaxf(acc, 0.0f);
        bias[(size_t)h*1025u*1025u + idx] = logf(fmaxf(wv, 1e-6f));
    }
}

// ---------------- temporal attention (bf16 hi/lo out) ----------------------
__global__ __launch_bounds__(256) void temporal_attn_kernel(
    const float* __restrict__ qkv,
    __nv_bfloat16* __restrict__ outH, __nv_bfloat16* __restrict__ outL)
{
    int gw = (blockIdx.x*256 + threadIdx.x) >> 5;
    int lane = threadIdx.x & 31;
    if (gw >= 2048*12) return;
    int s = gw/12, h = gw - s*12;
    size_t base = (size_t)(s*4)*2304u + h*64 + lane*2;
    float2 q[4],k[4],v[4];
    #pragma unroll
    for (int i=0;i<4;++i){
        q[i] = *(const float2*)(qkv + base + (size_t)i*2304u);
        k[i] = *(const float2*)(qkv + base + (size_t)i*2304u + 768u);
        v[i] = *(const float2*)(qkv + base + (size_t)i*2304u + 1536u);
    }
    float sc[16];
    #pragma unroll
    for (int i=0;i<4;++i)
        #pragma unroll
        for (int j=0;j<4;++j)
            sc[i*4+j] = q[i].x*k[j].x + q[i].y*k[j].y;
    #pragma unroll
    for (int t2=0;t2<16;++t2)
        #pragma unroll
        for (int off=16; off>0; off>>=1)
            sc[t2] += __shfl_xor_sync(0xffffffffu, sc[t2], off);
    #pragma unroll
    for (int i=0;i<4;++i){
        float s0=sc[i*4+0]*0.125f, s1=sc[i*4+1]*0.125f, s2=sc[i*4+2]*0.125f, s3=sc[i*4+3]*0.125f;
        float m = fmaxf(fmaxf(s0,s1),fmaxf(s2,s3));
        float e0=expf(s0-m), e1=expf(s1-m), e2=expf(s2-m), e3=expf(s3-m);
        float inv = 1.0f/(e0+e1+e2+e3);
        float ox = (e0*v[0].x + e1*v[1].x + e2*v[2].x + e3*v[3].x)*inv;
        float oy = (e0*v[0].y + e1*v[1].y + e2*v[2].y + e3*v[3].y)*inv;
        uint32_t hh, ll;
        split2(ox, oy, hh, ll);
        size_t o = (size_t)(s*4+i)*768u + h*64 + lane*2;
        *(uint32_t*)&outH[o] = hh;
        *(uint32_t*)&outL[o] = ll;
    }
}

// ---------------- spatial flash attention (scalar, bf16 hi/lo out) ---------
__global__ __launch_bounds__(256) void flash_attn_kernel(
    const float* __restrict__ qkv, const float* __restrict__ bias,
    __nv_bfloat16* __restrict__ outH, __nv_bfloat16* __restrict__ outL)
{
    extern __shared__ float sm[];
    float (*Qs)[68] = (float(*)[68])sm;
    float (*Ks)[68] = (float(*)[68])(sm + 64*68);
    float (*Vs)[68] = (float(*)[68])(sm + 2*64*68);
    float (*Ps)[68] = (float(*)[68])(sm + 3*64*68);
    int bh = blockIdx.y; int bt = bh/12, h = bh - bt*12;
    int i0 = blockIdx.x*64;
    int tid = threadIdx.x;
    int tx = tid & 15, ty = tid >> 4;

    #pragma unroll
    for (int u=0; u<16; ++u){
        int idx = u*256 + tid;
        int dd = idx & 63, ii = idx >> 6;
        int gi = i0 + ii;
        Qs[dd][ii] = (gi < 1025) ? qkv[(size_t)(bt*1025+gi)*2304u + h*64 + dd]*0.125f : 0.f;
    }

    float m[4], l[4], acc[4][4];
    #pragma unroll
    for (int r=0;r<4;++r){ m[r]=-1e30f; l[r]=0.f;
        #pragma unroll
        for (int c=0;c<4;++c) acc[r][c]=0.f; }

    for (int j0=0; j0<1025; j0+=64){
        #pragma unroll
        for (int u=0; u<16; ++u){
            int idx = u*256 + tid;
            int dd = idx & 63, jj = idx >> 6;
            int gj = j0 + jj;
            bool v = (gj < 1025);
            Ks[dd][jj] = v ? qkv[(size_t)(bt*1025+gj)*2304u + 768u  + h*64 + dd] : 0.f;
            Vs[jj][dd] = v ? qkv[(size_t)(bt*1025+gj)*2304u + 1536u + h*64 + dd] : 0.f;
        }
        __syncthreads();

        float s[4][4];
        #pragma unroll
        for (int r=0;r<4;++r)
            #pragma unroll
            for (int c=0;c<4;++c) s[r][c]=0.f;
        #pragma unroll 8
        for (int k=0;k<64;++k){
            float4 q4 = *(const float4*)&Qs[k][ty*4];
            float4 k4 = *(const float4*)&Ks[k][tx*4];
            float qr[4]={q4.x,q4.y,q4.z,q4.w}, kc[4]={k4.x,k4.y,k4.z,k4.w};
            #pragma unroll
            for (int r=0;r<4;++r)
                #pragma unroll
                for (int c=0;c<4;++c) s[r][c] += qr[r]*kc[c];
        }
        #pragma unroll
        for (int r=0;r<4;++r){
            int gi = i0 + ty*4 + r;
            #pragma unroll
            for (int c=0;c<4;++c){
                int gj = j0 + tx*4 + c;
                if (gi < 1025 && gj < 1025)
                    s[r][c] += bias[((size_t)h*1025u + gi)*1025u + gj];
                else
                    s[r][c] = -1e30f;
            }
        }
        #pragma unroll
        for (int r=0;r<4;++r){
            float rm = fmaxf(fmaxf(s[r][0],s[r][1]),fmaxf(s[r][2],s[r][3]));
            #pragma unroll
            for (int o=8;o>0;o>>=1) rm = fmaxf(rm, __shfl_xor_sync(0xffffffffu, rm, o));
            float mn = fmaxf(m[r], rm);
            float corr = __expf(m[r]-mn);
            m[r] = mn;
            float rs = 0.f;
            #pragma unroll
            for (int c=0;c<4;++c){ float p = __expf(s[r][c]-mn); s[r][c]=p; rs+=p; }
            #pragma unroll
            for (int o=8;o>0;o>>=1) rs += __shfl_xor_sync(0xffffffffu, rs, o);
            l[r] = l[r]*corr + rs;
            #pragma unroll
            for (int c=0;c<4;++c) acc[r][c] *= corr;
        }
        __syncthreads();
        #pragma unroll
        for (int r=0;r<4;++r)
            *(float4*)&Ps[ty*4+r][tx*4] = make_float4(s[r][0],s[r][1],s[r][2],s[r][3]);
        __syncthreads();
        #pragma unroll 8
        for (int jj=0;jj<64;++jj){
            float4 v4 = *(const float4*)&Vs[jj][tx*4];
            #pragma unroll
            for (int r=0;r<4;++r){
                float p = Ps[ty*4+r][jj];
                acc[r][0] += p*v4.x; acc[r][1] += p*v4.y;
                acc[r][2] += p*v4.z; acc[r][3] += p*v4.w;
            }
        }
        __syncthreads();
    }
    #pragma unroll
    for (int r=0;r<4;++r){
        int gi = i0 + ty*4 + r;
        if (gi < 1025){
            float inv = 1.0f/l[r];
            float a0 = acc[r][0]*inv, a1 = acc[r][1]*inv;
            float a2 = acc[r][2]*inv, a3 = acc[r][3]*inv;
            uint32_t h01,l01,h23,l23;
            split2(a0,a1,h01,l01);
            split2(a2,a3,h23,l23);
            size_t o = (size_t)(bt*1025+gi)*768u + h*64 + tx*4;
            *(uint32_t*)&outH[o]   = h01;
            *(uint32_t*)&outH[o+2] = h23;
            *(uint32_t*)&outL[o]   = l01;
            *(uint32_t*)&outL[o+2] = l23;
        }
    }
}

// ---------------- combine -------------------------------------------------
__global__ __launch_bounds__(256) void combine_kernel(
    const float* __restrict__ x, const float* __restrict__ xt,
    const float* __restrict__ res_s, float* __restrict__ out)
{
    size_t idx = (size_t)blockIdx.x*256u + threadIdx.x;
    if (idx >= (size_t)2u*4097u*768u) return;
    int c = (int)(idx % 768u);
    size_t row = idx / 768u;
    int b = (int)(row / 4097u);
    int rr = (int)(row - (size_t)b*4097u);
    float v;
    if (rr == 0){
        float s = 0.f;
        #pragma unroll
        for (int t2=0;t2<4;++t2)
            s += res_s[((size_t)((b*4+t2)*1025))*768u + c];
        v = x[row*768u + c] + 0.25f*s;
    } else {
        int qq = rr-1; int n = qq>>2, t2 = qq&3;
        v = xt[((size_t)(b*4096 + qq))*768u + c]
          + res_s[((size_t)((b*4+t2)*1025 + 1 + n))*768u + c];
    }
    out[row*768u + c] = v;
}

// ---------------- launcher -------------------------------------------------
extern "C" void kernel_launch(void* const* d_in, const int* in_sizes, int n_in,
                              void* d_out, int out_size)
{
    const float* x       = (const float*)d_in[0];
    const float* norm1_g = (const float*)d_in[1];
    const float* norm1_b = (const float*)d_in[2];
    const float* qkv_w   = (const float*)d_in[3];
    const float* proj_w  = (const float*)d_in[4];
    const float* proj_b  = (const float*)d_in[5];
    const float* wg_w    = (const float*)d_in[6];
    const float* wg_b    = (const float*)d_in[7];
    const float* tnorm1_g= (const float*)d_in[8];
    const float* tnorm1_b= (const float*)d_in[9];
    const float* tqkv_w  = (const float*)d_in[10];
    const float* tproj_w = (const float*)d_in[11];
    const float* tproj_b = (const float*)d_in[12];
    const float* tfc_w   = (const float*)d_in[13];
    const float* tfc_b   = (const float*)d_in[14];
    const float* norm2_g = (const float*)d_in[15];
    const float* norm2_b = (const float*)d_in[16];
    const float* fc1_w   = (const float*)d_in[17];
    const float* fc1_b   = (const float*)d_in[18];
    const float* fc2_w   = (const float*)d_in[19];
    const float* fc2_b   = (const float*)d_in[20];
    float* out = (float*)d_out;

    float* base = nullptr;
    cudaGetSymbolAddress((void**)&base, g_scratch);
    float* p_qkv  = base + OFF_QKV;
    float* p_xt   = base + OFF_XT;
    float* p_res  = base + OFF_RES;
    float* p_bias = base + OFF_BIAS;
    __nv_bfloat16* wb = (__nv_bfloat16*)(base + OFF_WBF);
    __nv_bfloat16* bf = (__nv_bfloat16*)(base + OFF_BF);
    __nv_bfloat16 *lnH = bf+BO_LNH,  *lnL = bf+BO_LNL;
    __nv_bfloat16 *atH = bf+BO_ATTH, *atL = bf+BO_ATTL;
    __nv_bfloat16 *r2H = bf+BO_R2H,  *r2L = bf+BO_R2L;
    __nv_bfloat16 *hH  = bf+BO_HH,   *hL  = bf+BO_HL;

    const int FLASH_SMEM = 4*64*68*4;
    cudaFuncSetAttribute(flash_attn_kernel,
                         cudaFuncAttributeMaxDynamicSharedMemorySize, FLASH_SMEM);
    cudaFuncSetAttribute(tgemm_nt,
                         cudaFuncAttributeMaxDynamicSharedMemorySize, TG_SMEM);

    // ---- weight bf16 hi/lo conversion ----
    wconv_kernel<<<1024,256>>>(tqkv_w, wb+WO_TQKV, wb+WO_TQKV+1769472u, 1769472);
    wconv_kernel<<<1024,256>>>(qkv_w,  wb+WO_QKV,  wb+WO_QKV +1769472u, 1769472);
    wconv_kernel<<<512,256>>>(tproj_w, wb+WO_TPROJ,wb+WO_TPROJ+589824u, 589824);
    wconv_kernel<<<512,256>>>(proj_w,  wb+WO_PROJ, wb+WO_PROJ +589824u, 589824);
    wconv_kernel<<<512,256>>>(tfc_w,   wb+WO_TFC,  wb+WO_TFC  +589824u, 589824);
    wconv_kernel<<<1024,256>>>(fc1_w,  wb+WO_FC1,  wb+WO_FC1 +2359296u, 2359296);
    wconv_kernel<<<1024,256>>>(fc2_w,  wb+WO_FC2,  wb+WO_FC2 +2359296u, 2359296);

    // ---- temporal branch ----
    ln_kernel<<<8192,256>>>(nullptr, x, lnH, lnL, tnorm1_g, tnorm1_b, 1);
    tgemm_nt<<<dim3(18,64),256,TG_SMEM>>>(lnH, lnL, wb+WO_TQKV, wb+WO_TQKV+1769472u,
        nullptr, p_qkv, nullptr, nullptr, 8192, 2304, 768, nullptr, 0, 0);
    temporal_attn_kernel<<<3072,256>>>(p_qkv, atH, atL);
    tgemm_nt<<<dim3(6,64),256,TG_SMEM>>>(atH, atL, wb+WO_TPROJ, wb+WO_TPROJ+589824u,
        tproj_b, nullptr, r2H, r2L, 8192, 768, 768, nullptr, 0, 0);
    tgemm_nt<<<dim3(6,64),256,TG_SMEM>>>(r2H, r2L, wb+WO_TFC, wb+WO_TFC+589824u,
        tfc_b, p_xt, nullptr, nullptr, 8192, 768, 768, x, 2, 0);

    // ---- spatial branch ----
    ln_kernel<<<8200,256>>>(p_xt, x, lnH, lnL, norm1_g, norm1_b, 2);
    tgemm_nt<<<dim3(18,65),256,TG_SMEM>>>(lnH, lnL, wb+WO_QKV, wb+WO_QKV+1769472u,
        nullptr, p_qkv, nullptr, nullptr, 8200, 2304, 768, nullptr, 0, 0);
    bias_kernel<<<4105,256>>>(wg_w, wg_b, p_bias);
    flash_attn_kernel<<<dim3(17,96),256,FLASH_SMEM>>>(p_qkv, p_bias, atH, atL);
    tgemm_nt<<<dim3(6,65),256,TG_SMEM>>>(atH, atL, wb+WO_PROJ, wb+WO_PROJ+589824u,
        proj_b, p_res, nullptr, nullptr, 8200, 768, 768, nullptr, 0, 0);
    combine_kernel<<<24582,256>>>(x, p_xt, p_res, out);

    // ---- MLP (chunked over 2x4097 rows) ----
    ln_kernel<<<8194,256>>>(out, nullptr, lnH, lnL, norm2_g, norm2_b, 0);
    for (int ch=0; ch<2; ++ch){
        size_t ro = (size_t)ch*4097u;
        tgemm_nt<<<dim3(24,33),256,TG_SMEM>>>(lnH + ro*768u, lnL + ro*768u,
            wb+WO_FC1, wb+WO_FC1+2359296u, fc1_b, nullptr, hH, hL,
            4097, 3072, 768, nullptr, 0, 1);
        tgemm_nt<<<dim3(6,33),256,TG_SMEM>>>(hH, hL, wb+WO_FC2, wb+WO_FC2+2359296u,
            fc2_b, out + ro*768u, nullptr, nullptr, 4097, 768, 3072, out + ro*768u, 1, 0);
    }
}

// round 10
// speedup vs baseline: 1.5041x; 1.0702x over previous
#include <cuda_runtime.h>
#include <cuda_bf16.h>
#include <math.h>
#include <stdint.h>

// ---------------- consolidated scratch (single symbol, ~342MB) -------------
#define OFF_QKV   0ull                       // 18,892,800 f32
#define OFF_XT    18892800ull                // 6,291,456 f32
#define OFF_RES   25184256ull                // 6,297,600 f32
#define OFF_BIAS  31481856ull                // 12,607,504 f32
#define OFF_WBF   44089360ull                // 10,027,008 f32 (weights bf16 h/l)
#define OFF_BF    54116368ull                // activation bf16 region
#define SCRATCH_TOTAL 85589008ull
__device__ float g_scratch[SCRATCH_TOTAL];

// bf16 activation offsets (in bf16 elements within OFF_BF region)
#define BO_LNH   0u
#define BO_LNL   6297600u
#define BO_ATTH  12595200u
#define BO_ATTL  18892800u
#define BO_R2H   25190400u
#define BO_R2L   31481856u
#define BO_HH    37773312u
#define BO_HL    50359296u

// weight offsets (bf16 elements; hi then lo contiguous)
#define WO_TQKV  0u
#define WO_QKV   3538944u
#define WO_TPROJ 7077888u
#define WO_PROJ  8257536u
#define WO_TFC   9437184u
#define WO_FC1   10616832u
#define WO_FC2   15335424u

__device__ __forceinline__ float gelu_exact(float x){
    return 0.5f*x*(1.0f+erff(x*0.70710678118654752440f));
}
__device__ __forceinline__ void split2(float a, float b, uint32_t &h, uint32_t &l){
    __nv_bfloat16 ha=__float2bfloat16(a), hb=__float2bfloat16(b);
    __nv_bfloat162 hh=__halves2bfloat162(ha,hb);
    __nv_bfloat162 ll=__halves2bfloat162(
        __float2bfloat16(a-__bfloat162float(ha)),
        __float2bfloat16(b-__bfloat162float(hb)));
    h=*(uint32_t*)&hh; l=*(uint32_t*)&ll;
}
__device__ __forceinline__ uint32_t smem_u32(const void* p){
    uint32_t a;
    asm("{ .reg .u64 t; cvta.to.shared.u64 t, %1; cvt.u32.u64 %0, t; }" : "=r"(a) : "l"(p));
    return a;
}
__device__ __forceinline__ void cp16(uint32_t dst, const void* src, int valid){
    int sz = valid ? 16 : 0;
    asm volatile("cp.async.ca.shared.global [%0], [%1], 16, %2;"
                 :: "r"(dst), "l"(src), "r"(sz) : "memory");
}
__device__ __forceinline__ void cp_commit(){ asm volatile("cp.async.commit_group;" ::: "memory"); }
__device__ __forceinline__ void cp_wait1(){ asm volatile("cp.async.wait_group 1;" ::: "memory"); }
__device__ __forceinline__ void cp_wait0(){ asm volatile("cp.async.wait_group 0;" ::: "memory"); }
__device__ __forceinline__ void ldsm4(uint32_t* r, uint32_t addr){
    asm volatile("ldmatrix.sync.aligned.m8n8.x4.shared.b16 {%0,%1,%2,%3}, [%4];"
        : "=r"(r[0]), "=r"(r[1]), "=r"(r[2]), "=r"(r[3]) : "r"(addr));
}

// ---------------- weight fp32 -> bf16 hi/lo conversion ---------------------
__global__ __launch_bounds__(256) void wconv_kernel(
    const float* __restrict__ w, __nv_bfloat16* __restrict__ hi,
    __nv_bfloat16* __restrict__ lo, int n)
{
    for (int i = blockIdx.x*256 + threadIdx.x; i < n; i += gridDim.x*256){
        float v = w[i];
        __nv_bfloat16 h = __float2bfloat16(v);
        hi[i] = h;
        lo[i] = __float2bfloat16(v - __bfloat162float(h));
    }
}

// ---------------- HMMA (mma.sync) split-bf16 GEMM, cp.async + ldmatrix -----
__device__ __forceinline__ void mma_bf16(float* d, const uint32_t* a, const uint32_t* b){
    asm volatile("mma.sync.aligned.m16n8k16.row.col.f32.bf16.bf16.f32 "
        "{%0,%1,%2,%3}, {%4,%5,%6,%7}, {%8,%9}, {%0,%1,%2,%3};"
        : "+f"(d[0]), "+f"(d[1]), "+f"(d[2]), "+f"(d[3])
        : "r"(a[0]), "r"(a[1]), "r"(a[2]), "r"(a[3]), "r"(b[0]), "r"(b[1]));
}

#define TG_BUF   40960               // one buffer: Ah|Al|Bh|Bl, each 128x40 bf16
#define TG_SMEM  (2*TG_BUF)          // 81920 bytes, double buffered

__global__ __launch_bounds__(256) void tgemm_nt(
    const __nv_bfloat16* __restrict__ Ahi, const __nv_bfloat16* __restrict__ Alo,
    const __nv_bfloat16* __restrict__ Whi, const __nv_bfloat16* __restrict__ Wlo,
    const float* __restrict__ bias,
    float* __restrict__ C, __nv_bfloat16* __restrict__ Chi, __nv_bfloat16* __restrict__ Clo,
    int M, int N, int K,
    const float* __restrict__ res, int resMode, int doGelu)
{
    extern __shared__ char smem[];
    uint32_t sb = smem_u32(smem);
    int tid = threadIdx.x;
    int wid = tid >> 5, lane = tid & 31;
    int warpM = wid >> 2, warpN = wid & 3;
    int g = lane >> 2, tg = lane & 3;
    int lrow = lane & 7, lt = lane >> 3;
    int bm = blockIdx.y*128, bn = blockIdx.x*128;

    int NC = K >> 5;

    auto stage = [&](int c, int buf){
        int k0 = c << 5;
        uint32_t bufb = sb + buf*TG_BUF;
        #pragma unroll
        for (int u = 0; u < 8; ++u){
            int idx = u*256 + tid;
            int arr = idx >> 9;
            int rem = idx & 511;
            int row = rem >> 2;
            int q = rem & 3;
            uint32_t dst = bufb + arr*10240 + row*80 + q*16;
            const __nv_bfloat16* src;
            int valid = 1;
            if (arr < 2){
                int gm = bm + row;
                valid = (gm < M);
                const __nv_bfloat16* base = (arr == 0) ? Ahi : Alo;
                src = base + (size_t)(valid ? gm : 0)*K + k0 + q*8;
            } else {
                int gn = bn + row;
                const __nv_bfloat16* base = (arr == 2) ? Whi : Wlo;
                src = base + (size_t)gn*K + k0 + q*8;
            }
            cp16(dst, src, valid);
        }
        cp_commit();
    };

    float acc[4][4][4];
    #pragma unroll
    for (int i=0;i<4;++i)
        #pragma unroll
        for (int j=0;j<4;++j)
            #pragma unroll
            for (int q=0;q<4;++q) acc[i][j][q]=0.f;

    stage(0, 0);
    for (int c = 0; c < NC; ++c){
        int buf = c & 1;
        if (c+1 < NC){ stage(c+1, buf^1); cp_wait1(); }
        else cp_wait0();
        __syncthreads();

        uint32_t bufA = sb + buf*TG_BUF;

        #pragma unroll
        for (int ks = 0; ks < 2; ++ks){
            int kb0 = ks*16;
            // A fragments via ldmatrix.x4: tiles (r,klo),(r+8,klo),(r,khi),(r+8,khi)
            uint32_t ahi[4][4], alo[4][4];
            #pragma unroll
            for (int i=0;i<4;++i){
                int row = warpM*64 + i*16 + lrow + ((lt&1)<<3);
                uint32_t off = (uint32_t)(row*40 + kb0 + ((lt>>1)<<3)) << 1;
                ldsm4(ahi[i], bufA + off);
                ldsm4(alo[i], bufA + 10240 + off);
            }
            // B fragments: one x4 covers two j's: tiles (j,klo),(j,khi),(j+1,klo),(j+1,khi)
            uint32_t bhi[4][2], blo[4][2];
            #pragma unroll
            for (int jp=0;jp<2;++jp){
                int row = warpN*32 + jp*16 + lrow + ((lt>>1)<<3);
                uint32_t off = (uint32_t)(row*40 + kb0 + ((lt&1)<<3)) << 1;
                uint32_t t[4];
                ldsm4(t, bufA + 20480 + off);
                bhi[jp*2][0]=t[0]; bhi[jp*2][1]=t[1];
                bhi[jp*2+1][0]=t[2]; bhi[jp*2+1][1]=t[3];
                ldsm4(t, bufA + 30720 + off);
                blo[jp*2][0]=t[0]; blo[jp*2][1]=t[1];
                blo[jp*2+1][0]=t[2]; blo[jp*2+1][1]=t[3];
            }
            #pragma unroll
            for (int i=0;i<4;++i)
                #pragma unroll
                for (int j=0;j<4;++j){
                    mma_bf16(acc[i][j], ahi[i], bhi[j]);
                    mma_bf16(acc[i][j], ahi[i], blo[j]);
                    mma_bf16(acc[i][j], alo[i], bhi[j]);
                }
        }
        __syncthreads();
    }

    // ---- epilogue ----
    #pragma unroll
    for (int i=0;i<4;++i){
        #pragma unroll
        for (int half=0; half<2; ++half){
            int m = bm + warpM*64 + i*16 + g + half*8;
            if (m >= M) continue;
            const float* rrow = nullptr;
            if (resMode == 1) rrow = res + (size_t)m*N;
            else if (resMode == 2){ int bb = m>>12, jj = m&4095; rrow = res + (size_t)(bb*4097+1+jj)*N; }
            #pragma unroll
            for (int j=0;j<4;++j){
                int n0 = bn + warpN*32 + j*8 + tg*2;
                float v0 = acc[i][j][half*2+0];
                float v1 = acc[i][j][half*2+1];
                if (bias){ float2 bv = *(const float2*)&bias[n0]; v0 += bv.x; v1 += bv.y; }
                if (doGelu){ v0 = gelu_exact(v0); v1 = gelu_exact(v1); }
                if (rrow){ float2 rv = *(const float2*)&rrow[n0]; v0 += rv.x; v1 += rv.y; }
                if (Chi){
                    uint32_t hh, ll;
                    split2(v0, v1, hh, ll);
                    *(uint32_t*)&Chi[(size_t)m*N + n0] = hh;
                    *(uint32_t*)&Clo[(size_t)m*N + n0] = ll;
                } else {
                    *(float2*)&C[(size_t)m*N + n0] = make_float2(v0, v1);
                }
            }
        }
    }
}

// ---------------- layernorm (bf16 hi/lo output) ----------------------------
__global__ __launch_bounds__(256) void ln_kernel(
    const float* __restrict__ src, const float* __restrict__ xsrc,
    __nv_bfloat16* __restrict__ dstH, __nv_bfloat16* __restrict__ dstL,
    const float* __restrict__ g, const float* __restrict__ b, int mode)
{
    __shared__ float red[8];
    int r = blockIdx.x;
    int t = threadIdx.x;
    int lane = t & 31, warp = t >> 5;
    const float* in; size_t base;
    if (mode == 0){ in = src; base = (size_t)r*768u; }
    else if (mode == 1){ int bb = r>>12; int j = r & 4095; in = xsrc; base = (size_t)(bb*4097 + 1 + j)*768u; }
    else {
        int bt = r/1025, pos = r - bt*1025;
        int bb = bt>>2, tt = bt&3;
        if (pos == 0){ in = xsrc; base = (size_t)(bb*4097)*768u; }
        else { int n = pos-1; in = src; base = (size_t)(bb*4096 + n*4 + tt)*768u; }
    }
    float v0 = in[base+t], v1 = in[base+t+256], v2 = in[base+t+512];
    float s = v0+v1+v2;
    #pragma unroll
    for (int o=16;o>0;o>>=1) s += __shfl_xor_sync(0xffffffffu, s, o);
    if (lane==0) red[warp]=s;
    __syncthreads();
    if (warp==0){
        float w = red[lane&7];
        #pragma unroll
        for (int o=4;o>0;o>>=1) w += __shfl_xor_sync(0xffffffffu, w, o);
        if (lane==0) red[0]=w;
    }
    __syncthreads();
    float mean = red[0]*(1.0f/768.0f);
    float d0=v0-mean, d1=v1-mean, d2=v2-mean;
    float q = d0*d0+d1*d1+d2*d2;
    #pragma unroll
    for (int o=16;o>0;o>>=1) q += __shfl_xor_sync(0xffffffffu, q, o);
    __syncthreads();
    if (lane==0) red[warp]=q;
    __syncthreads();
    if (warp==0){
        float w = red[lane&7];
        #pragma unroll
        for (int o=4;o>0;o>>=1) w += __shfl_xor_sync(0xffffffffu, w, o);
        if (lane==0) red[0]=w;
    }
    __syncthreads();
    float var = red[0]*(1.0f/768.0f);
    float rstd = rsqrtf(var + 1e-5f);
    size_t ob = (size_t)r*768u;
    #pragma unroll
    for (int p=0;p<3;++p){
        int col = t + p*256;
        float d = (p==0)?d0:((p==1)?d1:d2);
        float val = d*rstd*g[col] + b[col];
        __nv_bfloat16 h = __float2bfloat16(val);
        dstH[ob+col] = h;
        dstL[ob+col] = __float2bfloat16(val - __bfloat162float(h));
    }
}

// ---------------- geometry bias -------------------------------------------
__global__ __launch_bounds__(256) void bias_kernel(
    const float* __restrict__ wg_w, const float* __restrict__ wg_b,
    float* __restrict__ bias)
{
    __shared__ float sw[768];
    __shared__ float sc[12];
    int t = threadIdx.x;
    for (int i=t;i<768;i+=256) sw[i]=wg_w[i];
    __syncthreads();
    if (t < 12){
        float s = wg_b[t];
        #pragma unroll
        for (int k=48;k<64;++k) s += sw[t*64+k];
        sc[t] = s;
    }
    __syncthreads();
    size_t idx = (size_t)blockIdx.x*256u + t;
    if (idx >= (size_t)1025u*1025u) return;
    int i = (int)(idx/1025u), j = (int)(idx - (size_t)i*1025u);
    if (i==0 || j==0){
        #pragma unroll
        for (int h=0;h<12;++h) bias[(size_t)h*1025u*1025u + idx] = 0.f;
        return;
    }
    int a = i-1, b2 = j-1;
    float fx = (float)((a>>5)-(b2>>5)) * (1.0f/32.0f);
    float fy = (float)((a&31)-(b2&31)) * (1.0f/32.0f);
    const float inv_wbox = 1.0f/1.03125f;
    float dx = logf(fmaxf(fabsf(fx*inv_wbox), 0.001f));
    float dy = logf(fmaxf(fabsf(fy*inv_wbox), 0.001f));
    const float dm[8] = {1.0f, 0.42169650342f, 0.1778279410f, 0.074989420933f,
                         0.03162277660f, 0.013335214322f, 0.0056234132519f, 0.0023713737057f};
    float sx[8], cx[8], sy[8], cy[8];
    #pragma unroll
    for (int k=0;k<8;++k){
        sincosf(100.0f*dx*dm[k], &sx[k], &cx[k]);
        sincosf(100.0f*dy*dm[k], &sy[k], &cy[k]);
    }
    #pragma unroll
    for (int h=0;h<12;++h){
        const float* w = sw + h*64;
        float acc = sc[h];
        #pragma unroll
        for (int k=0;k<8;++k)
            acc += sx[k]*w[k] + sy[k]*w[8+k] + cx[k]*w[32+k] + cy[k]*w[40+k];
        float wv = fmaxf(acc, 0.0f);
        bias[(size_t)h*1025u*1025u + idx] = logf(fmaxf(wv, 1e-6f));
    }
}

// ---------------- temporal attention (bf16 hi/lo out) ----------------------
__global__ __launch_bounds__(256) void temporal_attn_kernel(
    const float* __restrict__ qkv,
    __nv_bfloat16* __restrict__ outH, __nv_bfloat16* __restrict__ outL)
{
    int gw = (blockIdx.x*256 + threadIdx.x) >> 5;
    int lane = threadIdx.x & 31;
    if (gw >= 2048*12) return;
    int s = gw/12, h = gw - s*12;
    size_t base = (size_t)(s*4)*2304u + h*64 + lane*2;
    float2 q[4],k[4],v[4];
    #pragma unroll
    for (int i=0;i<4;++i){
        q[i] = *(const float2*)(qkv + base + (size_t)i*2304u);
        k[i] = *(const float2*)(qkv + base + (size_t)i*2304u + 768u);
        v[i] = *(const float2*)(qkv + base + (size_t)i*2304u + 1536u);
    }
    float sc[16];
    #pragma unroll
    for (int i=0;i<4;++i)
        #pragma unroll
        for (int j=0;j<4;++j)
            sc[i*4+j] = q[i].x*k[j].x + q[i].y*k[j].y;
    #pragma unroll
    for (int t2=0;t2<16;++t2)
        #pragma unroll
        for (int off=16; off>0; off>>=1)
            sc[t2] += __shfl_xor_sync(0xffffffffu, sc[t2], off);
    #pragma unroll
    for (int i=0;i<4;++i){
        float s0=sc[i*4+0]*0.125f, s1=sc[i*4+1]*0.125f, s2=sc[i*4+2]*0.125f, s3=sc[i*4+3]*0.125f;
        float m = fmaxf(fmaxf(s0,s1),fmaxf(s2,s3));
        float e0=expf(s0-m), e1=expf(s1-m), e2=expf(s2-m), e3=expf(s3-m);
        float inv = 1.0f/(e0+e1+e2+e3);
        float ox = (e0*v[0].x + e1*v[1].x + e2*v[2].x + e3*v[3].x)*inv;
        float oy = (e0*v[0].y + e1*v[1].y + e2*v[2].y + e3*v[3].y)*inv;
        uint32_t hh, ll;
        split2(ox, oy, hh, ll);
        size_t o = (size_t)(s*4+i)*768u + h*64 + lane*2;
        *(uint32_t*)&outH[o] = hh;
        *(uint32_t*)&outL[o] = ll;
    }
}

// ---------------- spatial flash attention (scalar, bf16 hi/lo out) ---------
__global__ __launch_bounds__(256) void flash_attn_kernel(
    const float* __restrict__ qkv, const float* __restrict__ bias,
    __nv_bfloat16* __restrict__ outH, __nv_bfloat16* __restrict__ outL)
{
    extern __shared__ float sm[];
    float (*Qs)[68] = (float(*)[68])sm;
    float (*Ks)[68] = (float(*)[68])(sm + 64*68);
    float (*Vs)[68] = (float(*)[68])(sm + 2*64*68);
    float (*Ps)[68] = (float(*)[68])(sm + 3*64*68);
    int bh = blockIdx.y; int bt = bh/12, h = bh - bt*12;
    int i0 = blockIdx.x*64;
    int tid = threadIdx.x;
    int tx = tid & 15, ty = tid >> 4;

    #pragma unroll
    for (int u=0; u<16; ++u){
        int idx = u*256 + tid;
        int dd = idx & 63, ii = idx >> 6;
        int gi = i0 + ii;
        Qs[dd][ii] = (gi < 1025) ? qkv[(size_t)(bt*1025+gi)*2304u + h*64 + dd]*0.125f : 0.f;
    }

    float m[4], l[4], acc[4][4];
    #pragma unroll
    for (int r=0;r<4;++r){ m[r]=-1e30f; l[r]=0.f;
        #pragma unroll
        for (int c=0;c<4;++c) acc[r][c]=0.f; }

    for (int j0=0; j0<1025; j0+=64){
        #pragma unroll
        for (int u=0; u<16; ++u){
            int idx = u*256 + tid;
            int dd = idx & 63, jj = idx >> 6;
            int gj = j0 + jj;
            bool v = (gj < 1025);
            Ks[dd][jj] = v ? qkv[(size_t)(bt*1025+gj)*2304u + 768u  + h*64 + dd] : 0.f;
            Vs[jj][dd] = v ? qkv[(size_t)(bt*1025+gj)*2304u + 1536u + h*64 + dd] : 0.f;
        }
        __syncthreads();

        float s[4][4];
        #pragma unroll
        for (int r=0;r<4;++r)
            #pragma unroll
            for (int c=0;c<4;++c) s[r][c]=0.f;
        #pragma unroll 8
        for (int k=0;k<64;++k){
            float4 q4 = *(const float4*)&Qs[k][ty*4];
            float4 k4 = *(const float4*)&Ks[k][tx*4];
            float qr[4]={q4.x,q4.y,q4.z,q4.w}, kc[4]={k4.x,k4.y,k4.z,k4.w};
            #pragma unroll
            for (int r=0;r<4;++r)
                #pragma unroll
                for (int c=0;c<4;++c) s[r][c] += qr[r]*kc[c];
        }
        #pragma unroll
        for (int r=0;r<4;++r){
            int gi = i0 + ty*4 + r;
            #pragma unroll
            for (int c=0;c<4;++c){
                int gj = j0 + tx*4 + c;
                if (gi < 1025 && gj < 1025)
                    s[r][c] += bias[((size_t)h*1025u + gi)*1025u + gj];
                else
                    s[r][c] = -1e30f;
            }
        }
        #pragma unroll
        for (int r=0;r<4;++r){
            float rm = fmaxf(fmaxf(s[r][0],s[r][1]),fmaxf(s[r][2],s[r][3]));
            #pragma unroll
            for (int o=8;o>0;o>>=1) rm = fmaxf(rm, __shfl_xor_sync(0xffffffffu, rm, o));
            float mn = fmaxf(m[r], rm);
            float corr = __expf(m[r]-mn);
            m[r] = mn;
            float rs = 0.f;
            #pragma unroll
            for (int c=0;c<4;++c){ float p = __expf(s[r][c]-mn); s[r][c]=p; rs+=p; }
            #pragma unroll
            for (int o=8;o>0;o>>=1) rs += __shfl_xor_sync(0xffffffffu, rs, o);
            l[r] = l[r]*corr + rs;
            #pragma unroll
            for (int c=0;c<4;++c) acc[r][c] *= corr;
        }
        __syncthreads();
        #pragma unroll
        for (int r=0;r<4;++r)
            *(float4*)&Ps[ty*4+r][tx*4] = make_float4(s[r][0],s[r][1],s[r][2],s[r][3]);
        __syncthreads();
        #pragma unroll 8
        for (int jj=0;jj<64;++jj){
            float4 v4 = *(const float4*)&Vs[jj][tx*4];
            #pragma unroll
            for (int r=0;r<4;++r){
                float p = Ps[ty*4+r][jj];
                acc[r][0] += p*v4.x; acc[r][1] += p*v4.y;
                acc[r][2] += p*v4.z; acc[r][3] += p*v4.w;
            }
        }
        __syncthreads();
    }
    #pragma unroll
    for (int r=0;r<4;++r){
        int gi = i0 + ty*4 + r;
        if (gi < 1025){
            float inv = 1.0f/l[r];
            float a0 = acc[r][0]*inv, a1 = acc[r][1]*inv;
            float a2 = acc[r][2]*inv, a3 = acc[r][3]*inv;
            uint32_t h01,l01,h23,l23;
            split2(a0,a1,h01,l01);
            split2(a2,a3,h23,l23);
            size_t o = (size_t)(bt*1025+gi)*768u + h*64 + tx*4;
            *(uint32_t*)&outH[o]   = h01;
            *(uint32_t*)&outH[o+2] = h23;
            *(uint32_t*)&outL[o]   = l01;
            *(uint32_t*)&outL[o+2] = l23;
        }
    }
}

// ---------------- combine -------------------------------------------------
__global__ __launch_bounds__(256) void combine_kernel(
    const float* __restrict__ x, const float* __restrict__ xt,
    const float* __restrict__ res_s, float* __restrict__ out)
{
    size_t idx = (size_t)blockIdx.x*256u + threadIdx.x;
    if (idx >= (size_t)2u*4097u*768u) return;
    int c = (int)(idx % 768u);
    size_t row = idx / 768u;
    int b = (int)(row / 4097u);
    int rr = (int)(row - (size_t)b*4097u);
    float v;
    if (rr == 0){
        float s = 0.f;
        #pragma unroll
        for (int t2=0;t2<4;++t2)
            s += res_s[((size_t)((b*4+t2)*1025))*768u + c];
        v = x[row*768u + c] + 0.25f*s;
    } else {
        int qq = rr-1; int n = qq>>2, t2 = qq&3;
        v = xt[((size_t)(b*4096 + qq))*768u + c]
          + res_s[((size_t)((b*4+t2)*1025 + 1 + n))*768u + c];
    }
    out[row*768u + c] = v;
}

// ---------------- launcher -------------------------------------------------
extern "C" void kernel_launch(void* const* d_in, const int* in_sizes, int n_in,
                              void* d_out, int out_size)
{
    const float* x       = (const float*)d_in[0];
    const float* norm1_g = (const float*)d_in[1];
    const float* norm1_b = (const float*)d_in[2];
    const float* qkv_w   = (const float*)d_in[3];
    const float* proj_w  = (const float*)d_in[4];
    const float* proj_b  = (const float*)d_in[5];
    const float* wg_w    = (const float*)d_in[6];
    const float* wg_b    = (const float*)d_in[7];
    const float* tnorm1_g= (const float*)d_in[8];
    const float* tnorm1_b= (const float*)d_in[9];
    const float* tqkv_w  = (const float*)d_in[10];
    const float* tproj_w = (const float*)d_in[11];
    const float* tproj_b = (const float*)d_in[12];
    const float* tfc_w   = (const float*)d_in[13];
    const float* tfc_b   = (const float*)d_in[14];
    const float* norm2_g = (const float*)d_in[15];
    const float* norm2_b = (const float*)d_in[16];
    const float* fc1_w   = (const float*)d_in[17];
    const float* fc1_b   = (const float*)d_in[18];
    const float* fc2_w   = (const float*)d_in[19];
    const float* fc2_b   = (const float*)d_in[20];
    float* out = (float*)d_out;

    float* base = nullptr;
    cudaGetSymbolAddress((void**)&base, g_scratch);
    float* p_qkv  = base + OFF_QKV;
    float* p_xt   = base + OFF_XT;
    float* p_res  = base + OFF_RES;
    float* p_bias = base + OFF_BIAS;
    __nv_bfloat16* wb = (__nv_bfloat16*)(base + OFF_WBF);
    __nv_bfloat16* bf = (__nv_bfloat16*)(base + OFF_BF);
    __nv_bfloat16 *lnH = bf+BO_LNH,  *lnL = bf+BO_LNL;
    __nv_bfloat16 *atH = bf+BO_ATTH, *atL = bf+BO_ATTL;
    __nv_bfloat16 *r2H = bf+BO_R2H,  *r2L = bf+BO_R2L;
    __nv_bfloat16 *hH  = bf+BO_HH,   *hL  = bf+BO_HL;

    const int FLASH_SMEM = 4*64*68*4;
    cudaFuncSetAttribute(flash_attn_kernel,
                         cudaFuncAttributeMaxDynamicSharedMemorySize, FLASH_SMEM);
    cudaFuncSetAttribute(tgemm_nt,
                         cudaFuncAttributeMaxDynamicSharedMemorySize, TG_SMEM);

    // ---- weight bf16 hi/lo conversion ----
    wconv_kernel<<<1024,256>>>(tqkv_w, wb+WO_TQKV, wb+WO_TQKV+1769472u, 1769472);
    wconv_kernel<<<1024,256>>>(qkv_w,  wb+WO_QKV,  wb+WO_QKV +1769472u, 1769472);
    wconv_kernel<<<512,256>>>(tproj_w, wb+WO_TPROJ,wb+WO_TPROJ+589824u, 589824);
    wconv_kernel<<<512,256>>>(proj_w,  wb+WO_PROJ, wb+WO_PROJ +589824u, 589824);
    wconv_kernel<<<512,256>>>(tfc_w,   wb+WO_TFC,  wb+WO_TFC  +589824u, 589824);
    wconv_kernel<<<1024,256>>>(fc1_w,  wb+WO_FC1,  wb+WO_FC1 +2359296u, 2359296);
    wconv_kernel<<<1024,256>>>(fc2_w,  wb+WO_FC2,  wb+WO_FC2 +2359296u, 2359296);

    // ---- temporal branch ----
    ln_kernel<<<8192,256>>>(nullptr, x, lnH, lnL, tnorm1_g, tnorm1_b, 1);
    tgemm_nt<<<dim3(18,64),256,TG_SMEM>>>(lnH, lnL, wb+WO_TQKV, wb+WO_TQKV+1769472u,
        nullptr, p_qkv, nullptr, nullptr, 8192, 2304, 768, nullptr, 0, 0);
    temporal_attn_kernel<<<3072,256>>>(p_qkv, atH, atL);
    tgemm_nt<<<dim3(6,64),256,TG_SMEM>>>(atH, atL, wb+WO_TPROJ, wb+WO_TPROJ+589824u,
        tproj_b, nullptr, r2H, r2L, 8192, 768, 768, nullptr, 0, 0);
    tgemm_nt<<<dim3(6,64),256,TG_SMEM>>>(r2H, r2L, wb+WO_TFC, wb+WO_TFC+589824u,
        tfc_b, p_xt, nullptr, nullptr, 8192, 768, 768, x, 2, 0);

    // ---- spatial branch ----
    ln_kernel<<<8200,256>>>(p_xt, x, lnH, lnL, norm1_g, norm1_b, 2);
    tgemm_nt<<<dim3(18,65),256,TG_SMEM>>>(lnH, lnL, wb+WO_QKV, wb+WO_QKV+1769472u,
        nullptr, p_qkv, nullptr, nullptr, 8200, 2304, 768, nullptr, 0, 0);
    bias_kernel<<<4105,256>>>(wg_w, wg_b, p_bias);
    flash_attn_kernel<<<dim3(17,96),256,FLASH_SMEM>>>(p_qkv, p_bias, atH, atL);
    tgemm_nt<<<dim3(6,65),256,TG_SMEM>>>(atH, atL, wb+WO_PROJ, wb+WO_PROJ+589824u,
        proj_b, p_res, nullptr, nullptr, 8200, 768, 768, nullptr, 0, 0);
    combine_kernel<<<24582,256>>>(x, p_xt, p_res, out);

    // ---- MLP (chunked over 2x4097 rows) ----
    ln_kernel<<<8194,256>>>(out, nullptr, lnH, lnL, norm2_g, norm2_b, 0);
    for (int ch=0; ch<2; ++ch){
        size_t ro = (size_t)ch*4097u;
        tgemm_nt<<<dim3(24,33),256,TG_SMEM>>>(lnH + ro*768u, lnL + ro*768u,
            wb+WO_FC1, wb+WO_FC1+2359296u, fc1_b, nullptr, hH, hL,
            4097, 3072, 768, nullptr, 0, 1);
        tgemm_nt<<<dim3(6,33),256,TG_SMEM>>>(hH, hL, wb+WO_FC2, wb+WO_FC2+2359296u,
            fc2_b, out + ro*768u, nullptr, nullptr, 4097, 768, 3072, out + ro*768u, 1, 0);
    }
}

// round 12
// speedup vs baseline: 1.5417x; 1.0250x over previous
#include <cuda_runtime.h>
#include <cuda_bf16.h>
#include <math.h>
#include <stdint.h>

// ---------------- consolidated scratch (single symbol, ~418MB) -------------
#define OFF_QKV   0ull                       // 18,892,800 f32
#define OFF_XT    18892800ull                // 6,291,456 f32
#define OFF_RES   25184256ull                // 6,297,600 f32
#define OFF_BIAS  31481856ull                // 12,607,504 f32
#define OFF_WBF   44089360ull                // 10,027,008 f32 (weights bf16 h/l)
#define OFF_BF    54116368ull                // activation bf16 region
#define OFF_QB    85589008ull                // qkv bf16 hi/lo: 2*18,892,800 bf16
#define SCRATCH_TOTAL 104481808ull
__device__ float g_scratch[SCRATCH_TOTAL];

// bf16 activation offsets (in bf16 elements within OFF_BF region)
#define BO_LNH   0u
#define BO_LNL   6297600u
#define BO_ATTH  12595200u
#define BO_ATTL  18892800u
#define BO_R2H   25190400u
#define BO_R2L   31481856u
#define BO_HH    37773312u
#define BO_HL    50359296u

// weight offsets (bf16 elements; hi then lo contiguous)
#define WO_TQKV  0u
#define WO_QKV   3538944u
#define WO_TPROJ 7077888u
#define WO_PROJ  8257536u
#define WO_TFC   9437184u
#define WO_FC1   10616832u
#define WO_FC2   15335424u

__device__ __forceinline__ float gelu_exact(float x){
    return 0.5f*x*(1.0f+erff(x*0.70710678118654752440f));
}
__device__ __forceinline__ void split2(float a, float b, uint32_t &h, uint32_t &l){
    __nv_bfloat16 ha=__float2bfloat16(a), hb=__float2bfloat16(b);
    __nv_bfloat162 hh=__halves2bfloat162(ha,hb);
    __nv_bfloat162 ll=__halves2bfloat162(
        __float2bfloat16(a-__bfloat162float(ha)),
        __float2bfloat16(b-__bfloat162float(hb)));
    h=*(uint32_t*)&hh; l=*(uint32_t*)&ll;
}
__device__ __forceinline__ uint32_t smem_u32(const void* p){
    uint32_t a;
    asm("{ .reg .u64 t; cvta.to.shared.u64 t, %1; cvt.u32.u64 %0, t; }" : "=r"(a) : "l"(p));
    return a;
}
__device__ __forceinline__ void cp16(uint32_t dst, const void* src, int valid){
    int sz = valid ? 16 : 0;
    asm volatile("cp.async.ca.shared.global [%0], [%1], 16, %2;"
                 :: "r"(dst), "l"(src), "r"(sz) : "memory");
}
__device__ __forceinline__ void cp_commit(){ asm volatile("cp.async.commit_group;" ::: "memory"); }
__device__ __forceinline__ void cp_wait1(){ asm volatile("cp.async.wait_group 1;" ::: "memory"); }
__device__ __forceinline__ void cp_wait0(){ asm volatile("cp.async.wait_group 0;" ::: "memory"); }
__device__ __forceinline__ void ldsm4(uint32_t* r, uint32_t addr){
    asm volatile("ldmatrix.sync.aligned.m8n8.x4.shared.b16 {%0,%1,%2,%3}, [%4];"
        : "=r"(r[0]), "=r"(r[1]), "=r"(r[2]), "=r"(r[3]) : "r"(addr));
}
__device__ __forceinline__ void ldsm4t(uint32_t* r, uint32_t addr){
    asm volatile("ldmatrix.sync.aligned.m8n8.x4.trans.shared.b16 {%0,%1,%2,%3}, [%4];"
        : "=r"(r[0]), "=r"(r[1]), "=r"(r[2]), "=r"(r[3]) : "r"(addr));
}
__device__ __forceinline__ void mma_bf16(float* d, const uint32_t* a, const uint32_t* b){
    asm volatile("mma.sync.aligned.m16n8k16.row.col.f32.bf16.bf16.f32 "
        "{%0,%1,%2,%3}, {%4,%5,%6,%7}, {%8,%9}, {%0,%1,%2,%3};"
        : "+f"(d[0]), "+f"(d[1]), "+f"(d[2]), "+f"(d[3])
        : "r"(a[0]), "r"(a[1]), "r"(a[2]), "r"(a[3]), "r"(b[0]), "r"(b[1]));
}

// ---------------- fused weight fp32 -> bf16 hi/lo conversion ---------------
__global__ __launch_bounds__(256) void wconv_all(
    const float* __restrict__ w0, const float* __restrict__ w1,
    const float* __restrict__ w2, const float* __restrict__ w3,
    const float* __restrict__ w4, const float* __restrict__ w5,
    const float* __restrict__ w6, __nv_bfloat16* __restrict__ wb)
{
    const float* ws[7] = {w0,w1,w2,w3,w4,w5,w6};
    const int cum[8] = {0,1769472,3538944,4128768,4718592,5308416,7667712,10027008};
    const unsigned ho[7] = {WO_TQKV,WO_QKV,WO_TPROJ,WO_PROJ,WO_TFC,WO_FC1,WO_FC2};
    for (int i = blockIdx.x*256 + threadIdx.x; i < 10027008; i += gridDim.x*256){
        int r = 0;
        #pragma unroll
        for (int k=1;k<7;++k) if (i >= cum[k]) r = k;
        int li = i - cum[r];
        int n = cum[r+1] - cum[r];
        float v = ws[r][li];
        __nv_bfloat16 h = __float2bfloat16(v);
        wb[ho[r] + li] = h;
        wb[ho[r] + n + li] = __float2bfloat16(v - __bfloat162float(h));
    }
}

// ---------------- qkv fp32 -> bf16 hi/lo (0.125 folded into Q cols) --------
__global__ __launch_bounds__(256) void qkvconv_kernel(
    const float* __restrict__ q, __nv_bfloat16* __restrict__ hi,
    __nv_bfloat16* __restrict__ lo, int n)
{
    for (int i = blockIdx.x*256 + threadIdx.x; i < n; i += gridDim.x*256){
        int col = i % 2304;
        float v = q[i];
        if (col < 768) v *= 0.125f;
        __nv_bfloat16 h = __float2bfloat16(v);
        hi[i] = h;
        lo[i] = __float2bfloat16(v - __bfloat162float(h));
    }
}

// ---------------- HMMA split-bf16 GEMM, cp.async + ldmatrix ----------------
#define TG_BUF   40960
#define TG_SMEM  (2*TG_BUF)

__global__ __launch_bounds__(256) void tgemm_nt(
    const __nv_bfloat16* __restrict__ Ahi, const __nv_bfloat16* __restrict__ Alo,
    const __nv_bfloat16* __restrict__ Whi, const __nv_bfloat16* __restrict__ Wlo,
    const float* __restrict__ bias,
    float* __restrict__ C, __nv_bfloat16* __restrict__ Chi, __nv_bfloat16* __restrict__ Clo,
    int M, int N, int K,
    const float* __restrict__ res, int resMode, int doGelu)
{
    extern __shared__ char smem[];
    uint32_t sb = smem_u32(smem);
    int tid = threadIdx.x;
    int wid = tid >> 5, lane = tid & 31;
    int warpM = wid >> 2, warpN = wid & 3;
    int g = lane >> 2, tg = lane & 3;
    int lrow = lane & 7, lt = lane >> 3;
    int bm = blockIdx.y*128, bn = blockIdx.x*128;

    int NC = K >> 5;

    auto stage = [&](int c, int buf){
        int k0 = c << 5;
        uint32_t bufb = sb + buf*TG_BUF;
        #pragma unroll
        for (int u = 0; u < 8; ++u){
            int idx = u*256 + tid;
            int arr = idx >> 9;
            int rem = idx & 511;
            int row = rem >> 2;
            int q = rem & 3;
            uint32_t dst = bufb + arr*10240 + row*80 + q*16;
            const __nv_bfloat16* src;
            int valid = 1;
            if (arr < 2){
                int gm = bm + row;
                valid = (gm < M);
                const __nv_bfloat16* base = (arr == 0) ? Ahi : Alo;
                src = base + (size_t)(valid ? gm : 0)*K + k0 + q*8;
            } else {
                int gn = bn + row;
                const __nv_bfloat16* base = (arr == 2) ? Whi : Wlo;
                src = base + (size_t)gn*K + k0 + q*8;
            }
            cp16(dst, src, valid);
        }
        cp_commit();
    };

    float acc[4][4][4];
    #pragma unroll
    for (int i=0;i<4;++i)
        #pragma unroll
        for (int j=0;j<4;++j)
            #pragma unroll
            for (int q=0;q<4;++q) acc[i][j][q]=0.f;

    stage(0, 0);
    for (int c = 0; c < NC; ++c){
        int buf = c & 1;
        if (c+1 < NC){ stage(c+1, buf^1); cp_wait1(); }
        else cp_wait0();
        __syncthreads();

        uint32_t bufA = sb + buf*TG_BUF;

        #pragma unroll
        for (int ks = 0; ks < 2; ++ks){
            int kb0 = ks*16;
            uint32_t ahi[4][4], alo[4][4];
            #pragma unroll
            for (int i=0;i<4;++i){
                int row = warpM*64 + i*16 + lrow + ((lt&1)<<3);
                uint32_t off = (uint32_t)(row*40 + kb0 + ((lt>>1)<<3)) << 1;
                ldsm4(ahi[i], bufA + off);
                ldsm4(alo[i], bufA + 10240 + off);
            }
            uint32_t bhi[4][2], blo[4][2];
            #pragma unroll
            for (int jp=0;jp<2;++jp){
                int row = warpN*32 + jp*16 + lrow + ((lt>>1)<<3);
                uint32_t off = (uint32_t)(row*40 + kb0 + ((lt&1)<<3)) << 1;
                uint32_t t[4];
                ldsm4(t, bufA + 20480 + off);
                bhi[jp*2][0]=t[0]; bhi[jp*2][1]=t[1];
                bhi[jp*2+1][0]=t[2]; bhi[jp*2+1][1]=t[3];
                ldsm4(t, bufA + 30720 + off);
                blo[jp*2][0]=t[0]; blo[jp*2][1]=t[1];
                blo[jp*2+1][0]=t[2]; blo[jp*2+1][1]=t[3];
            }
            #pragma unroll
            for (int i=0;i<4;++i)
                #pragma unroll
                for (int j=0;j<4;++j){
                    mma_bf16(acc[i][j], ahi[i], bhi[j]);
                    mma_bf16(acc[i][j], ahi[i], blo[j]);
                    mma_bf16(acc[i][j], alo[i], bhi[j]);
                }
        }
        __syncthreads();
    }

    #pragma unroll
    for (int i=0;i<4;++i){
        #pragma unroll
        for (int half=0; half<2; ++half){
            int m = bm + warpM*64 + i*16 + g + half*8;
            if (m >= M) continue;
            const float* rrow = nullptr;
            if (resMode == 1) rrow = res + (size_t)m*N;
            else if (resMode == 2){ int bb = m>>12, jj = m&4095; rrow = res + (size_t)(bb*4097+1+jj)*N; }
            #pragma unroll
            for (int j=0;j<4;++j){
                int n0 = bn + warpN*32 + j*8 + tg*2;
                float v0 = acc[i][j][half*2+0];
                float v1 = acc[i][j][half*2+1];
                if (bias){ float2 bv = *(const float2*)&bias[n0]; v0 += bv.x; v1 += bv.y; }
                if (doGelu){ v0 = gelu_exact(v0); v1 = gelu_exact(v1); }
                if (rrow){ float2 rv = *(const float2*)&rrow[n0]; v0 += rv.x; v1 += rv.y; }
                if (Chi){
                    uint32_t hh, ll;
                    split2(v0, v1, hh, ll);
                    *(uint32_t*)&Chi[(size_t)m*N + n0] = hh;
                    *(uint32_t*)&Clo[(size_t)m*N + n0] = ll;
                } else {
                    *(float2*)&C[(size_t)m*N + n0] = make_float2(v0, v1);
                }
            }
        }
    }
}

// ---------------- HMMA flash attention v2 ----------------------------------
// grid (9, 96): 128 i-rows/CTA, 8 warps x 16-row bands; j-tiles of 64.
// Q held in registers; K non-trans ldsm (like tgemm B); V row-major + ldsm.trans.
#define FL_QBYTES (128*72*2)           // 18432
#define FL_KVARR  (64*72*2)            // 9216
#define FL_KVBUF  (4*FL_KVARR)         // 36864
#define FL_SMEM   (2*FL_QBYTES + 2*FL_KVBUF)   // 110592

__global__ __launch_bounds__(256) void flash_mma_kernel(
    const __nv_bfloat16* __restrict__ qh, const __nv_bfloat16* __restrict__ ql,
    const float* __restrict__ bias,
    __nv_bfloat16* __restrict__ outH, __nv_bfloat16* __restrict__ outL)
{
    extern __shared__ char fsm[];
    uint32_t sb = smem_u32(fsm);
    uint32_t Qh = sb, Ql = sb + FL_QBYTES;
    uint32_t KV = sb + 2*FL_QBYTES;
    int bh = blockIdx.y, bt = bh/12, h = bh - bt*12;
    int i0 = blockIdx.x*128;
    int tid = threadIdx.x, w = tid>>5, lane = tid&31;
    int g = lane>>2, tg = lane&3;
    int lrow = lane&7, lt = lane>>3;
    size_t qbase = (size_t)(bt*1025)*2304u + h*64;

    // stage Q (2048 cp16; commits with KV tile 0)
    #pragma unroll
    for (int u=0;u<8;++u){
        int idx = u*256+tid;
        int arr = idx>>10, rem = idx&1023, row = rem>>3, q = rem&7;
        int gi = i0+row;
        uint32_t dst = (arr? Ql:Qh) + row*144 + q*16;
        const __nv_bfloat16* src = (arr? ql:qh) + qbase + (size_t)(gi<1025?gi:0)*2304u + q*8;
        cp16(dst, src, gi<1025);
    }
    auto stage_kv = [&](int j0, int buf){
        uint32_t kb = KV + buf*FL_KVBUF;
        #pragma unroll
        for (int u=0;u<8;++u){
            int idx = u*256+tid;
            int arr = idx>>9, rem = idx&511, row = rem>>3, q = rem&7;
            int gj = j0+row;
            uint32_t dst = kb + arr*FL_KVARR + row*144 + q*16;
            int voff = (arr>=2)? 1536:768;
            const __nv_bfloat16* bsrc = (arr&1)? ql:qh;
            const __nv_bfloat16* src = bsrc + qbase + (size_t)(gj<1025?gj:0)*2304u + voff + q*8;
            cp16(dst, src, gj<1025);
        }
        cp_commit();
    };
    stage_kv(0,0);
    stage_kv(64,1);

    uint32_t qfh[4][4], qfl[4][4];
    float m0=-1e30f, m1=-1e30f, l0=0.f, l1=0.f;
    float o[8][4];
    #pragma unroll
    for (int d=0;d<8;++d){ o[d][0]=0.f;o[d][1]=0.f;o[d][2]=0.f;o[d][3]=0.f; }

    int gi_g = i0 + w*16 + g;
    int gi_h = gi_g + 8;
    const float* brow0 = bias + ((size_t)h*1025u + gi_g)*1025u;
    const float* brow1 = bias + ((size_t)h*1025u + gi_h)*1025u;

    for (int jt=0; jt<17; ++jt){
        if (jt < 16) cp_wait1(); else cp_wait0();
        __syncthreads();
        if (jt == 0){
            #pragma unroll
            for (int kf=0;kf<4;++kf){
                int row = w*16 + lrow + ((lt&1)<<3);
                uint32_t off = (uint32_t)(row*72 + kf*16 + ((lt>>1)<<3))<<1;
                ldsm4(qfh[kf], Qh + off);
                ldsm4(qfl[kf], Ql + off);
            }
        }
        int buf = jt & 1;
        uint32_t Kh = KV + buf*FL_KVBUF;
        uint32_t Kl = Kh + FL_KVARR;
        uint32_t Vh = Kl + FL_KVARR;
        uint32_t Vl = Vh + FL_KVARR;
        int j0 = jt*64;

        // ---- S = Q @ K^T (3-product split) ----
        float s[8][4];
        #pragma unroll
        for (int nf=0;nf<8;++nf){ s[nf][0]=0.f;s[nf][1]=0.f;s[nf][2]=0.f;s[nf][3]=0.f; }
        #pragma unroll
        for (int kf=0; kf<4; ++kf){
            #pragma unroll
            for (int jp=0; jp<4; ++jp){
                int row = jp*16 + lrow + ((lt>>1)<<3);
                uint32_t off = (uint32_t)(row*72 + kf*16 + ((lt&1)<<3))<<1;
                uint32_t th[4], tl[4];
                ldsm4(th, Kh + off);
                ldsm4(tl, Kl + off);
                uint32_t b0h[2]={th[0],th[1]}, b1h[2]={th[2],th[3]};
                uint32_t b0l[2]={tl[0],tl[1]}, b1l[2]={tl[2],tl[3]};
                mma_bf16(s[jp*2],   qfh[kf], b0h);
                mma_bf16(s[jp*2],   qfh[kf], b0l);
                mma_bf16(s[jp*2],   qfl[kf], b0h);
                mma_bf16(s[jp*2+1], qfh[kf], b1h);
                mma_bf16(s[jp*2+1], qfh[kf], b1l);
                mma_bf16(s[jp*2+1], qfl[kf], b1h);
            }
        }
        // ---- bias + mask ----
        #pragma unroll
        for (int nf=0;nf<8;++nf){
            int gj = j0 + nf*8 + tg*2;
            if (gi_g < 1025 && gj   < 1025) s[nf][0] += brow0[gj];   else s[nf][0] = -1e30f;
            if (gi_g < 1025 && gj+1 < 1025) s[nf][1] += brow0[gj+1]; else s[nf][1] = -1e30f;
            if (gi_h < 1025 && gj   < 1025) s[nf][2] += brow1[gj];   else s[nf][2] = -1e30f;
            if (gi_h < 1025 && gj+1 < 1025) s[nf][3] += brow1[gj+1]; else s[nf][3] = -1e30f;
        }
        // ---- online softmax (warp-local; rows g and g+8) ----
        float rm0 = -1e30f, rm1 = -1e30f;
        #pragma unroll
        for (int nf=0;nf<8;++nf){
            rm0 = fmaxf(rm0, fmaxf(s[nf][0], s[nf][1]));
            rm1 = fmaxf(rm1, fmaxf(s[nf][2], s[nf][3]));
        }
        rm0 = fmaxf(rm0, __shfl_xor_sync(0xffffffffu, rm0, 1));
        rm0 = fmaxf(rm0, __shfl_xor_sync(0xffffffffu, rm0, 2));
        rm1 = fmaxf(rm1, __shfl_xor_sync(0xffffffffu, rm1, 1));
        rm1 = fmaxf(rm1, __shfl_xor_sync(0xffffffffu, rm1, 2));
        float mn0 = fmaxf(m0, rm0), mn1 = fmaxf(m1, rm1);
        float c0 = __expf(m0 - mn0), c1 = __expf(m1 - mn1);
        m0 = mn0; m1 = mn1;
        float sum0 = 0.f, sum1 = 0.f;
        #pragma unroll
        for (int nf=0;nf<8;++nf){
            s[nf][0] = __expf(s[nf][0]-mn0);
            s[nf][1] = __expf(s[nf][1]-mn0);
            s[nf][2] = __expf(s[nf][2]-mn1);
            s[nf][3] = __expf(s[nf][3]-mn1);
            sum0 += s[nf][0] + s[nf][1];
            sum1 += s[nf][2] + s[nf][3];
        }
        sum0 += __shfl_xor_sync(0xffffffffu, sum0, 1);
        sum0 += __shfl_xor_sync(0xffffffffu, sum0, 2);
        sum1 += __shfl_xor_sync(0xffffffffu, sum1, 1);
        sum1 += __shfl_xor_sync(0xffffffffu, sum1, 2);
        l0 = l0*c0 + sum0;
        l1 = l1*c1 + sum1;
        #pragma unroll
        for (int d=0;d<8;++d){ o[d][0]*=c0; o[d][1]*=c0; o[d][2]*=c1; o[d][3]*=c1; }

        // ---- O += P @ V (3-product split; V frags via ldsm.trans) ----
        #pragma unroll
        for (int kk=0; kk<4; ++kk){
            uint32_t pah[4], pal[4];
            #pragma unroll
            for (int half=0; half<2; ++half){
                int nf = kk*2 + half;
                float p0 = s[nf][0], p1 = s[nf][1], p2 = s[nf][2], p3 = s[nf][3];
                uint32_t h01,l01,h23,l23;
                split2(p0,p1,h01,l01);
                split2(p2,p3,h23,l23);
                pah[half*2+0] = h01;
                pah[half*2+1] = h23;
                pal[half*2+0] = l01;
                pal[half*2+1] = l23;
            }
            // trans ldsm: lane -> mat = lt? use (lane>>3, lane&7)
            int mat = lane >> 3, r = lane & 7;
            int jrow = kk*16 + ((mat&1)<<3) + r;
            #pragma unroll
            for (int dp=0; dp<4; ++dp){
                int dcol = dp*16 + ((mat>>1)<<3);
                uint32_t off = (uint32_t)(jrow*72 + dcol)<<1;
                uint32_t tvh[4], tvl[4];
                ldsm4t(tvh, Vh + off);
                ldsm4t(tvl, Vl + off);
                uint32_t b0h[2]={tvh[0],tvh[1]}, b1h[2]={tvh[2],tvh[3]};
                uint32_t b0l[2]={tvl[0],tvl[1]}, b1l[2]={tvl[2],tvl[3]};
                mma_bf16(o[dp*2],   pah, b0h);
                mma_bf16(o[dp*2],   pah, b0l);
                mma_bf16(o[dp*2],   pal, b0h);
                mma_bf16(o[dp*2+1], pah, b1h);
                mma_bf16(o[dp*2+1], pah, b1l);
                mma_bf16(o[dp*2+1], pal, b1h);
            }
        }
        __syncthreads();
        if (jt+2 <= 16) stage_kv((jt+2)*64, buf);
    }

    // ---- store (split bf16 hi/lo) ----
    float inv0 = 1.0f/l0, inv1 = 1.0f/l1;
    #pragma unroll
    for (int df=0; df<8; ++df){
        int d0 = df*8 + tg*2;
        if (gi_g < 1025){
            uint32_t hh, ll;
            split2(o[df][0]*inv0, o[df][1]*inv0, hh, ll);
            size_t ob = (size_t)(bt*1025+gi_g)*768u + h*64 + d0;
            *(uint32_t*)&outH[ob] = hh;
            *(uint32_t*)&outL[ob] = ll;
        }
        if (gi_h < 1025){
            uint32_t hh, ll;
            split2(o[df][2]*inv1, o[df][3]*inv1, hh, ll);
            size_t ob = (size_t)(bt*1025+gi_h)*768u + h*64 + d0;
            *(uint32_t*)&outH[ob] = hh;
            *(uint32_t*)&outL[ob] = ll;
        }
    }
}

// ---------------- layernorm (bf16 hi/lo output) ----------------------------
__global__ __launch_bounds__(256) void ln_kernel(
    const float* __restrict__ src, const float* __restrict__ xsrc,
    __nv_bfloat16* __restrict__ dstH, __nv_bfloat16* __restrict__ dstL,
    const float* __restrict__ g, const float* __restrict__ b, int mode)
{
    __shared__ float red[8];
    int r = blockIdx.x;
    int t = threadIdx.x;
    int lane = t & 31, warp = t >> 5;
    const float* in; size_t base;
    if (mode == 0){ in = src; base = (size_t)r*768u; }
    else if (mode == 1){ int bb = r>>12; int j = r & 4095; in = xsrc; base = (size_t)(bb*4097 + 1 + j)*768u; }
    else {
        int bt = r/1025, pos = r - bt*1025;
        int bb = bt>>2, tt = bt&3;
        if (pos == 0){ in = xsrc; base = (size_t)(bb*4097)*768u; }
        else { int n = pos-1; in = src; base = (size_t)(bb*4096 + n*4 + tt)*768u; }
    }
    float v0 = in[base+t], v1 = in[base+t+256], v2 = in[base+t+512];
    float s = v0+v1+v2;
    #pragma unroll
    for (int o=16;o>0;o>>=1) s += __shfl_xor_sync(0xffffffffu, s, o);
    if (lane==0) red[warp]=s;
    __syncthreads();
    if (warp==0){
        float w = red[lane&7];
        #pragma unroll
        for (int o=4;o>0;o>>=1) w += __shfl_xor_sync(0xffffffffu, w, o);
        if (lane==0) red[0]=w;
    }
    __syncthreads();
    float mean = red[0]*(1.0f/768.0f);
    float d0=v0-mean, d1=v1-mean, d2=v2-mean;
    float q = d0*d0+d1*d1+d2*d2;
    #pragma unroll
    for (int o=16;o>0;o>>=1) q += __shfl_xor_sync(0xffffffffu, q, o);
    __syncthreads();
    if (lane==0) red[warp]=q;
    __syncthreads();
    if (warp==0){
        float w = red[lane&7];
        #pragma unroll
        for (int o=4;o>0;o>>=1) w += __shfl_xor_sync(0xffffffffu, w, o);
        if (lane==0) red[0]=w;
    }
    __syncthreads();
    float var = red[0]*(1.0f/768.0f);
    float rstd = rsqrtf(var + 1e-5f);
    size_t ob = (size_t)r*768u;
    #pragma unroll
    for (int p=0;p<3;++p){
        int col = t + p*256;
        float d = (p==0)?d0:((p==1)?d1:d2);
        float val = d*rstd*g[col] + b[col];
        __nv_bfloat16 h = __float2bfloat16(val);
        dstH[ob+col] = h;
        dstL[ob+col] = __float2bfloat16(val - __bfloat162float(h));
    }
}

// ---------------- geometry bias -------------------------------------------
__global__ __launch_bounds__(256) void bias_kernel(
    const float* __restrict__ wg_w, const float* __restrict__ wg_b,
    float* __restrict__ bias)
{
    __shared__ float sw[768];
    __shared__ float sc[12];
    int t = threadIdx.x;
    for (int i=t;i<768;i+=256) sw[i]=wg_w[i];
    __syncthreads();
    if (t < 12){
        float s = wg_b[t];
        #pragma unroll
        for (int k=48;k<64;++k) s += sw[t*64+k];
        sc[t] = s;
    }
    __syncthreads();
    size_t idx = (size_t)blockIdx.x*256u + t;
    if (idx >= (size_t)1025u*1025u) return;
    int i = (int)(idx/1025u), j = (int)(idx - (size_t)i*1025u);
    if (i==0 || j==0){
        #pragma unroll
        for (int h=0;h<12;++h) bias[(size_t)h*1025u*1025u + idx] = 0.f;
        return;
    }
    int a = i-1, b2 = j-1;
    float fx = (float)((a>>5)-(b2>>5)) * (1.0f/32.0f);
    float fy = (float)((a&31)-(b2&31)) * (1.0f/32.0f);
    const float inv_wbox = 1.0f/1.03125f;
    float dx = logf(fmaxf(fabsf(fx*inv_wbox), 0.001f));
    float dy = logf(fmaxf(fabsf(fy*inv_wbox), 0.001f));
    const float dm[8] = {1.0f, 0.42169650342f, 0.1778279410f, 0.074989420933f,
                         0.03162277660f, 0.013335214322f, 0.0056234132519f, 0.0023713737057f};
    float sx[8], cx[8], sy[8], cy[8];
    #pragma unroll
    for (int k=0;k<8;++k){
        sincosf(100.0f*dx*dm[k], &sx[k], &cx[k]);
        sincosf(100.0f*dy*dm[k], &sy[k], &cy[k]);
    }
    #pragma unroll
    for (int h=0;h<12;++h){
        const float* w = sw + h*64;
        float acc = sc[h];
        #pragma unroll
        for (int k=0;k<8;++k)
            acc += sx[k]*w[k] + sy[k]*w[8+k] + cx[k]*w[32+k] + cy[k]*w[40+k];
        float wv = fmaxf(acc, 0.0f);
        bias[(size_t)h*1025u*1025u + idx] = logf(fmaxf(wv, 1e-6f));
    }
}

// ---------------- temporal attention (bf16 hi/lo out) ----------------------
__global__ __launch_bounds__(256) void temporal_attn_kernel(
    const float* __restrict__ qkv,
    __nv_bfloat16* __restrict__ outH, __nv_bfloat16* __restrict__ outL)
{
    int gw = (blockIdx.x*256 + threadIdx.x) >> 5;
    int lane = threadIdx.x & 31;
    if (gw >= 2048*12) return;
    int s = gw/12, h = gw - s*12;
    size_t base = (size_t)(s*4)*2304u + h*64 + lane*2;
    float2 q[4],k[4],v[4];
    #pragma unroll
    for (int i=0;i<4;++i){
        q[i] = *(const float2*)(qkv + base + (size_t)i*2304u);
        k[i] = *(const float2*)(qkv + base + (size_t)i*2304u + 768u);
        v[i] = *(const float2*)(qkv + base + (size_t)i*2304u + 1536u);
    }
    float sc[16];
    #pragma unroll
    for (int i=0;i<4;++i)
        #pragma unroll
        for (int j=0;j<4;++j)
            sc[i*4+j] = q[i].x*k[j].x + q[i].y*k[j].y;
    #pragma unroll
    for (int t2=0;t2<16;++t2)
        #pragma unroll
        for (int off=16; off>0; off>>=1)
            sc[t2] += __shfl_xor_sync(0xffffffffu, sc[t2], off);
    #pragma unroll
    for (int i=0;i<4;++i){
        float s0=sc[i*4+0]*0.125f, s1=sc[i*4+1]*0.125f, s2=sc[i*4+2]*0.125f, s3=sc[i*4+3]*0.125f;
        float m = fmaxf(fmaxf(s0,s1),fmaxf(s2,s3));
        float e0=expf(s0-m), e1=expf(s1-m), e2=expf(s2-m), e3=expf(s3-m);
        float inv = 1.0f/(e0+e1+e2+e3);
        float ox = (e0*v[0].x + e1*v[1].x + e2*v[2].x + e3*v[3].x)*inv;
        float oy = (e0*v[0].y + e1*v[1].y + e2*v[2].y + e3*v[3].y)*inv;
        uint32_t hh, ll;
        split2(ox, oy, hh, ll);
        size_t o = (size_t)(s*4+i)*768u + h*64 + lane*2;
        *(uint32_t*)&outH[o] = hh;
        *(uint32_t*)&outL[o] = ll;
    }
}

// ---------------- combine -------------------------------------------------
__global__ __launch_bounds__(256) void combine_kernel(
    const float* __restrict__ x, const float* __restrict__ xt,
    const float* __restrict__ res_s, float* __restrict__ out)
{
    size_t idx = (size_t)blockIdx.x*256u + threadIdx.x;
    if (idx >= (size_t)2u*4097u*768u) return;
    int c = (int)(idx % 768u);
    size_t row = idx / 768u;
    int b = (int)(row / 4097u);
    int rr = (int)(row - (size_t)b*4097u);
    float v;
    if (rr == 0){
        float s = 0.f;
        #pragma unroll
        for (int t2=0;t2<4;++t2)
            s += res_s[((size_t)((b*4+t2)*1025))*768u + c];
        v = x[row*768u + c] + 0.25f*s;
    } else {
        int qq = rr-1; int n = qq>>2, t2 = qq&3;
        v = xt[((size_t)(b*4096 + qq))*768u + c]
          + res_s[((size_t)((b*4+t2)*1025 + 1 + n))*768u + c];
    }
    out[row*768u + c] = v;
}

// ---------------- launcher -------------------------------------------------
extern "C" void kernel_launch(void* const* d_in, const int* in_sizes, int n_in,
                              void* d_out, int out_size)
{
    const float* x       = (const float*)d_in[0];
    const float* norm1_g = (const float*)d_in[1];
    const float* norm1_b = (const float*)d_in[2];
    const float* qkv_w   = (const float*)d_in[3];
    const float* proj_w  = (const float*)d_in[4];
    const float* proj_b  = (const float*)d_in[5];
    const float* wg_w    = (const float*)d_in[6];
    const float* wg_b    = (const float*)d_in[7];
    const float* tnorm1_g= (const float*)d_in[8];
    const float* tnorm1_b= (const float*)d_in[9];
    const float* tqkv_w  = (const float*)d_in[10];
    const float* tproj_w = (const float*)d_in[11];
    const float* tproj_b = (const float*)d_in[12];
    const float* tfc_w   = (const float*)d_in[13];
    const float* tfc_b   = (const float*)d_in[14];
    const float* norm2_g = (const float*)d_in[15];
    const float* norm2_b = (const float*)d_in[16];
    const float* fc1_w   = (const float*)d_in[17];
    const float* fc1_b   = (const float*)d_in[18];
    const float* fc2_w   = (const float*)d_in[19];
    const float* fc2_b   = (const float*)d_in[20];
    float* out = (float*)d_out;

    float* base = nullptr;
    cudaGetSymbolAddress((void**)&base, g_scratch);
    float* p_qkv  = base + OFF_QKV;
    float* p_xt   = base + OFF_XT;
    float* p_res  = base + OFF_RES;
    float* p_bias = base + OFF_BIAS;
    __nv_bfloat16* wb = (__nv_bfloat16*)(base + OFF_WBF);
    __nv_bfloat16* bf = (__nv_bfloat16*)(base + OFF_BF);
    __nv_bfloat16 *lnH = bf+BO_LNH,  *lnL = bf+BO_LNL;
    __nv_bfloat16 *atH = bf+BO_ATTH, *atL = bf+BO_ATTL;
    __nv_bfloat16 *r2H = bf+BO_R2H,  *r2L = bf+BO_R2L;
    __nv_bfloat16 *hH  = bf+BO_HH,   *hL  = bf+BO_HL;
    __nv_bfloat16* qbh = (__nv_bfloat16*)(base + OFF_QB);
    __nv_bfloat16* qbl = qbh + 18892800u;

    cudaFuncSetAttribute(flash_mma_kernel,
                         cudaFuncAttributeMaxDynamicSharedMemorySize, FL_SMEM);
    cudaFuncSetAttribute(tgemm_nt,
                         cudaFuncAttributeMaxDynamicSharedMemorySize, TG_SMEM);

    // 1: fused weight conversion
    wconv_all<<<2048,256>>>(tqkv_w, qkv_w, tproj_w, proj_w, tfc_w, fc1_w, fc2_w, wb);

    // ---- temporal branch ----
    ln_kernel<<<8192,256>>>(nullptr, x, lnH, lnL, tnorm1_g, tnorm1_b, 1);
    tgemm_nt<<<dim3(18,64),256,TG_SMEM>>>(lnH, lnL, wb+WO_TQKV, wb+WO_TQKV+1769472u,
        nullptr, p_qkv, nullptr, nullptr, 8192, 2304, 768, nullptr, 0, 0);
    temporal_attn_kernel<<<3072,256>>>(p_qkv, atH, atL);
    tgemm_nt<<<dim3(6,64),256,TG_SMEM>>>(atH, atL, wb+WO_TPROJ, wb+WO_TPROJ+589824u,
        tproj_b, nullptr, r2H, r2L, 8192, 768, 768, nullptr, 0, 0);
    tgemm_nt<<<dim3(6,64),256,TG_SMEM>>>(r2H, r2L, wb+WO_TFC, wb+WO_TFC+589824u,
        tfc_b, p_xt, nullptr, nullptr, 8192, 768, 768, x, 2, 0);

    // ---- spatial branch ----
    ln_kernel<<<8200,256>>>(p_xt, x, lnH, lnL, norm1_g, norm1_b, 2);
    tgemm_nt<<<dim3(18,65),256,TG_SMEM>>>(lnH, lnL, wb+WO_QKV, wb+WO_QKV+1769472u,
        nullptr, p_qkv, nullptr, nullptr, 8200, 2304, 768, nullptr, 0, 0);
    bias_kernel<<<4105,256>>>(wg_w, wg_b, p_bias);
    qkvconv_kernel<<<4096,256>>>(p_qkv, qbh, qbl, 18892800);
    flash_mma_kernel<<<dim3(9,96),256,FL_SMEM>>>(qbh, qbl, p_bias, atH, atL);
    tgemm_nt<<<dim3(6,65),256,TG_SMEM>>>(atH, atL, wb+WO_PROJ, wb+WO_PROJ+589824u,
        proj_b, p_res, nullptr, nullptr, 8200, 768, 768, nullptr, 0, 0);
    combine_kernel<<<24582,256>>>(x, p_xt, p_res, out);

    // ---- MLP (chunked over 2x4097 rows) ----
    ln_kernel<<<8194,256>>>(out, nullptr, lnH, lnL, norm2_g, norm2_b, 0);
    for (int ch=0; ch<2; ++ch){
        size_t ro = (size_t)ch*4097u;
        tgemm_nt<<<dim3(24,33),256,TG_SMEM>>>(lnH + ro*768u, lnL + ro*768u,
            wb+WO_FC1, wb+WO_FC1+2359296u, fc1_b, nullptr, hH, hL,
            4097, 3072, 768, nullptr, 0, 1);
        tgemm_nt<<<dim3(6,33),256,TG_SMEM>>>(hH, hL, wb+WO_FC2, wb+WO_FC2+2359296u,
            fc2_b, out + ro*768u, nullptr, nullptr, 4097, 768, 3072, out + ro*768u, 1, 0);
    }
}

// round 14
// speedup vs baseline: 1.5670x; 1.0164x over previous
#include <cuda_runtime.h>
#include <cuda_bf16.h>
#include <math.h>
#include <stdint.h>

// ---------------- consolidated scratch (single symbol, ~418MB) -------------
#define OFF_QKV   0ull                       // 18,892,800 f32
#define OFF_XT    18892800ull                // 6,291,456 f32
#define OFF_RES   25184256ull                // 6,297,600 f32
#define OFF_BIAS  31481856ull                // 12,607,504 f32
#define OFF_WBF   44089360ull                // 10,027,008 f32 (weights bf16 h/l)
#define OFF_BF    54116368ull                // activation bf16 region
#define OFF_QB    85589008ull                // qkv bf16 hi/lo: 2*18,892,800 bf16
#define SCRATCH_TOTAL 104481808ull
__device__ float g_scratch[SCRATCH_TOTAL];

// bf16 activation offsets (in bf16 elements within OFF_BF region)
#define BO_LNH   0u
#define BO_LNL   6297600u
#define BO_ATTH  12595200u
#define BO_ATTL  18892800u
#define BO_R2H   25190400u
#define BO_R2L   31481856u
#define BO_HH    37773312u
#define BO_HL    50359296u

// weight offsets (bf16 elements; hi then lo contiguous)
#define WO_TQKV  0u
#define WO_QKV   3538944u
#define WO_TPROJ 7077888u
#define WO_PROJ  8257536u
#define WO_TFC   9437184u
#define WO_FC1   10616832u
#define WO_FC2   15335424u

__device__ __forceinline__ float gelu_exact(float x){
    return 0.5f*x*(1.0f+erff(x*0.70710678118654752440f));
}
__device__ __forceinline__ void split2(float a, float b, uint32_t &h, uint32_t &l){
    __nv_bfloat16 ha=__float2bfloat16(a), hb=__float2bfloat16(b);
    __nv_bfloat162 hh=__halves2bfloat162(ha,hb);
    __nv_bfloat162 ll=__halves2bfloat162(
        __float2bfloat16(a-__bfloat162float(ha)),
        __float2bfloat16(b-__bfloat162float(hb)));
    h=*(uint32_t*)&hh; l=*(uint32_t*)&ll;
}
__device__ __forceinline__ uint32_t smem_u32(const void* p){
    uint32_t a;
    asm("{ .reg .u64 t; cvta.to.shared.u64 t, %1; cvt.u32.u64 %0, t; }" : "=r"(a) : "l"(p));
    return a;
}
__device__ __forceinline__ void cp16(uint32_t dst, const void* src, int valid){
    int sz = valid ? 16 : 0;
    asm volatile("cp.async.ca.shared.global [%0], [%1], 16, %2;"
                 :: "r"(dst), "l"(src), "r"(sz) : "memory");
}
__device__ __forceinline__ void cp_commit(){ asm volatile("cp.async.commit_group;" ::: "memory"); }
__device__ __forceinline__ void cp_wait1(){ asm volatile("cp.async.wait_group 1;" ::: "memory"); }
__device__ __forceinline__ void cp_wait0(){ asm volatile("cp.async.wait_group 0;" ::: "memory"); }
__device__ __forceinline__ void ldsm4(uint32_t* r, uint32_t addr){
    asm volatile("ldmatrix.sync.aligned.m8n8.x4.shared.b16 {%0,%1,%2,%3}, [%4];"
        : "=r"(r[0]), "=r"(r[1]), "=r"(r[2]), "=r"(r[3]) : "r"(addr));
}
__device__ __forceinline__ void ldsm4t(uint32_t* r, uint32_t addr){
    asm volatile("ldmatrix.sync.aligned.m8n8.x4.trans.shared.b16 {%0,%1,%2,%3}, [%4];"
        : "=r"(r[0]), "=r"(r[1]), "=r"(r[2]), "=r"(r[3]) : "r"(addr));
}
__device__ __forceinline__ void mma_bf16(float* d, const uint32_t* a, const uint32_t* b){
    asm volatile("mma.sync.aligned.m16n8k16.row.col.f32.bf16.bf16.f32 "
        "{%0,%1,%2,%3}, {%4,%5,%6,%7}, {%8,%9}, {%0,%1,%2,%3};"
        : "+f"(d[0]), "+f"(d[1]), "+f"(d[2]), "+f"(d[3])
        : "r"(a[0]), "r"(a[1]), "r"(a[2]), "r"(a[3]), "r"(b[0]), "r"(b[1]));
}

// ---------------- fused weight fp32 -> bf16 hi/lo conversion ---------------
__global__ __launch_bounds__(256) void wconv_all(
    const float* __restrict__ w0, const float* __restrict__ w1,
    const float* __restrict__ w2, const float* __restrict__ w3,
    const float* __restrict__ w4, const float* __restrict__ w5,
    const float* __restrict__ w6, __nv_bfloat16* __restrict__ wb)
{
    const float* ws[7] = {w0,w1,w2,w3,w4,w5,w6};
    const int cum[8] = {0,1769472,3538944,4128768,4718592,5308416,7667712,10027008};
    const unsigned ho[7] = {WO_TQKV,WO_QKV,WO_TPROJ,WO_PROJ,WO_TFC,WO_FC1,WO_FC2};
    for (int i = blockIdx.x*256 + threadIdx.x; i < 10027008; i += gridDim.x*256){
        int r = 0;
        #pragma unroll
        for (int k=1;k<7;++k) if (i >= cum[k]) r = k;
        int li = i - cum[r];
        int n = cum[r+1] - cum[r];
        float v = ws[r][li];
        __nv_bfloat16 h = __float2bfloat16(v);
        wb[ho[r] + li] = h;
        wb[ho[r] + n + li] = __float2bfloat16(v - __bfloat162float(h));
    }
}

// ---------------- HMMA split-bf16 GEMM, cp.async + ldmatrix ----------------
#define TG_BUF   40960
#define TG_SMEM  (2*TG_BUF)

__global__ __launch_bounds__(256) void tgemm_nt(
    const __nv_bfloat16* __restrict__ Ahi, const __nv_bfloat16* __restrict__ Alo,
    const __nv_bfloat16* __restrict__ Whi, const __nv_bfloat16* __restrict__ Wlo,
    const float* __restrict__ bias,
    float* __restrict__ C, __nv_bfloat16* __restrict__ Chi, __nv_bfloat16* __restrict__ Clo,
    int M, int N, int K,
    const float* __restrict__ res, int resMode, int doGelu, int qkvSplit)
{
    extern __shared__ char smem[];
    uint32_t sb = smem_u32(smem);
    int tid = threadIdx.x;
    int wid = tid >> 5, lane = tid & 31;
    int warpM = wid >> 2, warpN = wid & 3;
    int g = lane >> 2, tg = lane & 3;
    int lrow = lane & 7, lt = lane >> 3;
    int bm = blockIdx.y*128, bn = blockIdx.x*128;

    int NC = K >> 5;

    auto stage = [&](int c, int buf){
        int k0 = c << 5;
        uint32_t bufb = sb + buf*TG_BUF;
        #pragma unroll
        for (int u = 0; u < 8; ++u){
            int idx = u*256 + tid;
            int arr = idx >> 9;
            int rem = idx & 511;
            int row = rem >> 2;
            int q = rem & 3;
            uint32_t dst = bufb + arr*10240 + row*80 + q*16;
            const __nv_bfloat16* src;
            int valid = 1;
            if (arr < 2){
                int gm = bm + row;
                valid = (gm < M);
                const __nv_bfloat16* base = (arr == 0) ? Ahi : Alo;
                src = base + (size_t)(valid ? gm : 0)*K + k0 + q*8;
            } else {
                int gn = bn + row;
                const __nv_bfloat16* base = (arr == 2) ? Whi : Wlo;
                src = base + (size_t)gn*K + k0 + q*8;
            }
            cp16(dst, src, valid);
        }
        cp_commit();
    };

    float acc[4][4][4];
    #pragma unroll
    for (int i=0;i<4;++i)
        #pragma unroll
        for (int j=0;j<4;++j)
            #pragma unroll
            for (int q=0;q<4;++q) acc[i][j][q]=0.f;

    stage(0, 0);
    for (int c = 0; c < NC; ++c){
        int buf = c & 1;
        if (c+1 < NC){ stage(c+1, buf^1); cp_wait1(); }
        else cp_wait0();
        __syncthreads();

        uint32_t bufA = sb + buf*TG_BUF;

        #pragma unroll
        for (int ks = 0; ks < 2; ++ks){
            int kb0 = ks*16;
            uint32_t ahi[4][4], alo[4][4];
            #pragma unroll
            for (int i=0;i<4;++i){
                int row = warpM*64 + i*16 + lrow + ((lt&1)<<3);
                uint32_t off = (uint32_t)(row*40 + kb0 + ((lt>>1)<<3)) << 1;
                ldsm4(ahi[i], bufA + off);
                ldsm4(alo[i], bufA + 10240 + off);
            }
            uint32_t bhi[4][2], blo[4][2];
            #pragma unroll
            for (int jp=0;jp<2;++jp){
                int row = warpN*32 + jp*16 + lrow + ((lt>>1)<<3);
                uint32_t off = (uint32_t)(row*40 + kb0 + ((lt&1)<<3)) << 1;
                uint32_t t[4];
                ldsm4(t, bufA + 20480 + off);
                bhi[jp*2][0]=t[0]; bhi[jp*2][1]=t[1];
                bhi[jp*2+1][0]=t[2]; bhi[jp*2+1][1]=t[3];
                ldsm4(t, bufA + 30720 + off);
                blo[jp*2][0]=t[0]; blo[jp*2][1]=t[1];
                blo[jp*2+1][0]=t[2]; blo[jp*2+1][1]=t[3];
            }
            #pragma unroll
            for (int i=0;i<4;++i)
                #pragma unroll
                for (int j=0;j<4;++j){
                    mma_bf16(acc[i][j], ahi[i], bhi[j]);
                    mma_bf16(acc[i][j], ahi[i], blo[j]);
                    mma_bf16(acc[i][j], alo[i], bhi[j]);
                }
        }
        __syncthreads();
    }

    #pragma unroll
    for (int i=0;i<4;++i){
        #pragma unroll
        for (int half=0; half<2; ++half){
            int m = bm + warpM*64 + i*16 + g + half*8;
            if (m >= M) continue;
            const float* rrow = nullptr;
            if (resMode == 1) rrow = res + (size_t)m*N;
            else if (resMode == 2){ int bb = m>>12, jj = m&4095; rrow = res + (size_t)(bb*4097+1+jj)*N; }
            #pragma unroll
            for (int j=0;j<4;++j){
                int n0 = bn + warpN*32 + j*8 + tg*2;
                float v0 = acc[i][j][half*2+0];
                float v1 = acc[i][j][half*2+1];
                if (bias){ float2 bv = *(const float2*)&bias[n0]; v0 += bv.x; v1 += bv.y; }
                if (doGelu){ v0 = gelu_exact(v0); v1 = gelu_exact(v1); }
                if (rrow){ float2 rv = *(const float2*)&rrow[n0]; v0 += rv.x; v1 += rv.y; }
                if (Chi){
                    if (qkvSplit && n0 < 768){ v0 *= 0.125f; v1 *= 0.125f; }
                    uint32_t hh, ll;
                    split2(v0, v1, hh, ll);
                    *(uint32_t*)&Chi[(size_t)m*N + n0] = hh;
                    *(uint32_t*)&Clo[(size_t)m*N + n0] = ll;
                } else {
                    *(float2*)&C[(size_t)m*N + n0] = make_float2(v0, v1);
                }
            }
        }
    }
}

// ---------------- HMMA flash attention v2 ----------------------------------
#define FL_QBYTES (128*72*2)           // 18432
#define FL_KVARR  (64*72*2)            // 9216
#define FL_KVBUF  (4*FL_KVARR)         // 36864
#define FL_SMEM   (2*FL_QBYTES + 2*FL_KVBUF)   // 110592

__global__ __launch_bounds__(256) void flash_mma_kernel(
    const __nv_bfloat16* __restrict__ qh, const __nv_bfloat16* __restrict__ ql,
    const float* __restrict__ bias,
    __nv_bfloat16* __restrict__ outH, __nv_bfloat16* __restrict__ outL)
{
    extern __shared__ char fsm[];
    uint32_t sb = smem_u32(fsm);
    uint32_t Qh = sb, Ql = sb + FL_QBYTES;
    uint32_t KV = sb + 2*FL_QBYTES;
    int bh = blockIdx.y, bt = bh/12, h = bh - bt*12;
    int i0 = blockIdx.x*128;
    int tid = threadIdx.x, w = tid>>5, lane = tid&31;
    int g = lane>>2, tg = lane&3;
    int lrow = lane&7, lt = lane>>3;
    size_t qbase = (size_t)(bt*1025)*2304u + h*64;

    #pragma unroll
    for (int u=0;u<8;++u){
        int idx = u*256+tid;
        int arr = idx>>10, rem = idx&1023, row = rem>>3, q = rem&7;
        int gi = i0+row;
        uint32_t dst = (arr? Ql:Qh) + row*144 + q*16;
        const __nv_bfloat16* src = (arr? ql:qh) + qbase + (size_t)(gi<1025?gi:0)*2304u + q*8;
        cp16(dst, src, gi<1025);
    }
    auto stage_kv = [&](int j0, int buf){
        uint32_t kb = KV + buf*FL_KVBUF;
        #pragma unroll
        for (int u=0;u<8;++u){
            int idx = u*256+tid;
            int arr = idx>>9, rem = idx&511, row = rem>>3, q = rem&7;
            int gj = j0+row;
            uint32_t dst = kb + arr*FL_KVARR + row*144 + q*16;
            int voff = (arr>=2)? 1536:768;
            const __nv_bfloat16* bsrc = (arr&1)? ql:qh;
            const __nv_bfloat16* src = bsrc + qbase + (size_t)(gj<1025?gj:0)*2304u + voff + q*8;
            cp16(dst, src, gj<1025);
        }
        cp_commit();
    };
    stage_kv(0,0);
    stage_kv(64,1);

    uint32_t qfh[4][4], qfl[4][4];
    float m0=-1e30f, m1=-1e30f, l0=0.f, l1=0.f;
    float o[8][4];
    #pragma unroll
    for (int d=0;d<8;++d){ o[d][0]=0.f;o[d][1]=0.f;o[d][2]=0.f;o[d][3]=0.f; }

    int gi_g = i0 + w*16 + g;
    int gi_h = gi_g + 8;
    const float* brow0 = bias + ((size_t)h*1025u + gi_g)*1025u;
    const float* brow1 = bias + ((size_t)h*1025u + gi_h)*1025u;

    for (int jt=0; jt<17; ++jt){
        if (jt < 16) cp_wait1(); else cp_wait0();
        __syncthreads();
        if (jt == 0){
            #pragma unroll
            for (int kf=0;kf<4;++kf){
                int row = w*16 + lrow + ((lt&1)<<3);
                uint32_t off = (uint32_t)(row*72 + kf*16 + ((lt>>1)<<3))<<1;
                ldsm4(qfh[kf], Qh + off);
                ldsm4(qfl[kf], Ql + off);
            }
        }
        int buf = jt & 1;
        uint32_t Kh = KV + buf*FL_KVBUF;
        uint32_t Kl = Kh + FL_KVARR;
        uint32_t Vh = Kl + FL_KVARR;
        uint32_t Vl = Vh + FL_KVARR;
        int j0 = jt*64;

        float s[8][4];
        #pragma unroll
        for (int nf=0;nf<8;++nf){ s[nf][0]=0.f;s[nf][1]=0.f;s[nf][2]=0.f;s[nf][3]=0.f; }
        #pragma unroll
        for (int kf=0; kf<4; ++kf){
            #pragma unroll
            for (int jp=0; jp<4; ++jp){
                int row = jp*16 + lrow + ((lt>>1)<<3);
                uint32_t off = (uint32_t)(row*72 + kf*16 + ((lt&1)<<3))<<1;
                uint32_t th[4], tl[4];
                ldsm4(th, Kh + off);
                ldsm4(tl, Kl + off);
                uint32_t b0h[2]={th[0],th[1]}, b1h[2]={th[2],th[3]};
                uint32_t b0l[2]={tl[0],tl[1]}, b1l[2]={tl[2],tl[3]};
                mma_bf16(s[jp*2],   qfh[kf], b0h);
                mma_bf16(s[jp*2],   qfh[kf], b0l);
                mma_bf16(s[jp*2],   qfl[kf], b0h);
                mma_bf16(s[jp*2+1], qfh[kf], b1h);
                mma_bf16(s[jp*2+1], qfh[kf], b1l);
                mma_bf16(s[jp*2+1], qfl[kf], b1h);
            }
        }
        #pragma unroll
        for (int nf=0;nf<8;++nf){
            int gj = j0 + nf*8 + tg*2;
            if (gi_g < 1025 && gj   < 1025) s[nf][0] += brow0[gj];   else s[nf][0] = -1e30f;
            if (gi_g < 1025 && gj+1 < 1025) s[nf][1] += brow0[gj+1]; else s[nf][1] = -1e30f;
            if (gi_h < 1025 && gj   < 1025) s[nf][2] += brow1[gj];   else s[nf][2] = -1e30f;
            if (gi_h < 1025 && gj+1 < 1025) s[nf][3] += brow1[gj+1]; else s[nf][3] = -1e30f;
        }
        float rm0 = -1e30f, rm1 = -1e30f;
        #pragma unroll
        for (int nf=0;nf<8;++nf){
            rm0 = fmaxf(rm0, fmaxf(s[nf][0], s[nf][1]));
            rm1 = fmaxf(rm1, fmaxf(s[nf][2], s[nf][3]));
        }
        rm0 = fmaxf(rm0, __shfl_xor_sync(0xffffffffu, rm0, 1));
        rm0 = fmaxf(rm0, __shfl_xor_sync(0xffffffffu, rm0, 2));
        rm1 = fmaxf(rm1, __shfl_xor_sync(0xffffffffu, rm1, 1));
        rm1 = fmaxf(rm1, __shfl_xor_sync(0xffffffffu, rm1, 2));
        float mn0 = fmaxf(m0, rm0), mn1 = fmaxf(m1, rm1);
        float c0 = __expf(m0 - mn0), c1 = __expf(m1 - mn1);
        m0 = mn0; m1 = mn1;
        float sum0 = 0.f, sum1 = 0.f;
        #pragma unroll
        for (int nf=0;nf<8;++nf){
            s[nf][0] = __expf(s[nf][0]-mn0);
            s[nf][1] = __expf(s[nf][1]-mn0);
            s[nf][2] = __expf(s[nf][2]-mn1);
            s[nf][3] = __expf(s[nf][3]-mn1);
            sum0 += s[nf][0] + s[nf][1];
            sum1 += s[nf][2] + s[nf][3];
        }
        sum0 += __shfl_xor_sync(0xffffffffu, sum0, 1);
        sum0 += __shfl_xor_sync(0xffffffffu, sum0, 2);
        sum1 += __shfl_xor_sync(0xffffffffu, sum1, 1);
        sum1 += __shfl_xor_sync(0xffffffffu, sum1, 2);
        l0 = l0*c0 + sum0;
        l1 = l1*c1 + sum1;
        #pragma unroll
        for (int d=0;d<8;++d){ o[d][0]*=c0; o[d][1]*=c0; o[d][2]*=c1; o[d][3]*=c1; }

        #pragma unroll
        for (int kk=0; kk<4; ++kk){
            uint32_t pah[4], pal[4];
            #pragma unroll
            for (int half=0; half<2; ++half){
                int nf = kk*2 + half;
                uint32_t h01,l01,h23,l23;
                split2(s[nf][0], s[nf][1], h01, l01);
                split2(s[nf][2], s[nf][3], h23, l23);
                pah[half*2+0] = h01;
                pah[half*2+1] = h23;
                pal[half*2+0] = l01;
                pal[half*2+1] = l23;
            }
            int mat = lane >> 3, r = lane & 7;
            int jrow = kk*16 + ((mat&1)<<3) + r;
            #pragma unroll
            for (int dp=0; dp<4; ++dp){
                int dcol = dp*16 + ((mat>>1)<<3);
                uint32_t off = (uint32_t)(jrow*72 + dcol)<<1;
                uint32_t tvh[4], tvl[4];
                ldsm4t(tvh, Vh + off);
                ldsm4t(tvl, Vl + off);
                uint32_t b0h[2]={tvh[0],tvh[1]}, b1h[2]={tvh[2],tvh[3]};
                uint32_t b0l[2]={tvl[0],tvl[1]}, b1l[2]={tvl[2],tvl[3]};
                mma_bf16(o[dp*2],   pah, b0h);
                mma_bf16(o[dp*2],   pah, b0l);
                mma_bf16(o[dp*2],   pal, b0h);
                mma_bf16(o[dp*2+1], pah, b1h);
                mma_bf16(o[dp*2+1], pah, b1l);
                mma_bf16(o[dp*2+1], pal, b1h);
            }
        }
        __syncthreads();
        if (jt+2 <= 16) stage_kv((jt+2)*64, buf);
    }

    float inv0 = 1.0f/l0, inv1 = 1.0f/l1;
    #pragma unroll
    for (int df=0; df<8; ++df){
        int d0 = df*8 + tg*2;
        if (gi_g < 1025){
            uint32_t hh, ll;
            split2(o[df][0]*inv0, o[df][1]*inv0, hh, ll);
            size_t ob = (size_t)(bt*1025+gi_g)*768u + h*64 + d0;
            *(uint32_t*)&outH[ob] = hh;
            *(uint32_t*)&outL[ob] = ll;
        }
        if (gi_h < 1025){
            uint32_t hh, ll;
            split2(o[df][2]*inv1, o[df][3]*inv1, hh, ll);
            size_t ob = (size_t)(bt*1025+gi_h)*768u + h*64 + d0;
            *(uint32_t*)&outH[ob] = hh;
            *(uint32_t*)&outL[ob] = ll;
        }
    }
}

// ---------------- layernorm (bf16 hi/lo output) ----------------------------
__global__ __launch_bounds__(256) void ln_kernel(
    const float* __restrict__ src, const float* __restrict__ xsrc,
    __nv_bfloat16* __restrict__ dstH, __nv_bfloat16* __restrict__ dstL,
    const float* __restrict__ g, const float* __restrict__ b, int mode)
{
    __shared__ float red[8];
    int r = blockIdx.x;
    int t = threadIdx.x;
    int lane = t & 31, warp = t >> 5;
    const float* in; size_t base;
    if (mode == 0){ in = src; base = (size_t)r*768u; }
    else if (mode == 1){ int bb = r>>12; int j = r & 4095; in = xsrc; base = (size_t)(bb*4097 + 1 + j)*768u; }
    else {
        int bt = r/1025, pos = r - bt*1025;
        int bb = bt>>2, tt = bt&3;
        if (pos == 0){ in = xsrc; base = (size_t)(bb*4097)*768u; }
        else { int n = pos-1; in = src; base = (size_t)(bb*4096 + n*4 + tt)*768u; }
    }
    float v0 = in[base+t], v1 = in[base+t+256], v2 = in[base+t+512];
    float s = v0+v1+v2;
    #pragma unroll
    for (int o=16;o>0;o>>=1) s += __shfl_xor_sync(0xffffffffu, s, o);
    if (lane==0) red[warp]=s;
    __syncthreads();
    if (warp==0){
        float w = red[lane&7];
        #pragma unroll
        for (int o=4;o>0;o>>=1) w += __shfl_xor_sync(0xffffffffu, w, o);
        if (lane==0) red[0]=w;
    }
    __syncthreads();
    float mean = red[0]*(1.0f/768.0f);
    float d0=v0-mean, d1=v1-mean, d2=v2-mean;
    float q = d0*d0+d1*d1+d2*d2;
    #pragma unroll
    for (int o=16;o>0;o>>=1) q += __shfl_xor_sync(0xffffffffu, q, o);
    __syncthreads();
    if (lane==0) red[warp]=q;
    __syncthreads();
    if (warp==0){
        float w = red[lane&7];
        #pragma unroll
        for (int o=4;o>0;o>>=1) w += __shfl_xor_sync(0xffffffffu, w, o);
        if (lane==0) red[0]=w;
    }
    __syncthreads();
    float var = red[0]*(1.0f/768.0f);
    float rstd = rsqrtf(var + 1e-5f);
    size_t ob = (size_t)r*768u;
    #pragma unroll
    for (int p=0;p<3;++p){
        int col = t + p*256;
        float d = (p==0)?d0:((p==1)?d1:d2);
        float val = d*rstd*g[col] + b[col];
        __nv_bfloat16 h = __float2bfloat16(val);
        dstH[ob+col] = h;
        dstL[ob+col] = __float2bfloat16(val - __bfloat162float(h));
    }
}

// ---------------- geometry bias (sincos table version) ---------------------
__global__ __launch_bounds__(256) void bias_kernel(
    const float* __restrict__ wg_w, const float* __restrict__ wg_b,
    float* __restrict__ bias)
{
    __shared__ float sw[768];
    __shared__ float sc[12];
    __shared__ float st[32][8];
    __shared__ float ct[32][8];
    int t = threadIdx.x;
    for (int i=t;i<768;i+=256) sw[i]=wg_w[i];
    __syncthreads();
    if (t < 12){
        float s = wg_b[t];
        #pragma unroll
        for (int k=48;k<64;++k) s += sw[t*64+k];
        sc[t] = s;
    }
    {
        const float dm[8] = {1.0f, 0.42169650342f, 0.1778279410f, 0.074989420933f,
                             0.03162277660f, 0.013335214322f, 0.0056234132519f, 0.0023713737057f};
        int d = t >> 3, k = t & 7;
        float fd = (float)d * (1.0f/32.0f);
        float arg = 100.0f * logf(fmaxf(fd*(1.0f/1.03125f), 0.001f)) * dm[k];
        float sv, cv;
        sincosf(arg, &sv, &cv);
        st[d][k] = sv;
        ct[d][k] = cv;
    }
    __syncthreads();
    size_t idx = (size_t)blockIdx.x*256u + t;
    if (idx >= (size_t)1025u*1025u) return;
    int i = (int)(idx/1025u), j = (int)(idx - (size_t)i*1025u);
    if (i==0 || j==0){
        #pragma unroll
        for (int h=0;h<12;++h) bias[(size_t)h*1025u*1025u + idx] = 0.f;
        return;
    }
    int a = i-1, b2 = j-1;
    int dxi = abs((a>>5)-(b2>>5));
    int dyi = abs((a&31)-(b2&31));
    const float* sx = st[dxi];
    const float* cx = ct[dxi];
    const float* sy = st[dyi];
    const float* cy = ct[dyi];
    #pragma unroll
    for (int h=0;h<12;++h){
        const float* w = sw + h*64;
        float acc = sc[h];
        #pragma unroll
        for (int k=0;k<8;++k)
            acc += sx[k]*w[k] + sy[k]*w[8+k] + cx[k]*w[32+k] + cy[k]*w[40+k];
        float wv = fmaxf(acc, 0.0f);
        bias[(size_t)h*1025u*1025u + idx] = logf(fmaxf(wv, 1e-6f));
    }
}

// ---------------- temporal attention (bf16 hi/lo out) ----------------------
__global__ __launch_bounds__(256) void temporal_attn_kernel(
    const float* __restrict__ qkv,
    __nv_bfloat16* __restrict__ outH, __nv_bfloat16* __restrict__ outL)
{
    int gw = (blockIdx.x*256 + threadIdx.x) >> 5;
    int lane = threadIdx.x & 31;
    if (gw >= 2048*12) return;
    int s = gw/12, h = gw - s*12;
    size_t base = (size_t)(s*4)*2304u + h*64 + lane*2;
    float2 q[4],k[4],v[4];
    #pragma unroll
    for (int i=0;i<4;++i){
        q[i] = *(const float2*)(qkv + base + (size_t)i*2304u);
        k[i] = *(const float2*)(qkv + base + (size_t)i*2304u + 768u);
        v[i] = *(const float2*)(qkv + base + (size_t)i*2304u + 1536u);
    }
    float sc[16];
    #pragma unroll
    for (int i=0;i<4;++i)
        #pragma unroll
        for (int j=0;j<4;++j)
            sc[i*4+j] = q[i].x*k[j].x + q[i].y*k[j].y;
    #pragma unroll
    for (int t2=0;t2<16;++t2)
        #pragma unroll
        for (int off=16; off>0; off>>=1)
            sc[t2] += __shfl_xor_sync(0xffffffffu, sc[t2], off);
    #pragma unroll
    for (int i=0;i<4;++i){
        float s0=sc[i*4+0]*0.125f, s1=sc[i*4+1]*0.125f, s2=sc[i*4+2]*0.125f, s3=sc[i*4+3]*0.125f;
        float m = fmaxf(fmaxf(s0,s1),fmaxf(s2,s3));
        float e0=expf(s0-m), e1=expf(s1-m), e2=expf(s2-m), e3=expf(s3-m);
        float inv = 1.0f/(e0+e1+e2+e3);
        float ox = (e0*v[0].x + e1*v[1].x + e2*v[2].x + e3*v[3].x)*inv;
        float oy = (e0*v[0].y + e1*v[1].y + e2*v[2].y + e3*v[3].y)*inv;
        uint32_t hh, ll;
        split2(ox, oy, hh, ll);
        size_t o = (size_t)(s*4+i)*768u + h*64 + lane*2;
        *(uint32_t*)&outH[o] = hh;
        *(uint32_t*)&outL[o] = ll;
    }
}

// ---------------- combine -------------------------------------------------
__global__ __launch_bounds__(256) void combine_kernel(
    const float* __restrict__ x, const float* __restrict__ xt,
    const float* __restrict__ res_s, float* __restrict__ out)
{
    size_t idx = (size_t)blockIdx.x*256u + threadIdx.x;
    if (idx >= (size_t)2u*4097u*768u) return;
    int c = (int)(idx % 768u);
    size_t row = idx / 768u;
    int b = (int)(row / 4097u);
    int rr = (int)(row - (size_t)b*4097u);
    float v;
    if (rr == 0){
        float s = 0.f;
        #pragma unroll
        for (int t2=0;t2<4;++t2)
            s += res_s[((size_t)((b*4+t2)*1025))*768u + c];
        v = x[row*768u + c] + 0.25f*s;
    } else {
        int qq = rr-1; int n = qq>>2, t2 = qq&3;
        v = xt[((size_t)(b*4096 + qq))*768u + c]
          + res_s[((size_t)((b*4+t2)*1025 + 1 + n))*768u + c];
    }
    out[row*768u + c] = v;
}

// ---------------- launcher -------------------------------------------------
extern "C" void kernel_launch(void* const* d_in, const int* in_sizes, int n_in,
                              void* d_out, int out_size)
{
    const float* x       = (const float*)d_in[0];
    const float* norm1_g = (const float*)d_in[1];
    const float* norm1_b = (const float*)d_in[2];
    const float* qkv_w   = (const float*)d_in[3];
    const float* proj_w  = (const float*)d_in[4];
    const float* proj_b  = (const float*)d_in[5];
    const float* wg_w    = (const float*)d_in[6];
    const float* wg_b    = (const float*)d_in[7];
    const float* tnorm1_g= (const float*)d_in[8];
    const float* tnorm1_b= (const float*)d_in[9];
    const float* tqkv_w  = (const float*)d_in[10];
    const float* tproj_w = (const float*)d_in[11];
    const float* tproj_b = (const float*)d_in[12];
    const float* tfc_w   = (const float*)d_in[13];
    const float* tfc_b   = (const float*)d_in[14];
    const float* norm2_g = (const float*)d_in[15];
    const float* norm2_b = (const float*)d_in[16];
    const float* fc1_w   = (const float*)d_in[17];
    const float* fc1_b   = (const float*)d_in[18];
    const float* fc2_w   = (const float*)d_in[19];
    const float* fc2_b   = (const float*)d_in[20];
    float* out = (float*)d_out;

    float* base = nullptr;
    cudaGetSymbolAddress((void**)&base, g_scratch);
    float* p_qkv  = base + OFF_QKV;
    float* p_xt   = base + OFF_XT;
    float* p_res  = base + OFF_RES;
    float* p_bias = base + OFF_BIAS;
    __nv_bfloat16* wb = (__nv_bfloat16*)(base + OFF_WBF);
    __nv_bfloat16* bf = (__nv_bfloat16*)(base + OFF_BF);
    __nv_bfloat16 *lnH = bf+BO_LNH,  *lnL = bf+BO_LNL;
    __nv_bfloat16 *atH = bf+BO_ATTH, *atL = bf+BO_ATTL;
    __nv_bfloat16 *r2H = bf+BO_R2H,  *r2L = bf+BO_R2L;
    __nv_bfloat16 *hH  = bf+BO_HH,   *hL  = bf+BO_HL;
    __nv_bfloat16* qbh = (__nv_bfloat16*)(base + OFF_QB);
    __nv_bfloat16* qbl = qbh + 18892800u;

    cudaFuncSetAttribute(flash_mma_kernel,
                         cudaFuncAttributeMaxDynamicSharedMemorySize, FL_SMEM);
    cudaFuncSetAttribute(tgemm_nt,
                         cudaFuncAttributeMaxDynamicSharedMemorySize, TG_SMEM);

    // fused weight conversion
    wconv_all<<<2048,256>>>(tqkv_w, qkv_w, tproj_w, proj_w, tfc_w, fc1_w, fc2_w, wb);

    // ---- temporal branch ----
    ln_kernel<<<8192,256>>>(nullptr, x, lnH, lnL, tnorm1_g, tnorm1_b, 1);
    tgemm_nt<<<dim3(18,64),256,TG_SMEM>>>(lnH, lnL, wb+WO_TQKV, wb+WO_TQKV+1769472u,
        nullptr, p_qkv, nullptr, nullptr, 8192, 2304, 768, nullptr, 0, 0, 0);
    temporal_attn_kernel<<<3072,256>>>(p_qkv, atH, atL);
    tgemm_nt<<<dim3(6,64),256,TG_SMEM>>>(atH, atL, wb+WO_TPROJ, wb+WO_TPROJ+589824u,
        tproj_b, nullptr, r2H, r2L, 8192, 768, 768, nullptr, 0, 0, 0);
    tgemm_nt<<<dim3(6,64),256,TG_SMEM>>>(r2H, r2L, wb+WO_TFC, wb+WO_TFC+589824u,
        tfc_b, p_xt, nullptr, nullptr, 8192, 768, 768, x, 2, 0, 0);

    // ---- spatial branch ----
    ln_kernel<<<8200,256>>>(p_xt, x, lnH, lnL, norm1_g, norm1_b, 2);
    bias_kernel<<<4105,256>>>(wg_w, wg_b, p_bias);
    tgemm_nt<<<dim3(18,65),256,TG_SMEM>>>(lnH, lnL, wb+WO_QKV, wb+WO_QKV+1769472u,
        nullptr, nullptr, qbh, qbl, 8200, 2304, 768, nullptr, 0, 0, 1);
    flash_mma_kernel<<<dim3(9,96),256,FL_SMEM>>>(qbh, qbl, p_bias, atH, atL);
    tgemm_nt<<<dim3(6,65),256,TG_SMEM>>>(atH, atL, wb+WO_PROJ, wb+WO_PROJ+589824u,
        proj_b, p_res, nullptr, nullptr, 8200, 768, 768, nullptr, 0, 0, 0);
    combine_kernel<<<24582,256>>>(x, p_xt, p_res, out);

    // ---- MLP (chunked over 2x4097 rows) ----
    ln_kernel<<<8194,256>>>(out, nullptr, lnH, lnL, norm2_g, norm2_b, 0);
    for (int ch=0; ch<2; ++ch){
        size_t ro = (size_t)ch*4097u;
        tgemm_nt<<<dim3(24,33),256,TG_SMEM>>>(lnH + ro*768u, lnL + ro*768u,
            wb+WO_FC1, wb+WO_FC1+2359296u, fc1_b, nullptr, hH, hL,
            4097, 3072, 768, nullptr, 0, 1, 0);
        tgemm_nt<<<dim3(6,33),256,TG_SMEM>>>(hH, hL, wb+WO_FC2, wb+WO_FC2+2359296u,
            fc2_b, out + ro*768u, nullptr, nullptr, 4097, 768, 3072, out + ro*768u, 1, 0, 0);
    }
}

// round 15
// speedup vs baseline: 1.8636x; 1.1893x over previous
#include <cuda_runtime.h>
#include <cuda_bf16.h>
#include <math.h>
#include <stdint.h>

// ---------------- consolidated scratch (single symbol, ~468MB) -------------
#define OFF_QKV   0ull                       // 18,892,800 f32
#define OFF_XT    18892800ull                // 6,291,456 f32
#define OFF_RES   25184256ull                // 6,297,600 f32
#define OFF_BIAS  31481856ull                // 12,607,504 f32
#define OFF_WBF   44089360ull                // 10,027,008 f32 (weights bf16 h/l)
#define OFF_BF    54116368ull                // activation bf16 region (44,058,624 f32)
#define OFF_QB    98174992ull                // qkv bf16 hi/lo: 2*18,892,800 bf16
#define SCRATCH_TOTAL 117067792ull
__device__ float g_scratch[SCRATCH_TOTAL];

// bf16 activation offsets (in bf16 elements within OFF_BF region)
#define BO_LNH   0u
#define BO_LNL   6297600u
#define BO_ATTH  12595200u
#define BO_ATTL  18892800u
#define BO_R2H   25190400u
#define BO_R2L   31481856u
#define BO_HH    37773312u                   // 8194*3072
#define BO_HL    62945280u                   // 8194*3072

// weight offsets (bf16 elements; hi then lo contiguous)
#define WO_TQKV  0u
#define WO_QKV   3538944u
#define WO_TPROJ 7077888u
#define WO_PROJ  8257536u
#define WO_TFC   9437184u
#define WO_FC1   10616832u
#define WO_FC2   15335424u

__device__ __forceinline__ float gelu_exact(float x){
    return 0.5f*x*(1.0f+erff(x*0.70710678118654752440f));
}
__device__ __forceinline__ void split2(float a, float b, uint32_t &h, uint32_t &l){
    __nv_bfloat16 ha=__float2bfloat16(a), hb=__float2bfloat16(b);
    __nv_bfloat162 hh=__halves2bfloat162(ha,hb);
    __nv_bfloat162 ll=__halves2bfloat162(
        __float2bfloat16(a-__bfloat162float(ha)),
        __float2bfloat16(b-__bfloat162float(hb)));
    h=*(uint32_t*)&hh; l=*(uint32_t*)&ll;
}
__device__ __forceinline__ uint32_t smem_u32(const void* p){
    uint32_t a;
    asm("{ .reg .u64 t; cvta.to.shared.u64 t, %1; cvt.u32.u64 %0, t; }" : "=r"(a) : "l"(p));
    return a;
}
__device__ __forceinline__ void cp16(uint32_t dst, const void* src, int valid){
    int sz = valid ? 16 : 0;
    asm volatile("cp.async.ca.shared.global [%0], [%1], 16, %2;"
                 :: "r"(dst), "l"(src), "r"(sz) : "memory");
}
__device__ __forceinline__ void cp_commit(){ asm volatile("cp.async.commit_group;" ::: "memory"); }
__device__ __forceinline__ void cp_wait1(){ asm volatile("cp.async.wait_group 1;" ::: "memory"); }
__device__ __forceinline__ void cp_wait0(){ asm volatile("cp.async.wait_group 0;" ::: "memory"); }
__device__ __forceinline__ void ldsm4(uint32_t* r, uint32_t addr){
    asm volatile("ldmatrix.sync.aligned.m8n8.x4.shared.b16 {%0,%1,%2,%3}, [%4];"
        : "=r"(r[0]), "=r"(r[1]), "=r"(r[2]), "=r"(r[3]) : "r"(addr));
}
__device__ __forceinline__ void ldsm4t(uint32_t* r, uint32_t addr){
    asm volatile("ldmatrix.sync.aligned.m8n8.x4.trans.shared.b16 {%0,%1,%2,%3}, [%4];"
        : "=r"(r[0]), "=r"(r[1]), "=r"(r[2]), "=r"(r[3]) : "r"(addr));
}
__device__ __forceinline__ void mma_bf16(float* d, const uint32_t* a, const uint32_t* b){
    asm volatile("mma.sync.aligned.m16n8k16.row.col.f32.bf16.bf16.f32 "
        "{%0,%1,%2,%3}, {%4,%5,%6,%7}, {%8,%9}, {%0,%1,%2,%3};"
        : "+f"(d[0]), "+f"(d[1]), "+f"(d[2]), "+f"(d[3])
        : "r"(a[0]), "r"(a[1]), "r"(a[2]), "r"(a[3]), "r"(b[0]), "r"(b[1]));
}

// ---------------- fused weight fp32 -> bf16 hi/lo conversion ---------------
__global__ __launch_bounds__(256) void wconv_all(
    const float* __restrict__ w0, const float* __restrict__ w1,
    const float* __restrict__ w2, const float* __restrict__ w3,
    const float* __restrict__ w4, const float* __restrict__ w5,
    const float* __restrict__ w6, __nv_bfloat16* __restrict__ wb)
{
    const float* ws[7] = {w0,w1,w2,w3,w4,w5,w6};
    const int cum[8] = {0,1769472,3538944,4128768,4718592,5308416,7667712,10027008};
    const unsigned ho[7] = {WO_TQKV,WO_QKV,WO_TPROJ,WO_PROJ,WO_TFC,WO_FC1,WO_FC2};
    for (int i = blockIdx.x*256 + threadIdx.x; i < 10027008; i += gridDim.x*256){
        int r = 0;
        #pragma unroll
        for (int k=1;k<7;++k) if (i >= cum[k]) r = k;
        int li = i - cum[r];
        int n = cum[r+1] - cum[r];
        float v = ws[r][li];
        __nv_bfloat16 h = __float2bfloat16(v);
        wb[ho[r] + li] = h;
        wb[ho[r] + n + li] = __float2bfloat16(v - __bfloat162float(h));
    }
}

// ---------------- HMMA split-bf16 GEMM, cp.async + ldmatrix, 2 CTA/SM ------
#define TG_BUF   40960
#define TG_SMEM  (2*TG_BUF)

__global__ __launch_bounds__(256,2) void tgemm_nt(
    const __nv_bfloat16* __restrict__ Ahi, const __nv_bfloat16* __restrict__ Alo,
    const __nv_bfloat16* __restrict__ Whi, const __nv_bfloat16* __restrict__ Wlo,
    const float* __restrict__ bias,
    float* __restrict__ C, __nv_bfloat16* __restrict__ Chi, __nv_bfloat16* __restrict__ Clo,
    int M, int N, int K,
    const float* __restrict__ res, int resMode, int doGelu, int qkvSplit)
{
    extern __shared__ char smem[];
    uint32_t sb = smem_u32(smem);
    int tid = threadIdx.x;
    int wid = tid >> 5, lane = tid & 31;
    int warpM = wid >> 2, warpN = wid & 3;
    int g = lane >> 2, tg = lane & 3;
    int lrow = lane & 7, lt = lane >> 3;
    int bm = blockIdx.y*128, bn = blockIdx.x*128;

    int NC = K >> 5;

    auto stage = [&](int c, int buf){
        int k0 = c << 5;
        uint32_t bufb = sb + buf*TG_BUF;
        #pragma unroll
        for (int u = 0; u < 8; ++u){
            int idx = u*256 + tid;
            int arr = idx >> 9;
            int rem = idx & 511;
            int row = rem >> 2;
            int q = rem & 3;
            uint32_t dst = bufb + arr*10240 + row*80 + q*16;
            const __nv_bfloat16* src;
            int valid = 1;
            if (arr < 2){
                int gm = bm + row;
                valid = (gm < M);
                const __nv_bfloat16* base = (arr == 0) ? Ahi : Alo;
                src = base + (size_t)(valid ? gm : 0)*K + k0 + q*8;
            } else {
                int gn = bn + row;
                const __nv_bfloat16* base = (arr == 2) ? Whi : Wlo;
                src = base + (size_t)gn*K + k0 + q*8;
            }
            cp16(dst, src, valid);
        }
        cp_commit();
    };

    float acc[4][4][4];
    #pragma unroll
    for (int i=0;i<4;++i)
        #pragma unroll
        for (int j=0;j<4;++j)
            #pragma unroll
            for (int q=0;q<4;++q) acc[i][j][q]=0.f;

    stage(0, 0);
    for (int c = 0; c < NC; ++c){
        int buf = c & 1;
        if (c+1 < NC){ stage(c+1, buf^1); cp_wait1(); }
        else cp_wait0();
        __syncthreads();

        uint32_t bufA = sb + buf*TG_BUF;

        #pragma unroll
        for (int ks = 0; ks < 2; ++ks){
            int kb0 = ks*16;
            uint32_t ahi[4][4], alo[4][4];
            #pragma unroll
            for (int i=0;i<4;++i){
                int row = warpM*64 + i*16 + lrow + ((lt&1)<<3);
                uint32_t off = (uint32_t)(row*40 + kb0 + ((lt>>1)<<3)) << 1;
                ldsm4(ahi[i], bufA + off);
                ldsm4(alo[i], bufA + 10240 + off);
            }
            uint32_t bhi[4][2], blo[4][2];
            #pragma unroll
            for (int jp=0;jp<2;++jp){
                int row = warpN*32 + jp*16 + lrow + ((lt>>1)<<3);
                uint32_t off = (uint32_t)(row*40 + kb0 + ((lt&1)<<3)) << 1;
                uint32_t t[4];
                ldsm4(t, bufA + 20480 + off);
                bhi[jp*2][0]=t[0]; bhi[jp*2][1]=t[1];
                bhi[jp*2+1][0]=t[2]; bhi[jp*2+1][1]=t[3];
                ldsm4(t, bufA + 30720 + off);
                blo[jp*2][0]=t[0]; blo[jp*2][1]=t[1];
                blo[jp*2+1][0]=t[2]; blo[jp*2+1][1]=t[3];
            }
            #pragma unroll
            for (int i=0;i<4;++i)
                #pragma unroll
                for (int j=0;j<4;++j){
                    mma_bf16(acc[i][j], ahi[i], bhi[j]);
                    mma_bf16(acc[i][j], ahi[i], blo[j]);
                    mma_bf16(acc[i][j], alo[i], bhi[j]);
                }
        }
        __syncthreads();
    }

    #pragma unroll
    for (int i=0;i<4;++i){
        #pragma unroll
        for (int half=0; half<2; ++half){
            int m = bm + warpM*64 + i*16 + g + half*8;
            if (m >= M) continue;
            const float* rrow = nullptr;
            if (resMode == 1) rrow = res + (size_t)m*N;
            else if (resMode == 2){ int bb = m>>12, jj = m&4095; rrow = res + (size_t)(bb*4097+1+jj)*N; }
            #pragma unroll
            for (int j=0;j<4;++j){
                int n0 = bn + warpN*32 + j*8 + tg*2;
                float v0 = acc[i][j][half*2+0];
                float v1 = acc[i][j][half*2+1];
                if (bias){ float2 bv = *(const float2*)&bias[n0]; v0 += bv.x; v1 += bv.y; }
                if (doGelu){ v0 = gelu_exact(v0); v1 = gelu_exact(v1); }
                if (rrow){ float2 rv = *(const float2*)&rrow[n0]; v0 += rv.x; v1 += rv.y; }
                if (Chi){
                    if (qkvSplit && n0 < 768){ v0 *= 0.125f; v1 *= 0.125f; }
                    uint32_t hh, ll;
                    split2(v0, v1, hh, ll);
                    *(uint32_t*)&Chi[(size_t)m*N + n0] = hh;
                    *(uint32_t*)&Clo[(size_t)m*N + n0] = ll;
                } else {
                    *(float2*)&C[(size_t)m*N + n0] = make_float2(v0, v1);
                }
            }
        }
    }
}

// ---------------- HMMA flash attention v2 ----------------------------------
#define FL_QBYTES (128*72*2)           // 18432
#define FL_KVARR  (64*72*2)            // 9216
#define FL_KVBUF  (4*FL_KVARR)         // 36864
#define FL_SMEM   (2*FL_QBYTES + 2*FL_KVBUF)   // 110592

__global__ __launch_bounds__(256) void flash_mma_kernel(
    const __nv_bfloat16* __restrict__ qh, const __nv_bfloat16* __restrict__ ql,
    const float* __restrict__ bias,
    __nv_bfloat16* __restrict__ outH, __nv_bfloat16* __restrict__ outL)
{
    extern __shared__ char fsm[];
    uint32_t sb = smem_u32(fsm);
    uint32_t Qh = sb, Ql = sb + FL_QBYTES;
    uint32_t KV = sb + 2*FL_QBYTES;
    int bh = blockIdx.y, bt = bh/12, h = bh - bt*12;
    int i0 = blockIdx.x*128;
    int tid = threadIdx.x, w = tid>>5, lane = tid&31;
    int g = lane>>2, tg = lane&3;
    int lrow = lane&7, lt = lane>>3;
    size_t qbase = (size_t)(bt*1025)*2304u + h*64;

    #pragma unroll
    for (int u=0;u<8;++u){
        int idx = u*256+tid;
        int arr = idx>>10, rem = idx&1023, row = rem>>3, q = rem&7;
        int gi = i0+row;
        uint32_t dst = (arr? Ql:Qh) + row*144 + q*16;
        const __nv_bfloat16* src = (arr? ql:qh) + qbase + (size_t)(gi<1025?gi:0)*2304u + q*8;
        cp16(dst, src, gi<1025);
    }
    auto stage_kv = [&](int j0, int buf){
        uint32_t kb = KV + buf*FL_KVBUF;
        #pragma unroll
        for (int u=0;u<8;++u){
            int idx = u*256+tid;
            int arr = idx>>9, rem = idx&511, row = rem>>3, q = rem&7;
            int gj = j0+row;
            uint32_t dst = kb + arr*FL_KVARR + row*144 + q*16;
            int voff = (arr>=2)? 1536:768;
            const __nv_bfloat16* bsrc = (arr&1)? ql:qh;
            const __nv_bfloat16* src = bsrc + qbase + (size_t)(gj<1025?gj:0)*2304u + voff + q*8;
            cp16(dst, src, gj<1025);
        }
        cp_commit();
    };
    stage_kv(0,0);
    stage_kv(64,1);

    uint32_t qfh[4][4], qfl[4][4];
    float m0=-1e30f, m1=-1e30f, l0=0.f, l1=0.f;
    float o[8][4];
    #pragma unroll
    for (int d=0;d<8;++d){ o[d][0]=0.f;o[d][1]=0.f;o[d][2]=0.f;o[d][3]=0.f; }

    int gi_g = i0 + w*16 + g;
    int gi_h = gi_g + 8;
    const float* brow0 = bias + ((size_t)h*1025u + gi_g)*1025u;
    const float* brow1 = bias + ((size_t)h*1025u + gi_h)*1025u;

    for (int jt=0; jt<17; ++jt){
        if (jt < 16) cp_wait1(); else cp_wait0();
        __syncthreads();
        if (jt == 0){
            #pragma unroll
            for (int kf=0;kf<4;++kf){
                int row = w*16 + lrow + ((lt&1)<<3);
                uint32_t off = (uint32_t)(row*72 + kf*16 + ((lt>>1)<<3))<<1;
                ldsm4(qfh[kf], Qh + off);
                ldsm4(qfl[kf], Ql + off);
            }
        }
        int buf = jt & 1;
        uint32_t Kh = KV + buf*FL_KVBUF;
        uint32_t Kl = Kh + FL_KVARR;
        uint32_t Vh = Kl + FL_KVARR;
        uint32_t Vl = Vh + FL_KVARR;
        int j0 = jt*64;

        float s[8][4];
        #pragma unroll
        for (int nf=0;nf<8;++nf){ s[nf][0]=0.f;s[nf][1]=0.f;s[nf][2]=0.f;s[nf][3]=0.f; }
        #pragma unroll
        for (int kf=0; kf<4; ++kf){
            #pragma unroll
            for (int jp=0; jp<4; ++jp){
                int row = jp*16 + lrow + ((lt>>1)<<3);
                uint32_t off = (uint32_t)(row*72 + kf*16 + ((lt&1)<<3))<<1;
                uint32_t th[4], tl[4];
                ldsm4(th, Kh + off);
                ldsm4(tl, Kl + off);
                uint32_t b0h[2]={th[0],th[1]}, b1h[2]={th[2],th[3]};
                uint32_t b0l[2]={tl[0],tl[1]}, b1l[2]={tl[2],tl[3]};
                mma_bf16(s[jp*2],   qfh[kf], b0h);
                mma_bf16(s[jp*2],   qfh[kf], b0l);
                mma_bf16(s[jp*2],   qfl[kf], b0h);
                mma_bf16(s[jp*2+1], qfh[kf], b1h);
                mma_bf16(s[jp*2+1], qfh[kf], b1l);
                mma_bf16(s[jp*2+1], qfl[kf], b1h);
            }
        }
        #pragma unroll
        for (int nf=0;nf<8;++nf){
            int gj = j0 + nf*8 + tg*2;
            if (gi_g < 1025 && gj   < 1025) s[nf][0] += brow0[gj];   else s[nf][0] = -1e30f;
            if (gi_g < 1025 && gj+1 < 1025) s[nf][1] += brow0[gj+1]; else s[nf][1] = -1e30f;
            if (gi_h < 1025 && gj   < 1025) s[nf][2] += brow1[gj];   else s[nf][2] = -1e30f;
            if (gi_h < 1025 && gj+1 < 1025) s[nf][3] += brow1[gj+1]; else s[nf][3] = -1e30f;
        }
        float rm0 = -1e30f, rm1 = -1e30f;
        #pragma unroll
        for (int nf=0;nf<8;++nf){
            rm0 = fmaxf(rm0, fmaxf(s[nf][0], s[nf][1]));
            rm1 = fmaxf(rm1, fmaxf(s[nf][2], s[nf][3]));
        }
        rm0 = fmaxf(rm0, __shfl_xor_sync(0xffffffffu, rm0, 1));
        rm0 = fmaxf(rm0, __shfl_xor_sync(0xffffffffu, rm0, 2));
        rm1 = fmaxf(rm1, __shfl_xor_sync(0xffffffffu, rm1, 1));
        rm1 = fmaxf(rm1, __shfl_xor_sync(0xffffffffu, rm1, 2));
        float mn0 = fmaxf(m0, rm0), mn1 = fmaxf(m1, rm1);
        float c0 = __expf(m0 - mn0), c1 = __expf(m1 - mn1);
        m0 = mn0; m1 = mn1;
        float sum0 = 0.f, sum1 = 0.f;
        #pragma unroll
        for (int nf=0;nf<8;++nf){
            s[nf][0] = __expf(s[nf][0]-mn0);
            s[nf][1] = __expf(s[nf][1]-mn0);
            s[nf][2] = __expf(s[nf][2]-mn1);
            s[nf][3] = __expf(s[nf][3]-mn1);
            sum0 += s[nf][0] + s[nf][1];
            sum1 += s[nf][2] + s[nf][3];
        }
        sum0 += __shfl_xor_sync(0xffffffffu, sum0, 1);
        sum0 += __shfl_xor_sync(0xffffffffu, sum0, 2);
        sum1 += __shfl_xor_sync(0xffffffffu, sum1, 1);
        sum1 += __shfl_xor_sync(0xffffffffu, sum1, 2);
        l0 = l0*c0 + sum0;
        l1 = l1*c1 + sum1;
        #pragma unroll
        for (int d=0;d<8;++d){ o[d][0]*=c0; o[d][1]*=c0; o[d][2]*=c1; o[d][3]*=c1; }

        #pragma unroll
        for (int kk=0; kk<4; ++kk){
            uint32_t pah[4], pal[4];
            #pragma unroll
            for (int half=0; half<2; ++half){
                int nf = kk*2 + half;
                uint32_t h01,l01,h23,l23;
                split2(s[nf][0], s[nf][1], h01, l01);
                split2(s[nf][2], s[nf][3], h23, l23);
                pah[half*2+0] = h01;
                pah[half*2+1] = h23;
                pal[half*2+0] = l01;
                pal[half*2+1] = l23;
            }
            int mat = lane >> 3, r = lane & 7;
            int jrow = kk*16 + ((mat&1)<<3) + r;
            #pragma unroll
            for (int dp=0; dp<4; ++dp){
                int dcol = dp*16 + ((mat>>1)<<3);
                uint32_t off = (uint32_t)(jrow*72 + dcol)<<1;
                uint32_t tvh[4], tvl[4];
                ldsm4t(tvh, Vh + off);
                ldsm4t(tvl, Vl + off);
                uint32_t b0h[2]={tvh[0],tvh[1]}, b1h[2]={tvh[2],tvh[3]};
                uint32_t b0l[2]={tvl[0],tvl[1]}, b1l[2]={tvl[2],tvl[3]};
                mma_bf16(o[dp*2],   pah, b0h);
                mma_bf16(o[dp*2],   pah, b0l);
                mma_bf16(o[dp*2],   pal, b0h);
                mma_bf16(o[dp*2+1], pah, b1h);
                mma_bf16(o[dp*2+1], pah, b1l);
                mma_bf16(o[dp*2+1], pal, b1h);
            }
        }
        __syncthreads();
        if (jt+2 <= 16) stage_kv((jt+2)*64, buf);
    }

    float inv0 = 1.0f/l0, inv1 = 1.0f/l1;
    #pragma unroll
    for (int df=0; df<8; ++df){
        int d0 = df*8 + tg*2;
        if (gi_g < 1025){
            uint32_t hh, ll;
            split2(o[df][0]*inv0, o[df][1]*inv0, hh, ll);
            size_t ob = (size_t)(bt*1025+gi_g)*768u + h*64 + d0;
            *(uint32_t*)&outH[ob] = hh;
            *(uint32_t*)&outL[ob] = ll;
        }
        if (gi_h < 1025){
            uint32_t hh, ll;
            split2(o[df][2]*inv1, o[df][3]*inv1, hh, ll);
            size_t ob = (size_t)(bt*1025+gi_h)*768u + h*64 + d0;
            *(uint32_t*)&outH[ob] = hh;
            *(uint32_t*)&outL[ob] = ll;
        }
    }
}

// ---------------- layernorm (modes 1,2; bf16 hi/lo output) -----------------
__global__ __launch_bounds__(256) void ln_kernel(
    const float* __restrict__ src, const float* __restrict__ xsrc,
    __nv_bfloat16* __restrict__ dstH, __nv_bfloat16* __restrict__ dstL,
    const float* __restrict__ g, const float* __restrict__ b, int mode)
{
    __shared__ float red[8];
    int r = blockIdx.x;
    int t = threadIdx.x;
    int lane = t & 31, warp = t >> 5;
    const float* in; size_t base;
    if (mode == 0){ in = src; base = (size_t)r*768u; }
    else if (mode == 1){ int bb = r>>12; int j = r & 4095; in = xsrc; base = (size_t)(bb*4097 + 1 + j)*768u; }
    else {
        int bt = r/1025, pos = r - bt*1025;
        int bb = bt>>2, tt = bt&3;
        if (pos == 0){ in = xsrc; base = (size_t)(bb*4097)*768u; }
        else { int n = pos-1; in = src; base = (size_t)(bb*4096 + n*4 + tt)*768u; }
    }
    float v0 = in[base+t], v1 = in[base+t+256], v2 = in[base+t+512];
    float s = v0+v1+v2;
    #pragma unroll
    for (int o=16;o>0;o>>=1) s += __shfl_xor_sync(0xffffffffu, s, o);
    if (lane==0) red[warp]=s;
    __syncthreads();
    if (warp==0){
        float w = red[lane&7];
        #pragma unroll
        for (int o=4;o>0;o>>=1) w += __shfl_xor_sync(0xffffffffu, w, o);
        if (lane==0) red[0]=w;
    }
    __syncthreads();
    float mean = red[0]*(1.0f/768.0f);
    float d0=v0-mean, d1=v1-mean, d2=v2-mean;
    float q = d0*d0+d1*d1+d2*d2;
    #pragma unroll
    for (int o=16;o>0;o>>=1) q += __shfl_xor_sync(0xffffffffu, q, o);
    __syncthreads();
    if (lane==0) red[warp]=q;
    __syncthreads();
    if (warp==0){
        float w = red[lane&7];
        #pragma unroll
        for (int o=4;o>0;o>>=1) w += __shfl_xor_sync(0xffffffffu, w, o);
        if (lane==0) red[0]=w;
    }
    __syncthreads();
    float var = red[0]*(1.0f/768.0f);
    float rstd = rsqrtf(var + 1e-5f);
    size_t ob = (size_t)r*768u;
    #pragma unroll
    for (int p=0;p<3;++p){
        int col = t + p*256;
        float d = (p==0)?d0:((p==1)?d1:d2);
        float val = d*rstd*g[col] + b[col];
        __nv_bfloat16 h = __float2bfloat16(val);
        dstH[ob+col] = h;
        dstL[ob+col] = __float2bfloat16(val - __bfloat162float(h));
    }
}

// ---------------- fused combine + LN (norm2) -------------------------------
__global__ __launch_bounds__(256) void combine_ln_kernel(
    const float* __restrict__ x, const float* __restrict__ xt,
    const float* __restrict__ res_s, float* __restrict__ out,
    __nv_bfloat16* __restrict__ dstH, __nv_bfloat16* __restrict__ dstL,
    const float* __restrict__ g, const float* __restrict__ b)
{
    __shared__ float red[8];
    int r = blockIdx.x;                 // 0..8193
    int t = threadIdx.x;
    int lane = t & 31, warp = t >> 5;
    int bb = r / 4097;
    int rr = r - bb*4097;
    float v[3];
    #pragma unroll
    for (int p=0;p<3;++p){
        int c = t + p*256;
        float val;
        if (rr == 0){
            float s = 0.f;
            #pragma unroll
            for (int t2=0;t2<4;++t2)
                s += res_s[((size_t)((bb*4+t2)*1025))*768u + c];
            val = x[(size_t)r*768u + c] + 0.25f*s;
        } else {
            int qq = rr-1; int n = qq>>2, t2 = qq&3;
            val = xt[((size_t)(bb*4096 + qq))*768u + c]
                + res_s[((size_t)((bb*4+t2)*1025 + 1 + n))*768u + c];
        }
        out[(size_t)r*768u + c] = val;
        v[p] = val;
    }
    float s = v[0]+v[1]+v[2];
    #pragma unroll
    for (int o=16;o>0;o>>=1) s += __shfl_xor_sync(0xffffffffu, s, o);
    if (lane==0) red[warp]=s;
    __syncthreads();
    if (warp==0){
        float w = red[lane&7];
        #pragma unroll
        for (int o=4;o>0;o>>=1) w += __shfl_xor_sync(0xffffffffu, w, o);
        if (lane==0) red[0]=w;
    }
    __syncthreads();
    float mean = red[0]*(1.0f/768.0f);
    float d0=v[0]-mean, d1=v[1]-mean, d2=v[2]-mean;
    float q = d0*d0+d1*d1+d2*d2;
    #pragma unroll
    for (int o=16;o>0;o>>=1) q += __shfl_xor_sync(0xffffffffu, q, o);
    __syncthreads();
    if (lane==0) red[warp]=q;
    __syncthreads();
    if (warp==0){
        float w = red[lane&7];
        #pragma unroll
        for (int o=4;o>0;o>>=1) w += __shfl_xor_sync(0xffffffffu, w, o);
        if (lane==0) red[0]=w;
    }
    __syncthreads();
    float var = red[0]*(1.0f/768.0f);
    float rstd = rsqrtf(var + 1e-5f);
    size_t ob = (size_t)r*768u;
    #pragma unroll
    for (int p=0;p<3;++p){
        int col = t + p*256;
        float d = (p==0)?d0:((p==1)?d1:d2);
        float val = d*rstd*g[col] + b[col];
        __nv_bfloat16 h = __float2bfloat16(val);
        dstH[ob+col] = h;
        dstL[ob+col] = __float2bfloat16(val - __bfloat162float(h));
    }
}

// ---------------- geometry bias (sincos table version) ---------------------
__global__ __launch_bounds__(256) void bias_kernel(
    const float* __restrict__ wg_w, const float* __restrict__ wg_b,
    float* __restrict__ bias)
{
    __shared__ float sw[768];
    __shared__ float sc[12];
    __shared__ float st[32][8];
    __shared__ float ct[32][8];
    int t = threadIdx.x;
    for (int i=t;i<768;i+=256) sw[i]=wg_w[i];
    __syncthreads();
    if (t < 12){
        float s = wg_b[t];
        #pragma unroll
        for (int k=48;k<64;++k) s += sw[t*64+k];
        sc[t] = s;
    }
    {
        const float dm[8] = {1.0f, 0.42169650342f, 0.1778279410f, 0.074989420933f,
                             0.03162277660f, 0.013335214322f, 0.0056234132519f, 0.0023713737057f};
        int d = t >> 3, k = t & 7;
        float fd = (float)d * (1.0f/32.0f);
        float arg = 100.0f * logf(fmaxf(fd*(1.0f/1.03125f), 0.001f)) * dm[k];
        float sv, cv;
        sincosf(arg, &sv, &cv);
        st[d][k] = sv;
        ct[d][k] = cv;
    }
    __syncthreads();
    size_t idx = (size_t)blockIdx.x*256u + t;
    if (idx >= (size_t)1025u*1025u) return;
    int i = (int)(idx/1025u), j = (int)(idx - (size_t)i*1025u);
    if (i==0 || j==0){
        #pragma unroll
        for (int h=0;h<12;++h) bias[(size_t)h*1025u*1025u + idx] = 0.f;
        return;
    }
    int a = i-1, b2 = j-1;
    int dxi = abs((a>>5)-(b2>>5));
    int dyi = abs((a&31)-(b2&31));
    const float* sx = st[dxi];
    const float* cx = ct[dxi];
    const float* sy = st[dyi];
    const float* cy = ct[dyi];
    #pragma unroll
    for (int h=0;h<12;++h){
        const float* w = sw + h*64;
        float acc = sc[h];
        #pragma unroll
        for (int k=0;k<8;++k)
            acc += sx[k]*w[k] + sy[k]*w[8+k] + cx[k]*w[32+k] + cy[k]*w[40+k];
        float wv = fmaxf(acc, 0.0f);
        bias[(size_t)h*1025u*1025u + idx] = logf(fmaxf(wv, 1e-6f));
    }
}

// ---------------- temporal attention (bf16 hi/lo out) ----------------------
__global__ __launch_bounds__(256) void temporal_attn_kernel(
    const float* __restrict__ qkv,
    __nv_bfloat16* __restrict__ outH, __nv_bfloat16* __restrict__ outL)
{
    int gw = (blockIdx.x*256 + threadIdx.x) >> 5;
    int lane = threadIdx.x & 31;
    if (gw >= 2048*12) return;
    int s = gw/12, h = gw - s*12;
    size_t base = (size_t)(s*4)*2304u + h*64 + lane*2;
    float2 q[4],k[4],v[4];
    #pragma unroll
    for (int i=0;i<4;++i){
        q[i] = *(const float2*)(qkv + base + (size_t)i*2304u);
        k[i] = *(const float2*)(qkv + base + (size_t)i*2304u + 768u);
        v[i] = *(const float2*)(qkv + base + (size_t)i*2304u + 1536u);
    }
    float sc[16];
    #pragma unroll
    for (int i=0;i<4;++i)
        #pragma unroll
        for (int j=0;j<4;++j)
            sc[i*4+j] = q[i].x*k[j].x + q[i].y*k[j].y;
    #pragma unroll
    for (int t2=0;t2<16;++t2)
        #pragma unroll
        for (int off=16; off>0; off>>=1)
            sc[t2] += __shfl_xor_sync(0xffffffffu, sc[t2], off);
    #pragma unroll
    for (int i=0;i<4;++i){
        float s0=sc[i*4+0]*0.125f, s1=sc[i*4+1]*0.125f, s2=sc[i*4+2]*0.125f, s3=sc[i*4+3]*0.125f;
        float m = fmaxf(fmaxf(s0,s1),fmaxf(s2,s3));
        float e0=expf(s0-m), e1=expf(s1-m), e2=expf(s2-m), e3=expf(s3-m);
        float inv = 1.0f/(e0+e1+e2+e3);
        float ox = (e0*v[0].x + e1*v[1].x + e2*v[2].x + e3*v[3].x)*inv;
        float oy = (e0*v[0].y + e1*v[1].y + e2*v[2].y + e3*v[3].y)*inv;
        uint32_t hh, ll;
        split2(ox, oy, hh, ll);
        size_t o = (size_t)(s*4+i)*768u + h*64 + lane*2;
        *(uint32_t*)&outH[o] = hh;
        *(uint32_t*)&outL[o] = ll;
    }
}

// ---------------- launcher -------------------------------------------------
extern "C" void kernel_launch(void* const* d_in, const int* in_sizes, int n_in,
                              void* d_out, int out_size)
{
    const float* x       = (const float*)d_in[0];
    const float* norm1_g = (const float*)d_in[1];
    const float* norm1_b = (const float*)d_in[2];
    const float* qkv_w   = (const float*)d_in[3];
    const float* proj_w  = (const float*)d_in[4];
    const float* proj_b  = (const float*)d_in[5];
    const float* wg_w    = (const float*)d_in[6];
    const float* wg_b    = (const float*)d_in[7];
    const float* tnorm1_g= (const float*)d_in[8];
    const float* tnorm1_b= (const float*)d_in[9];
    const float* tqkv_w  = (const float*)d_in[10];
    const float* tproj_w = (const float*)d_in[11];
    const float* tproj_b = (const float*)d_in[12];
    const float* tfc_w   = (const float*)d_in[13];
    const float* tfc_b   = (const float*)d_in[14];
    const float* norm2_g = (const float*)d_in[15];
    const float* norm2_b = (const float*)d_in[16];
    const float* fc1_w   = (const float*)d_in[17];
    const float* fc1_b   = (const float*)d_in[18];
    const float* fc2_w   = (const float*)d_in[19];
    const float* fc2_b   = (const float*)d_in[20];
    float* out = (float*)d_out;

    float* base = nullptr;
    cudaGetSymbolAddress((void**)&base, g_scratch);
    float* p_qkv  = base + OFF_QKV;
    float* p_xt   = base + OFF_XT;
    float* p_res  = base + OFF_RES;
    float* p_bias = base + OFF_BIAS;
    __nv_bfloat16* wb = (__nv_bfloat16*)(base + OFF_WBF);
    __nv_bfloat16* bf = (__nv_bfloat16*)(base + OFF_BF);
    __nv_bfloat16 *lnH = bf+BO_LNH,  *lnL = bf+BO_LNL;
    __nv_bfloat16 *atH = bf+BO_ATTH, *atL = bf+BO_ATTL;
    __nv_bfloat16 *r2H = bf+BO_R2H,  *r2L = bf+BO_R2L;
    __nv_bfloat16 *hH  = bf+BO_HH,   *hL  = bf+BO_HL;
    __nv_bfloat16* qbh = (__nv_bfloat16*)(base + OFF_QB);
    __nv_bfloat16* qbl = qbh + 18892800u;

    cudaFuncSetAttribute(flash_mma_kernel,
                         cudaFuncAttributeMaxDynamicSharedMemorySize, FL_SMEM);
    cudaFuncSetAttribute(tgemm_nt,
                         cudaFuncAttributeMaxDynamicSharedMemorySize, TG_SMEM);

    // fused weight conversion
    wconv_all<<<2048,256>>>(tqkv_w, qkv_w, tproj_w, proj_w, tfc_w, fc1_w, fc2_w, wb);

    // ---- temporal branch ----
    ln_kernel<<<8192,256>>>(nullptr, x, lnH, lnL, tnorm1_g, tnorm1_b, 1);
    tgemm_nt<<<dim3(18,64),256,TG_SMEM>>>(lnH, lnL, wb+WO_TQKV, wb+WO_TQKV+1769472u,
        nullptr, p_qkv, nullptr, nullptr, 8192, 2304, 768, nullptr, 0, 0, 0);
    temporal_attn_kernel<<<3072,256>>>(p_qkv, atH, atL);
    tgemm_nt<<<dim3(6,64),256,TG_SMEM>>>(atH, atL, wb+WO_TPROJ, wb+WO_TPROJ+589824u,
        tproj_b, nullptr, r2H, r2L, 8192, 768, 768, nullptr, 0, 0, 0);
    tgemm_nt<<<dim3(6,64),256,TG_SMEM>>>(r2H, r2L, wb+WO_TFC, wb+WO_TFC+589824u,
        tfc_b, p_xt, nullptr, nullptr, 8192, 768, 768, x, 2, 0, 0);

    // ---- spatial branch ----
    ln_kernel<<<8200,256>>>(p_xt, x, lnH, lnL, norm1_g, norm1_b, 2);
    bias_kernel<<<4105,256>>>(wg_w, wg_b, p_bias);
    tgemm_nt<<<dim3(18,65),256,TG_SMEM>>>(lnH, lnL, wb+WO_QKV, wb+WO_QKV+1769472u,
        nullptr, nullptr, qbh, qbl, 8200, 2304, 768, nullptr, 0, 0, 1);
    flash_mma_kernel<<<dim3(9,96),256,FL_SMEM>>>(qbh, qbl, p_bias, atH, atL);
    tgemm_nt<<<dim3(6,65),256,TG_SMEM>>>(atH, atL, wb+WO_PROJ, wb+WO_PROJ+589824u,
        proj_b, p_res, nullptr, nullptr, 8200, 768, 768, nullptr, 0, 0, 0);

    // ---- fused combine + LN(norm2), then single-shot MLP ----
    combine_ln_kernel<<<8194,256>>>(x, p_xt, p_res, out, lnH, lnL, norm2_g, norm2_b);
    tgemm_nt<<<dim3(24,65),256,TG_SMEM>>>(lnH, lnL,
        wb+WO_FC1, wb+WO_FC1+2359296u, fc1_b, nullptr, hH, hL,
        8194, 3072, 768, nullptr, 0, 1, 0);
    tgemm_nt<<<dim3(6,65),256,TG_SMEM>>>(hH, hL, wb+WO_FC2, wb+WO_FC2+2359296u,
        fc2_b, out, nullptr, nullptr, 8194, 768, 3072, out, 1, 0, 0);
}

// round 16
// speedup vs baseline: 2.1093x; 1.1318x over previous
#include <cuda_runtime.h>
#include <cuda_bf16.h>
#include <math.h>
#include <stdint.h>

// ---------------- consolidated scratch (single symbol, ~468MB) -------------
#define OFF_QKV   0ull                       // 18,892,800 f32
#define OFF_XT    18892800ull                // 6,291,456 f32
#define OFF_RES   25184256ull                // 6,297,600 f32
#define OFF_BIAS  31481856ull                // 12,607,504 f32
#define OFF_WBF   44089360ull                // 10,027,008 f32 (weights bf16 h/l)
#define OFF_BF    54116368ull                // activation bf16 region (44,058,624 f32)
#define OFF_QB    98174992ull                // qkv bf16 hi/lo: 2*18,892,800 bf16
#define SCRATCH_TOTAL 117067792ull
__device__ float g_scratch[SCRATCH_TOTAL];

// bf16 activation offsets (in bf16 elements within OFF_BF region)
#define BO_LNH   0u
#define BO_LNL   6297600u
#define BO_ATTH  12595200u
#define BO_ATTL  18892800u
#define BO_R2H   25190400u
#define BO_R2L   31481856u
#define BO_HH    37773312u                   // 8194*3072
#define BO_HL    62945280u                   // 8194*3072

// weight offsets (bf16 elements; hi then lo contiguous)
#define WO_TQKV  0u
#define WO_QKV   3538944u
#define WO_TPROJ 7077888u
#define WO_PROJ  8257536u
#define WO_TFC   9437184u
#define WO_FC1   10616832u
#define WO_FC2   15335424u

__device__ __forceinline__ float gelu_exact(float x){
    return 0.5f*x*(1.0f+erff(x*0.70710678118654752440f));
}
__device__ __forceinline__ void split2(float a, float b, uint32_t &h, uint32_t &l){
    __nv_bfloat16 ha=__float2bfloat16(a), hb=__float2bfloat16(b);
    __nv_bfloat162 hh=__halves2bfloat162(ha,hb);
    __nv_bfloat162 ll=__halves2bfloat162(
        __float2bfloat16(a-__bfloat162float(ha)),
        __float2bfloat16(b-__bfloat162float(hb)));
    h=*(uint32_t*)&hh; l=*(uint32_t*)&ll;
}
__device__ __forceinline__ uint32_t smem_u32(const void* p){
    uint32_t a;
    asm("{ .reg .u64 t; cvta.to.shared.u64 t, %1; cvt.u32.u64 %0, t; }" : "=r"(a) : "l"(p));
    return a;
}
__device__ __forceinline__ void cp16(uint32_t dst, const void* src, int valid){
    int sz = valid ? 16 : 0;
    asm volatile("cp.async.ca.shared.global [%0], [%1], 16, %2;"
                 :: "r"(dst), "l"(src), "r"(sz) : "memory");
}
__device__ __forceinline__ void cp_commit(){ asm volatile("cp.async.commit_group;" ::: "memory"); }
__device__ __forceinline__ void cp_wait1(){ asm volatile("cp.async.wait_group 1;" ::: "memory"); }
__device__ __forceinline__ void cp_wait0(){ asm volatile("cp.async.wait_group 0;" ::: "memory"); }
__device__ __forceinline__ void ldsm4(uint32_t* r, uint32_t addr){
    asm volatile("ldmatrix.sync.aligned.m8n8.x4.shared.b16 {%0,%1,%2,%3}, [%4];"
        : "=r"(r[0]), "=r"(r[1]), "=r"(r[2]), "=r"(r[3]) : "r"(addr));
}
__device__ __forceinline__ void ldsm4t(uint32_t* r, uint32_t addr){
    asm volatile("ldmatrix.sync.aligned.m8n8.x4.trans.shared.b16 {%0,%1,%2,%3}, [%4];"
        : "=r"(r[0]), "=r"(r[1]), "=r"(r[2]), "=r"(r[3]) : "r"(addr));
}
__device__ __forceinline__ void mma_bf16(float* d, const uint32_t* a, const uint32_t* b){
    asm volatile("mma.sync.aligned.m16n8k16.row.col.f32.bf16.bf16.f32 "
        "{%0,%1,%2,%3}, {%4,%5,%6,%7}, {%8,%9}, {%0,%1,%2,%3};"
        : "+f"(d[0]), "+f"(d[1]), "+f"(d[2]), "+f"(d[3])
        : "r"(a[0]), "r"(a[1]), "r"(a[2]), "r"(a[3]), "r"(b[0]), "r"(b[1]));
}

// ---------------- fused weight fp32 -> bf16 hi/lo conversion ---------------
__global__ __launch_bounds__(256) void wconv_all(
    const float* __restrict__ w0, const float* __restrict__ w1,
    const float* __restrict__ w2, const float* __restrict__ w3,
    const float* __restrict__ w4, const float* __restrict__ w5,
    const float* __restrict__ w6, __nv_bfloat16* __restrict__ wb)
{
    const float* ws[7] = {w0,w1,w2,w3,w4,w5,w6};
    const int cum[8] = {0,1769472,3538944,4128768,4718592,5308416,7667712,10027008};
    const unsigned ho[7] = {WO_TQKV,WO_QKV,WO_TPROJ,WO_PROJ,WO_TFC,WO_FC1,WO_FC2};
    for (int i = blockIdx.x*256 + threadIdx.x; i < 10027008; i += gridDim.x*256){
        int r = 0;
        #pragma unroll
        for (int k=1;k<7;++k) if (i >= cum[k]) r = k;
        int li = i - cum[r];
        int n = cum[r+1] - cum[r];
        float v = ws[r][li];
        __nv_bfloat16 h = __float2bfloat16(v);
        wb[ho[r] + li] = h;
        wb[ho[r] + n + li] = __float2bfloat16(v - __bfloat162float(h));
    }
}

// ---------------- HMMA split-bf16 GEMM, cp.async + ldmatrix, 2 CTA/SM ------
#define TG_BUF   40960
#define TG_SMEM  (2*TG_BUF)

__global__ __launch_bounds__(256,2) void tgemm_nt(
    const __nv_bfloat16* __restrict__ Ahi, const __nv_bfloat16* __restrict__ Alo,
    const __nv_bfloat16* __restrict__ Whi, const __nv_bfloat16* __restrict__ Wlo,
    const float* __restrict__ bias,
    float* __restrict__ C, __nv_bfloat16* __restrict__ Chi, __nv_bfloat16* __restrict__ Clo,
    int M, int N, int K,
    const float* __restrict__ res, int resMode, int doGelu, int qkvSplit)
{
    extern __shared__ char smem[];
    uint32_t sb = smem_u32(smem);
    int tid = threadIdx.x;
    int wid = tid >> 5, lane = tid & 31;
    int warpM = wid >> 2, warpN = wid & 3;
    int g = lane >> 2, tg = lane & 3;
    int lrow = lane & 7, lt = lane >> 3;
    int bm = blockIdx.y*128, bn = blockIdx.x*128;

    int NC = K >> 5;

    auto stage = [&](int c, int buf){
        int k0 = c << 5;
        uint32_t bufb = sb + buf*TG_BUF;
        #pragma unroll
        for (int u = 0; u < 8; ++u){
            int idx = u*256 + tid;
            int arr = idx >> 9;
            int rem = idx & 511;
            int row = rem >> 2;
            int q = rem & 3;
            uint32_t dst = bufb + arr*10240 + row*80 + q*16;
            const __nv_bfloat16* src;
            int valid = 1;
            if (arr < 2){
                int gm = bm + row;
                valid = (gm < M);
                const __nv_bfloat16* base = (arr == 0) ? Ahi : Alo;
                src = base + (size_t)(valid ? gm : 0)*K + k0 + q*8;
            } else {
                int gn = bn + row;
                const __nv_bfloat16* base = (arr == 2) ? Whi : Wlo;
                src = base + (size_t)gn*K + k0 + q*8;
            }
            cp16(dst, src, valid);
        }
        cp_commit();
    };

    float acc[4][4][4];
    #pragma unroll
    for (int i=0;i<4;++i)
        #pragma unroll
        for (int j=0;j<4;++j)
            #pragma unroll
            for (int q=0;q<4;++q) acc[i][j][q]=0.f;

    stage(0, 0);
    for (int c = 0; c < NC; ++c){
        int buf = c & 1;
        if (c+1 < NC){ stage(c+1, buf^1); cp_wait1(); }
        else cp_wait0();
        __syncthreads();

        uint32_t bufA = sb + buf*TG_BUF;

        #pragma unroll
        for (int ks = 0; ks < 2; ++ks){
            int kb0 = ks*16;
            uint32_t ahi[4][4], alo[4][4];
            #pragma unroll
            for (int i=0;i<4;++i){
                int row = warpM*64 + i*16 + lrow + ((lt&1)<<3);
                uint32_t off = (uint32_t)(row*40 + kb0 + ((lt>>1)<<3)) << 1;
                ldsm4(ahi[i], bufA + off);
                ldsm4(alo[i], bufA + 10240 + off);
            }
            uint32_t bhi[4][2], blo[4][2];
            #pragma unroll
            for (int jp=0;jp<2;++jp){
                int row = warpN*32 + jp*16 + lrow + ((lt>>1)<<3);
                uint32_t off = (uint32_t)(row*40 + kb0 + ((lt&1)<<3)) << 1;
                uint32_t t[4];
                ldsm4(t, bufA + 20480 + off);
                bhi[jp*2][0]=t[0]; bhi[jp*2][1]=t[1];
                bhi[jp*2+1][0]=t[2]; bhi[jp*2+1][1]=t[3];
                ldsm4(t, bufA + 30720 + off);
                blo[jp*2][0]=t[0]; blo[jp*2][1]=t[1];
                blo[jp*2+1][0]=t[2]; blo[jp*2+1][1]=t[3];
            }
            #pragma unroll
            for (int i=0;i<4;++i)
                #pragma unroll
                for (int j=0;j<4;++j){
                    mma_bf16(acc[i][j], ahi[i], bhi[j]);
                    mma_bf16(acc[i][j], ahi[i], blo[j]);
                    mma_bf16(acc[i][j], alo[i], bhi[j]);
                }
        }
        __syncthreads();
    }

    #pragma unroll
    for (int i=0;i<4;++i){
        #pragma unroll
        for (int half=0; half<2; ++half){
            int m = bm + warpM*64 + i*16 + g + half*8;
            if (m >= M) continue;
            const float* rrow = nullptr;
            if (resMode == 1) rrow = res + (size_t)m*N;
            else if (resMode == 2){ int bb = m>>12, jj = m&4095; rrow = res + (size_t)(bb*4097+1+jj)*N; }
            #pragma unroll
            for (int j=0;j<4;++j){
                int n0 = bn + warpN*32 + j*8 + tg*2;
                float v0 = acc[i][j][half*2+0];
                float v1 = acc[i][j][half*2+1];
                if (bias){ float2 bv = *(const float2*)&bias[n0]; v0 += bv.x; v1 += bv.y; }
                if (doGelu){ v0 = gelu_exact(v0); v1 = gelu_exact(v1); }
                if (rrow){ float2 rv = *(const float2*)&rrow[n0]; v0 += rv.x; v1 += rv.y; }
                if (Chi){
                    if (qkvSplit && n0 < 768){ v0 *= 0.125f; v1 *= 0.125f; }
                    uint32_t hh, ll;
                    split2(v0, v1, hh, ll);
                    *(uint32_t*)&Chi[(size_t)m*N + n0] = hh;
                    *(uint32_t*)&Clo[(size_t)m*N + n0] = ll;
                } else {
                    *(float2*)&C[(size_t)m*N + n0] = make_float2(v0, v1);
                }
            }
        }
    }
}

// ---------------- HMMA flash attention v2 (2 CTA/SM) -----------------------
#define FL_QBYTES (128*72*2)           // 18432
#define FL_KVARR  (64*72*2)            // 9216
#define FL_KVBUF  (4*FL_KVARR)         // 36864
#define FL_SMEM   (2*FL_QBYTES + 2*FL_KVBUF)   // 110592

__global__ __launch_bounds__(256,2) void flash_mma_kernel(
    const __nv_bfloat16* __restrict__ qh, const __nv_bfloat16* __restrict__ ql,
    const float* __restrict__ bias,
    __nv_bfloat16* __restrict__ outH, __nv_bfloat16* __restrict__ outL)
{
    extern __shared__ char fsm[];
    uint32_t sb = smem_u32(fsm);
    uint32_t Qh = sb, Ql = sb + FL_QBYTES;
    uint32_t KV = sb + 2*FL_QBYTES;
    int bh = blockIdx.y, bt = bh/12, h = bh - bt*12;
    int i0 = blockIdx.x*128;
    int tid = threadIdx.x, w = tid>>5, lane = tid&31;
    int g = lane>>2, tg = lane&3;
    int lrow = lane&7, lt = lane>>3;
    size_t qbase = (size_t)(bt*1025)*2304u + h*64;

    #pragma unroll
    for (int u=0;u<8;++u){
        int idx = u*256+tid;
        int arr = idx>>10, rem = idx&1023, row = rem>>3, q = rem&7;
        int gi = i0+row;
        uint32_t dst = (arr? Ql:Qh) + row*144 + q*16;
        const __nv_bfloat16* src = (arr? ql:qh) + qbase + (size_t)(gi<1025?gi:0)*2304u + q*8;
        cp16(dst, src, gi<1025);
    }
    auto stage_kv = [&](int j0, int buf){
        uint32_t kb = KV + buf*FL_KVBUF;
        #pragma unroll
        for (int u=0;u<8;++u){
            int idx = u*256+tid;
            int arr = idx>>9, rem = idx&511, row = rem>>3, q = rem&7;
            int gj = j0+row;
            uint32_t dst = kb + arr*FL_KVARR + row*144 + q*16;
            int voff = (arr>=2)? 1536:768;
            const __nv_bfloat16* bsrc = (arr&1)? ql:qh;
            const __nv_bfloat16* src = bsrc + qbase + (size_t)(gj<1025?gj:0)*2304u + voff + q*8;
            cp16(dst, src, gj<1025);
        }
        cp_commit();
    };
    stage_kv(0,0);
    stage_kv(64,1);

    uint32_t qfh[4][4], qfl[4][4];
    float m0=-1e30f, m1=-1e30f, l0=0.f, l1=0.f;
    float o[8][4];
    #pragma unroll
    for (int d=0;d<8;++d){ o[d][0]=0.f;o[d][1]=0.f;o[d][2]=0.f;o[d][3]=0.f; }

    int gi_g = i0 + w*16 + g;
    int gi_h = gi_g + 8;
    const float* brow0 = bias + ((size_t)h*1025u + gi_g)*1025u;
    const float* brow1 = bias + ((size_t)h*1025u + gi_h)*1025u;

    for (int jt=0; jt<17; ++jt){
        if (jt < 16) cp_wait1(); else cp_wait0();
        __syncthreads();
        if (jt == 0){
            #pragma unroll
            for (int kf=0;kf<4;++kf){
                int row = w*16 + lrow + ((lt&1)<<3);
                uint32_t off = (uint32_t)(row*72 + kf*16 + ((lt>>1)<<3))<<1;
                ldsm4(qfh[kf], Qh + off);
                ldsm4(qfl[kf], Ql + off);
            }
        }
        int buf = jt & 1;
        uint32_t Kh = KV + buf*FL_KVBUF;
        uint32_t Kl = Kh + FL_KVARR;
        uint32_t Vh = Kl + FL_KVARR;
        uint32_t Vl = Vh + FL_KVARR;
        int j0 = jt*64;

        float s[8][4];
        #pragma unroll
        for (int nf=0;nf<8;++nf){ s[nf][0]=0.f;s[nf][1]=0.f;s[nf][2]=0.f;s[nf][3]=0.f; }
        #pragma unroll
        for (int kf=0; kf<4; ++kf){
            #pragma unroll
            for (int jp=0; jp<4; ++jp){
                int row = jp*16 + lrow + ((lt>>1)<<3);
                uint32_t off = (uint32_t)(row*72 + kf*16 + ((lt&1)<<3))<<1;
                uint32_t th[4], tl[4];
                ldsm4(th, Kh + off);
                ldsm4(tl, Kl + off);
                uint32_t b0h[2]={th[0],th[1]}, b1h[2]={th[2],th[3]};
                uint32_t b0l[2]={tl[0],tl[1]}, b1l[2]={tl[2],tl[3]};
                mma_bf16(s[jp*2],   qfh[kf], b0h);
                mma_bf16(s[jp*2],   qfh[kf], b0l);
                mma_bf16(s[jp*2],   qfl[kf], b0h);
                mma_bf16(s[jp*2+1], qfh[kf], b1h);
                mma_bf16(s[jp*2+1], qfh[kf], b1l);
                mma_bf16(s[jp*2+1], qfl[kf], b1h);
            }
        }
        #pragma unroll
        for (int nf=0;nf<8;++nf){
            int gj = j0 + nf*8 + tg*2;
            if (gi_g < 1025 && gj   < 1025) s[nf][0] += brow0[gj];   else s[nf][0] = -1e30f;
            if (gi_g < 1025 && gj+1 < 1025) s[nf][1] += brow0[gj+1]; else s[nf][1] = -1e30f;
            if (gi_h < 1025 && gj   < 1025) s[nf][2] += brow1[gj];   else s[nf][2] = -1e30f;
            if (gi_h < 1025 && gj+1 < 1025) s[nf][3] += brow1[gj+1]; else s[nf][3] = -1e30f;
        }
        float rm0 = -1e30f, rm1 = -1e30f;
        #pragma unroll
        for (int nf=0;nf<8;++nf){
            rm0 = fmaxf(rm0, fmaxf(s[nf][0], s[nf][1]));
            rm1 = fmaxf(rm1, fmaxf(s[nf][2], s[nf][3]));
        }
        rm0 = fmaxf(rm0, __shfl_xor_sync(0xffffffffu, rm0, 1));
        rm0 = fmaxf(rm0, __shfl_xor_sync(0xffffffffu, rm0, 2));
        rm1 = fmaxf(rm1, __shfl_xor_sync(0xffffffffu, rm1, 1));
        rm1 = fmaxf(rm1, __shfl_xor_sync(0xffffffffu, rm1, 2));
        float mn0 = fmaxf(m0, rm0), mn1 = fmaxf(m1, rm1);
        float c0 = __expf(m0 - mn0), c1 = __expf(m1 - mn1);
        m0 = mn0; m1 = mn1;
        float sum0 = 0.f, sum1 = 0.f;
        #pragma unroll
        for (int nf=0;nf<8;++nf){
            s[nf][0] = __expf(s[nf][0]-mn0);
            s[nf][1] = __expf(s[nf][1]-mn0);
            s[nf][2] = __expf(s[nf][2]-mn1);
            s[nf][3] = __expf(s[nf][3]-mn1);
            sum0 += s[nf][0] + s[nf][1];
            sum1 += s[nf][2] + s[nf][3];
        }
        sum0 += __shfl_xor_sync(0xffffffffu, sum0, 1);
        sum0 += __shfl_xor_sync(0xffffffffu, sum0, 2);
        sum1 += __shfl_xor_sync(0xffffffffu, sum1, 1);
        sum1 += __shfl_xor_sync(0xffffffffu, sum1, 2);
        l0 = l0*c0 + sum0;
        l1 = l1*c1 + sum1;
        #pragma unroll
        for (int d=0;d<8;++d){ o[d][0]*=c0; o[d][1]*=c0; o[d][2]*=c1; o[d][3]*=c1; }

        #pragma unroll
        for (int kk=0; kk<4; ++kk){
            uint32_t pah[4], pal[4];
            #pragma unroll
            for (int half=0; half<2; ++half){
                int nf = kk*2 + half;
                uint32_t h01,l01,h23,l23;
                split2(s[nf][0], s[nf][1], h01, l01);
                split2(s[nf][2], s[nf][3], h23, l23);
                pah[half*2+0] = h01;
                pah[half*2+1] = h23;
                pal[half*2+0] = l01;
                pal[half*2+1] = l23;
            }
            int mat = lane >> 3, r = lane & 7;
            int jrow = kk*16 + ((mat&1)<<3) + r;
            #pragma unroll
            for (int dp=0; dp<4; ++dp){
                int dcol = dp*16 + ((mat>>1)<<3);
                uint32_t off = (uint32_t)(jrow*72 + dcol)<<1;
                uint32_t tvh[4], tvl[4];
                ldsm4t(tvh, Vh + off);
                ldsm4t(tvl, Vl + off);
                uint32_t b0h[2]={tvh[0],tvh[1]}, b1h[2]={tvh[2],tvh[3]};
                uint32_t b0l[2]={tvl[0],tvl[1]}, b1l[2]={tvl[2],tvl[3]};
                mma_bf16(o[dp*2],   pah, b0h);
                mma_bf16(o[dp*2],   pah, b0l);
                mma_bf16(o[dp*2],   pal, b0h);
                mma_bf16(o[dp*2+1], pah, b1h);
                mma_bf16(o[dp*2+1], pah, b1l);
                mma_bf16(o[dp*2+1], pal, b1h);
            }
        }
        __syncthreads();
        if (jt+2 <= 16) stage_kv((jt+2)*64, buf);
    }

    float inv0 = 1.0f/l0, inv1 = 1.0f/l1;
    #pragma unroll
    for (int df=0; df<8; ++df){
        int d0 = df*8 + tg*2;
        if (gi_g < 1025){
            uint32_t hh, ll;
            split2(o[df][0]*inv0, o[df][1]*inv0, hh, ll);
            size_t ob = (size_t)(bt*1025+gi_g)*768u + h*64 + d0;
            *(uint32_t*)&outH[ob] = hh;
            *(uint32_t*)&outL[ob] = ll;
        }
        if (gi_h < 1025){
            uint32_t hh, ll;
            split2(o[df][2]*inv1, o[df][3]*inv1, hh, ll);
            size_t ob = (size_t)(bt*1025+gi_h)*768u + h*64 + d0;
            *(uint32_t*)&outH[ob] = hh;
            *(uint32_t*)&outL[ob] = ll;
        }
    }
}

// ---------------- layernorm (modes 1,2; bf16 hi/lo output) -----------------
__global__ __launch_bounds__(256) void ln_kernel(
    const float* __restrict__ src, const float* __restrict__ xsrc,
    __nv_bfloat16* __restrict__ dstH, __nv_bfloat16* __restrict__ dstL,
    const float* __restrict__ g, const float* __restrict__ b, int mode)
{
    __shared__ float red[8];
    int r = blockIdx.x;
    int t = threadIdx.x;
    int lane = t & 31, warp = t >> 5;
    const float* in; size_t base;
    if (mode == 0){ in = src; base = (size_t)r*768u; }
    else if (mode == 1){ int bb = r>>12; int j = r & 4095; in = xsrc; base = (size_t)(bb*4097 + 1 + j)*768u; }
    else {
        int bt = r/1025, pos = r - bt*1025;
        int bb = bt>>2, tt = bt&3;
        if (pos == 0){ in = xsrc; base = (size_t)(bb*4097)*768u; }
        else { int n = pos-1; in = src; base = (size_t)(bb*4096 + n*4 + tt)*768u; }
    }
    float v0 = in[base+t], v1 = in[base+t+256], v2 = in[base+t+512];
    float s = v0+v1+v2;
    #pragma unroll
    for (int o=16;o>0;o>>=1) s += __shfl_xor_sync(0xffffffffu, s, o);
    if (lane==0) red[warp]=s;
    __syncthreads();
    if (warp==0){
        float w = red[lane&7];
        #pragma unroll
        for (int o=4;o>0;o>>=1) w += __shfl_xor_sync(0xffffffffu, w, o);
        if (lane==0) red[0]=w;
    }
    __syncthreads();
    float mean = red[0]*(1.0f/768.0f);
    float d0=v0-mean, d1=v1-mean, d2=v2-mean;
    float q = d0*d0+d1*d1+d2*d2;
    #pragma unroll
    for (int o=16;o>0;o>>=1) q += __shfl_xor_sync(0xffffffffu, q, o);
    __syncthreads();
    if (lane==0) red[warp]=q;
    __syncthreads();
    if (warp==0){
        float w = red[lane&7];
        #pragma unroll
        for (int o=4;o>0;o>>=1) w += __shfl_xor_sync(0xffffffffu, w, o);
        if (lane==0) red[0]=w;
    }
    __syncthreads();
    float var = red[0]*(1.0f/768.0f);
    float rstd = rsqrtf(var + 1e-5f);
    size_t ob = (size_t)r*768u;
    #pragma unroll
    for (int p=0;p<3;++p){
        int col = t + p*256;
        float d = (p==0)?d0:((p==1)?d1:d2);
        float val = d*rstd*g[col] + b[col];
        __nv_bfloat16 h = __float2bfloat16(val);
        dstH[ob+col] = h;
        dstL[ob+col] = __float2bfloat16(val - __bfloat162float(h));
    }
}

// ---------------- fused combine + LN (norm2) -------------------------------
__global__ __launch_bounds__(256) void combine_ln_kernel(
    const float* __restrict__ x, const float* __restrict__ xt,
    const float* __restrict__ res_s, float* __restrict__ out,
    __nv_bfloat16* __restrict__ dstH, __nv_bfloat16* __restrict__ dstL,
    const float* __restrict__ g, const float* __restrict__ b)
{
    __shared__ float red[8];
    int r = blockIdx.x;                 // 0..8193
    int t = threadIdx.x;
    int lane = t & 31, warp = t >> 5;
    int bb = r / 4097;
    int rr = r - bb*4097;
    float v[3];
    #pragma unroll
    for (int p=0;p<3;++p){
        int c = t + p*256;
        float val;
        if (rr == 0){
            float s = 0.f;
            #pragma unroll
            for (int t2=0;t2<4;++t2)
                s += res_s[((size_t)((bb*4+t2)*1025))*768u + c];
            val = x[(size_t)r*768u + c] + 0.25f*s;
        } else {
            int qq = rr-1; int n = qq>>2, t2 = qq&3;
            val = xt[((size_t)(bb*4096 + qq))*768u + c]
                + res_s[((size_t)((bb*4+t2)*1025 + 1 + n))*768u + c];
        }
        out[(size_t)r*768u + c] = val;
        v[p] = val;
    }
    float s = v[0]+v[1]+v[2];
    #pragma unroll
    for (int o=16;o>0;o>>=1) s += __shfl_xor_sync(0xffffffffu, s, o);
    if (lane==0) red[warp]=s;
    __syncthreads();
    if (warp==0){
        float w = red[lane&7];
        #pragma unroll
        for (int o=4;o>0;o>>=1) w += __shfl_xor_sync(0xffffffffu, w, o);
        if (lane==0) red[0]=w;
    }
    __syncthreads();
    float mean = red[0]*(1.0f/768.0f);
    float d0=v[0]-mean, d1=v[1]-mean, d2=v[2]-mean;
    float q = d0*d0+d1*d1+d2*d2;
    #pragma unroll
    for (int o=16;o>0;o>>=1) q += __shfl_xor_sync(0xffffffffu, q, o);
    __syncthreads();
    if (lane==0) red[warp]=q;
    __syncthreads();
    if (warp==0){
        float w = red[lane&7];
        #pragma unroll
        for (int o=4;o>0;o>>=1) w += __shfl_xor_sync(0xffffffffu, w, o);
        if (lane==0) red[0]=w;
    }
    __syncthreads();
    float var = red[0]*(1.0f/768.0f);
    float rstd = rsqrtf(var + 1e-5f);
    size_t ob = (size_t)r*768u;
    #pragma unroll
    for (int p=0;p<3;++p){
        int col = t + p*256;
        float d = (p==0)?d0:((p==1)?d1:d2);
        float val = d*rstd*g[col] + b[col];
        __nv_bfloat16 h = __float2bfloat16(val);
        dstH[ob+col] = h;
        dstL[ob+col] = __float2bfloat16(val - __bfloat162float(h));
    }
}

// ---------------- geometry bias (sincos table version) ---------------------
__global__ __launch_bounds__(256) void bias_kernel(
    const float* __restrict__ wg_w, const float* __restrict__ wg_b,
    float* __restrict__ bias)
{
    __shared__ float sw[768];
    __shared__ float sc[12];
    __shared__ float st[32][8];
    __shared__ float ct[32][8];
    int t = threadIdx.x;
    for (int i=t;i<768;i+=256) sw[i]=wg_w[i];
    __syncthreads();
    if (t < 12){
        float s = wg_b[t];
        #pragma unroll
        for (int k=48;k<64;++k) s += sw[t*64+k];
        sc[t] = s;
    }
    {
        const float dm[8] = {1.0f, 0.42169650342f, 0.1778279410f, 0.074989420933f,
                             0.03162277660f, 0.013335214322f, 0.0056234132519f, 0.0023713737057f};
        int d = t >> 3, k = t & 7;
        float fd = (float)d * (1.0f/32.0f);
        float arg = 100.0f * logf(fmaxf(fd*(1.0f/1.03125f), 0.001f)) * dm[k];
        float sv, cv;
        sincosf(arg, &sv, &cv);
        st[d][k] = sv;
        ct[d][k] = cv;
    }
    __syncthreads();
    size_t idx = (size_t)blockIdx.x*256u + t;
    if (idx >= (size_t)1025u*1025u) return;
    int i = (int)(idx/1025u), j = (int)(idx - (size_t)i*1025u);
    if (i==0 || j==0){
        #pragma unroll
        for (int h=0;h<12;++h) bias[(size_t)h*1025u*1025u + idx] = 0.f;
        return;
    }
    int a = i-1, b2 = j-1;
    int dxi = abs((a>>5)-(b2>>5));
    int dyi = abs((a&31)-(b2&31));
    const float* sx = st[dxi];
    const float* cx = ct[dxi];
    const float* sy = st[dyi];
    const float* cy = ct[dyi];
    #pragma unroll
    for (int h=0;h<12;++h){
        const float* w = sw + h*64;
        float acc = sc[h];
        #pragma unroll
        for (int k=0;k<8;++k)
            acc += sx[k]*w[k] + sy[k]*w[8+k] + cx[k]*w[32+k] + cy[k]*w[40+k];
        float wv = fmaxf(acc, 0.0f);
        bias[(size_t)h*1025u*1025u + idx] = logf(fmaxf(wv, 1e-6f));
    }
}

// ---------------- temporal attention (bf16 hi/lo out) ----------------------
__global__ __launch_bounds__(256) void temporal_attn_kernel(
    const float* __restrict__ qkv,
    __nv_bfloat16* __restrict__ outH, __nv_bfloat16* __restrict__ outL)
{
    int gw = (blockIdx.x*256 + threadIdx.x) >> 5;
    int lane = threadIdx.x & 31;
    if (gw >= 2048*12) return;
    int s = gw/12, h = gw - s*12;
    size_t base = (size_t)(s*4)*2304u + h*64 + lane*2;
    float2 q[4],k[4],v[4];
    #pragma unroll
    for (int i=0;i<4;++i){
        q[i] = *(const float2*)(qkv + base + (size_t)i*2304u);
        k[i] = *(const float2*)(qkv + base + (size_t)i*2304u + 768u);
        v[i] = *(const float2*)(qkv + base + (size_t)i*2304u + 1536u);
    }
    float sc[16];
    #pragma unroll
    for (int i=0;i<4;++i)
        #pragma unroll
        for (int j=0;j<4;++j)
            sc[i*4+j] = q[i].x*k[j].x + q[i].y*k[j].y;
    #pragma unroll
    for (int t2=0;t2<16;++t2)
        #pragma unroll
        for (int off=16; off>0; off>>=1)
            sc[t2] += __shfl_xor_sync(0xffffffffu, sc[t2], off);
    #pragma unroll
    for (int i=0;i<4;++i){
        float s0=sc[i*4+0]*0.125f, s1=sc[i*4+1]*0.125f, s2=sc[i*4+2]*0.125f, s3=sc[i*4+3]*0.125f;
        float m = fmaxf(fmaxf(s0,s1),fmaxf(s2,s3));
        float e0=expf(s0-m), e1=expf(s1-m), e2=expf(s2-m), e3=expf(s3-m);
        float inv = 1.0f/(e0+e1+e2+e3);
        float ox = (e0*v[0].x + e1*v[1].x + e2*v[2].x + e3*v[3].x)*inv;
        float oy = (e0*v[0].y + e1*v[1].y + e2*v[2].y + e3*v[3].y)*inv;
        uint32_t hh, ll;
        split2(ox, oy, hh, ll);
        size_t o = (size_t)(s*4+i)*768u + h*64 + lane*2;
        *(uint32_t*)&outH[o] = hh;
        *(uint32_t*)&outL[o] = ll;
    }
}

// ---------------- launcher -------------------------------------------------
extern "C" void kernel_launch(void* const* d_in, const int* in_sizes, int n_in,
                              void* d_out, int out_size)
{
    const float* x       = (const float*)d_in[0];
    const float* norm1_g = (const float*)d_in[1];
    const float* norm1_b = (const float*)d_in[2];
    const float* qkv_w   = (const float*)d_in[3];
    const float* proj_w  = (const float*)d_in[4];
    const float* proj_b  = (const float*)d_in[5];
    const float* wg_w    = (const float*)d_in[6];
    const float* wg_b    = (const float*)d_in[7];
    const float* tnorm1_g= (const float*)d_in[8];
    const float* tnorm1_b= (const float*)d_in[9];
    const float* tqkv_w  = (const float*)d_in[10];
    const float* tproj_w = (const float*)d_in[11];
    const float* tproj_b = (const float*)d_in[12];
    const float* tfc_w   = (const float*)d_in[13];
    const float* tfc_b   = (const float*)d_in[14];
    const float* norm2_g = (const float*)d_in[15];
    const float* norm2_b = (const float*)d_in[16];
    const float* fc1_w   = (const float*)d_in[17];
    const float* fc1_b   = (const float*)d_in[18];
    const float* fc2_w   = (const float*)d_in[19];
    const float* fc2_b   = (const float*)d_in[20];
    float* out = (float*)d_out;

    float* base = nullptr;
    cudaGetSymbolAddress((void**)&base, g_scratch);
    float* p_qkv  = base + OFF_QKV;
    float* p_xt   = base + OFF_XT;
    float* p_res  = base + OFF_RES;
    float* p_bias = base + OFF_BIAS;
    __nv_bfloat16* wb = (__nv_bfloat16*)(base + OFF_WBF);
    __nv_bfloat16* bf = (__nv_bfloat16*)(base + OFF_BF);
    __nv_bfloat16 *lnH = bf+BO_LNH,  *lnL = bf+BO_LNL;
    __nv_bfloat16 *atH = bf+BO_ATTH, *atL = bf+BO_ATTL;
    __nv_bfloat16 *r2H = bf+BO_R2H,  *r2L = bf+BO_R2L;
    __nv_bfloat16 *hH  = bf+BO_HH,   *hL  = bf+BO_HL;
    __nv_bfloat16* qbh = (__nv_bfloat16*)(base + OFF_QB);
    __nv_bfloat16* qbl = qbh + 18892800u;

    cudaFuncSetAttribute(flash_mma_kernel,
                         cudaFuncAttributeMaxDynamicSharedMemorySize, FL_SMEM);
    cudaFuncSetAttribute(tgemm_nt,
                         cudaFuncAttributeMaxDynamicSharedMemorySize, TG_SMEM);

    // fused weight conversion
    wconv_all<<<2048,256>>>(tqkv_w, qkv_w, tproj_w, proj_w, tfc_w, fc1_w, fc2_w, wb);

    // ---- temporal branch ----
    ln_kernel<<<8192,256>>>(nullptr, x, lnH, lnL, tnorm1_g, tnorm1_b, 1);
    tgemm_nt<<<dim3(18,64),256,TG_SMEM>>>(lnH, lnL, wb+WO_TQKV, wb+WO_TQKV+1769472u,
        nullptr, p_qkv, nullptr, nullptr, 8192, 2304, 768, nullptr, 0, 0, 0);
    temporal_attn_kernel<<<3072,256>>>(p_qkv, atH, atL);
    tgemm_nt<<<dim3(6,64),256,TG_SMEM>>>(atH, atL, wb+WO_TPROJ, wb+WO_TPROJ+589824u,
        tproj_b, nullptr, r2H, r2L, 8192, 768, 768, nullptr, 0, 0, 0);
    tgemm_nt<<<dim3(6,64),256,TG_SMEM>>>(r2H, r2L, wb+WO_TFC, wb+WO_TFC+589824u,
        tfc_b, p_xt, nullptr, nullptr, 8192, 768, 768, x, 2, 0, 0);

    // ---- spatial branch ----
    ln_kernel<<<8200,256>>>(p_xt, x, lnH, lnL, norm1_g, norm1_b, 2);
    bias_kernel<<<4105,256>>>(wg_w, wg_b, p_bias);
    tgemm_nt<<<dim3(18,65),256,TG_SMEM>>>(lnH, lnL, wb+WO_QKV, wb+WO_QKV+1769472u,
        nullptr, nullptr, qbh, qbl, 8200, 2304, 768, nullptr, 0, 0, 1);
    flash_mma_kernel<<<dim3(9,96),256,FL_SMEM>>>(qbh, qbl, p_bias, atH, atL);
    tgemm_nt<<<dim3(6,65),256,TG_SMEM>>>(atH, atL, wb+WO_PROJ, wb+WO_PROJ+589824u,
        proj_b, p_res, nullptr, nullptr, 8200, 768, 768, nullptr, 0, 0, 0);

    // ---- fused combine + LN(norm2), then single-shot MLP ----
    combine_ln_kernel<<<8194,256>>>(x, p_xt, p_res, out, lnH, lnL, norm2_g, norm2_b);
    tgemm_nt<<<dim3(24,65),256,TG_SMEM>>>(lnH, lnL,
        wb+WO_FC1, wb+WO_FC1+2359296u, fc1_b, nullptr, hH, hL,
        8194, 3072, 768, nullptr, 0, 1, 0);
    tgemm_nt<<<dim3(6,65),256,TG_SMEM>>>(hH, hL, wb+WO_FC2, wb+WO_FC2+2359296u,
        fc2_b, out, nullptr, nullptr, 8194, 768, 3072, out, 1, 0, 0);
}

// round 17
// speedup vs baseline: 2.1431x; 1.0160x over previous
#include <cuda_runtime.h>
#include <cuda_bf16.h>
#include <math.h>
#include <stdint.h>

// ---------------- consolidated scratch (single symbol, ~473MB) -------------
#define OFF_QKV   0ull                       // 18,892,800 f32
#define OFF_XT    18892800ull                // 6,291,456 f32
#define OFF_RES   25184256ull                // 6,297,600 f32
#define OFF_BIAS  31481856ull                // 12,607,504 f32
#define OFF_WBF   44089360ull                // 10,027,008 f32 (weights bf16 h/l)
#define OFF_BF    54116368ull                // activation bf16 region (44,058,624 f32)
#define OFF_QB    98174992ull                // qkv bf16 hi/lo: 2*18,892,800 bf16
#define OFF_WCOMB 117067792ull               // 589,824 f32 (W_comb fp32)
#define OFF_WCB   117657616ull               // 2*589,824 bf16 = 589,824 f32
#define OFF_BC    118247440ull               // 768 f32
#define SCRATCH_TOTAL 118248208ull
__device__ float g_scratch[SCRATCH_TOTAL];

// bf16 activation offsets (in bf16 elements within OFF_BF region)
#define BO_LNH   0u
#define BO_LNL   6297600u
#define BO_ATTH  12595200u
#define BO_ATTL  18892800u
#define BO_HH    37773312u                   // 8194*3072
#define BO_HL    62945280u                   // 8194*3072

// weight offsets (bf16 elements; hi then lo contiguous)
#define WO_TQKV  0u
#define WO_QKV   3538944u
#define WO_TPROJ 7077888u                    // NOTE: stores tproj TRANSPOSED hi/lo
#define WO_PROJ  8257536u
#define WO_TFC   9437184u
#define WO_FC1   10616832u
#define WO_FC2   15335424u

__device__ __forceinline__ float gelu_exact(float x){
    return 0.5f*x*(1.0f+erff(x*0.70710678118654752440f));
}
__device__ __forceinline__ void split2(float a, float b, uint32_t &h, uint32_t &l){
    __nv_bfloat16 ha=__float2bfloat16(a), hb=__float2bfloat16(b);
    __nv_bfloat162 hh=__halves2bfloat162(ha,hb);
    __nv_bfloat162 ll=__halves2bfloat162(
        __float2bfloat16(a-__bfloat162float(ha)),
        __float2bfloat16(b-__bfloat162float(hb)));
    h=*(uint32_t*)&hh; l=*(uint32_t*)&ll;
}
__device__ __forceinline__ uint32_t smem_u32(const void* p){
    uint32_t a;
    asm("{ .reg .u64 t; cvta.to.shared.u64 t, %1; cvt.u32.u64 %0, t; }" : "=r"(a) : "l"(p));
    return a;
}
__device__ __forceinline__ void cp16(uint32_t dst, const void* src, int valid){
    int sz = valid ? 16 : 0;
    asm volatile("cp.async.ca.shared.global [%0], [%1], 16, %2;"
                 :: "r"(dst), "l"(src), "r"(sz) : "memory");
}
__device__ __forceinline__ void cp_commit(){ asm volatile("cp.async.commit_group;" ::: "memory"); }
__device__ __forceinline__ void cp_wait1(){ asm volatile("cp.async.wait_group 1;" ::: "memory"); }
__device__ __forceinline__ void cp_wait0(){ asm volatile("cp.async.wait_group 0;" ::: "memory"); }
__device__ __forceinline__ void ldsm4(uint32_t* r, uint32_t addr){
    asm volatile("ldmatrix.sync.aligned.m8n8.x4.shared.b16 {%0,%1,%2,%3}, [%4];"
        : "=r"(r[0]), "=r"(r[1]), "=r"(r[2]), "=r"(r[3]) : "r"(addr));
}
__device__ __forceinline__ void ldsm4t(uint32_t* r, uint32_t addr){
    asm volatile("ldmatrix.sync.aligned.m8n8.x4.trans.shared.b16 {%0,%1,%2,%3}, [%4];"
        : "=r"(r[0]), "=r"(r[1]), "=r"(r[2]), "=r"(r[3]) : "r"(addr));
}
__device__ __forceinline__ void mma_bf16(float* d, const uint32_t* a, const uint32_t* b){
    asm volatile("mma.sync.aligned.m16n8k16.row.col.f32.bf16.bf16.f32 "
        "{%0,%1,%2,%3}, {%4,%5,%6,%7}, {%8,%9}, {%0,%1,%2,%3};"
        : "+f"(d[0]), "+f"(d[1]), "+f"(d[2]), "+f"(d[3])
        : "r"(a[0]), "r"(a[1]), "r"(a[2]), "r"(a[3]), "r"(b[0]), "r"(b[1]));
}

// ---------------- fused weight fp32 -> bf16 hi/lo conversion ---------------
// tproj (r==2) is written TRANSPOSED: wb[WO_TPROJ + n*768 + k] = tproj_w[k*768+n]
__global__ __launch_bounds__(256) void wconv_all(
    const float* __restrict__ w0, const float* __restrict__ w1,
    const float* __restrict__ w2, const float* __restrict__ w3,
    const float* __restrict__ w4, const float* __restrict__ w5,
    const float* __restrict__ w6, __nv_bfloat16* __restrict__ wb)
{
    const float* ws[7] = {w0,w1,w2,w3,w4,w5,w6};
    const int cum[8] = {0,1769472,3538944,4128768,4718592,5308416,7667712,10027008};
    const unsigned ho[7] = {WO_TQKV,WO_QKV,WO_TPROJ,WO_PROJ,WO_TFC,WO_FC1,WO_FC2};
    for (int i = blockIdx.x*256 + threadIdx.x; i < 10027008; i += gridDim.x*256){
        int r = 0;
        #pragma unroll
        for (int k=1;k<7;++k) if (i >= cum[k]) r = k;
        int li = i - cum[r];
        int n = cum[r+1] - cum[r];
        float v = ws[r][li];
        __nv_bfloat16 h = __float2bfloat16(v);
        __nv_bfloat16 l = __float2bfloat16(v - __bfloat162float(h));
        int lo = li;
        if (r == 2){   // transpose tproj
            int kk = li / 768, nn = li - kk*768;
            lo = nn*768 + kk;
        }
        wb[ho[r] + lo] = h;
        wb[ho[r] + n + lo] = l;
    }
}

// ---------------- W_comb fp32 -> bf16 hi/lo split --------------------------
__global__ __launch_bounds__(256) void wcomb_split(
    const float* __restrict__ w, __nv_bfloat16* __restrict__ hi,
    __nv_bfloat16* __restrict__ lo)
{
    int i = blockIdx.x*256 + threadIdx.x;
    if (i >= 589824) return;
    float v = w[i];
    __nv_bfloat16 h = __float2bfloat16(v);
    hi[i] = h;
    lo[i] = __float2bfloat16(v - __bfloat162float(h));
}

// ---------------- bc = tfc_w @ tproj_b + tfc_b -----------------------------
__global__ __launch_bounds__(256) void bias_comb(
    const float* __restrict__ tfc_w, const float* __restrict__ tproj_b,
    const float* __restrict__ tfc_b, float* __restrict__ bc)
{
    __shared__ float red[8];
    int i = blockIdx.x;
    int t = threadIdx.x;
    int lane = t & 31, warp = t >> 5;
    float s = 0.f;
    #pragma unroll
    for (int p=0;p<3;++p){
        int k = t + p*256;
        s += tfc_w[(size_t)i*768u + k] * tproj_b[k];
    }
    #pragma unroll
    for (int o=16;o>0;o>>=1) s += __shfl_xor_sync(0xffffffffu, s, o);
    if (lane==0) red[warp]=s;
    __syncthreads();
    if (t==0){
        float w = 0.f;
        #pragma unroll
        for (int q=0;q<8;++q) w += red[q];
        bc[i] = w + tfc_b[i];
    }
}

// ---------------- HMMA split-bf16 GEMM, cp.async + ldmatrix, 2 CTA/SM ------
#define TG_BUF   40960
#define TG_SMEM  (2*TG_BUF)

__global__ __launch_bounds__(256,2) void tgemm_nt(
    const __nv_bfloat16* __restrict__ Ahi, const __nv_bfloat16* __restrict__ Alo,
    const __nv_bfloat16* __restrict__ Whi, const __nv_bfloat16* __restrict__ Wlo,
    const float* __restrict__ bias,
    float* __restrict__ C, __nv_bfloat16* __restrict__ Chi, __nv_bfloat16* __restrict__ Clo,
    int M, int N, int K,
    const float* __restrict__ res, int resMode, int doGelu, int qkvSplit)
{
    extern __shared__ char smem[];
    uint32_t sb = smem_u32(smem);
    int tid = threadIdx.x;
    int wid = tid >> 5, lane = tid & 31;
    int warpM = wid >> 2, warpN = wid & 3;
    int g = lane >> 2, tg = lane & 3;
    int lrow = lane & 7, lt = lane >> 3;
    int bm = blockIdx.y*128, bn = blockIdx.x*128;

    int NC = K >> 5;

    auto stage = [&](int c, int buf){
        int k0 = c << 5;
        uint32_t bufb = sb + buf*TG_BUF;
        #pragma unroll
        for (int u = 0; u < 8; ++u){
            int idx = u*256 + tid;
            int arr = idx >> 9;
            int rem = idx & 511;
            int row = rem >> 2;
            int q = rem & 3;
            uint32_t dst = bufb + arr*10240 + row*80 + q*16;
            const __nv_bfloat16* src;
            int valid = 1;
            if (arr < 2){
                int gm = bm + row;
                valid = (gm < M);
                const __nv_bfloat16* base = (arr == 0) ? Ahi : Alo;
                src = base + (size_t)(valid ? gm : 0)*K + k0 + q*8;
            } else {
                int gn = bn + row;
                const __nv_bfloat16* base = (arr == 2) ? Whi : Wlo;
                src = base + (size_t)gn*K + k0 + q*8;
            }
            cp16(dst, src, valid);
        }
        cp_commit();
    };

    float acc[4][4][4];
    #pragma unroll
    for (int i=0;i<4;++i)
        #pragma unroll
        for (int j=0;j<4;++j)
            #pragma unroll
            for (int q=0;q<4;++q) acc[i][j][q]=0.f;

    stage(0, 0);
    for (int c = 0; c < NC; ++c){
        int buf = c & 1;
        if (c+1 < NC){ stage(c+1, buf^1); cp_wait1(); }
        else cp_wait0();
        __syncthreads();

        uint32_t bufA = sb + buf*TG_BUF;

        #pragma unroll
        for (int ks = 0; ks < 2; ++ks){
            int kb0 = ks*16;
            uint32_t ahi[4][4], alo[4][4];
            #pragma unroll
            for (int i=0;i<4;++i){
                int row = warpM*64 + i*16 + lrow + ((lt&1)<<3);
                uint32_t off = (uint32_t)(row*40 + kb0 + ((lt>>1)<<3)) << 1;
                ldsm4(ahi[i], bufA + off);
                ldsm4(alo[i], bufA + 10240 + off);
            }
            uint32_t bhi[4][2], blo[4][2];
            #pragma unroll
            for (int jp=0;jp<2;++jp){
                int row = warpN*32 + jp*16 + lrow + ((lt>>1)<<3);
                uint32_t off = (uint32_t)(row*40 + kb0 + ((lt&1)<<3)) << 1;
                uint32_t t[4];
                ldsm4(t, bufA + 20480 + off);
                bhi[jp*2][0]=t[0]; bhi[jp*2][1]=t[1];
                bhi[jp*2+1][0]=t[2]; bhi[jp*2+1][1]=t[3];
                ldsm4(t, bufA + 30720 + off);
                blo[jp*2][0]=t[0]; blo[jp*2][1]=t[1];
                blo[jp*2+1][0]=t[2]; blo[jp*2+1][1]=t[3];
            }
            #pragma unroll
            for (int i=0;i<4;++i)
                #pragma unroll
                for (int j=0;j<4;++j){
                    mma_bf16(acc[i][j], ahi[i], bhi[j]);
                    mma_bf16(acc[i][j], ahi[i], blo[j]);
                    mma_bf16(acc[i][j], alo[i], bhi[j]);
                }
        }
        __syncthreads();
    }

    #pragma unroll
    for (int i=0;i<4;++i){
        #pragma unroll
        for (int half=0; half<2; ++half){
            int m = bm + warpM*64 + i*16 + g + half*8;
            if (m >= M) continue;
            const float* rrow = nullptr;
            if (resMode == 1) rrow = res + (size_t)m*N;
            else if (resMode == 2){ int bb = m>>12, jj = m&4095; rrow = res + (size_t)(bb*4097+1+jj)*N; }
            #pragma unroll
            for (int j=0;j<4;++j){
                int n0 = bn + warpN*32 + j*8 + tg*2;
                float v0 = acc[i][j][half*2+0];
                float v1 = acc[i][j][half*2+1];
                if (bias){ float2 bv = *(const float2*)&bias[n0]; v0 += bv.x; v1 += bv.y; }
                if (doGelu){ v0 = gelu_exact(v0); v1 = gelu_exact(v1); }
                if (rrow){ float2 rv = *(const float2*)&rrow[n0]; v0 += rv.x; v1 += rv.y; }
                if (Chi){
                    if (qkvSplit && n0 < 768){ v0 *= 0.125f; v1 *= 0.125f; }
                    uint32_t hh, ll;
                    split2(v0, v1, hh, ll);
                    *(uint32_t*)&Chi[(size_t)m*N + n0] = hh;
                    *(uint32_t*)&Clo[(size_t)m*N + n0] = ll;
                } else {
                    *(float2*)&C[(size_t)m*N + n0] = make_float2(v0, v1);
                }
            }
        }
    }
}

// ---------------- HMMA flash attention v2 (2 CTA/SM) -----------------------
#define FL_QBYTES (128*72*2)           // 18432
#define FL_KVARR  (64*72*2)            // 9216
#define FL_KVBUF  (4*FL_KVARR)         // 36864
#define FL_SMEM   (2*FL_QBYTES + 2*FL_KVBUF)   // 110592

__global__ __launch_bounds__(256,2) void flash_mma_kernel(
    const __nv_bfloat16* __restrict__ qh, const __nv_bfloat16* __restrict__ ql,
    const float* __restrict__ bias,
    __nv_bfloat16* __restrict__ outH, __nv_bfloat16* __restrict__ outL)
{
    extern __shared__ char fsm[];
    uint32_t sb = smem_u32(fsm);
    uint32_t Qh = sb, Ql = sb + FL_QBYTES;
    uint32_t KV = sb + 2*FL_QBYTES;
    int bh = blockIdx.y, bt = bh/12, h = bh - bt*12;
    int i0 = blockIdx.x*128;
    int tid = threadIdx.x, w = tid>>5, lane = tid&31;
    int g = lane>>2, tg = lane&3;
    int lrow = lane&7, lt = lane>>3;
    size_t qbase = (size_t)(bt*1025)*2304u + h*64;

    #pragma unroll
    for (int u=0;u<8;++u){
        int idx = u*256+tid;
        int arr = idx>>10, rem = idx&1023, row = rem>>3, q = rem&7;
        int gi = i0+row;
        uint32_t dst = (arr? Ql:Qh) + row*144 + q*16;
        const __nv_bfloat16* src = (arr? ql:qh) + qbase + (size_t)(gi<1025?gi:0)*2304u + q*8;
        cp16(dst, src, gi<1025);
    }
    auto stage_kv = [&](int j0, int buf){
        uint32_t kb = KV + buf*FL_KVBUF;
        #pragma unroll
        for (int u=0;u<8;++u){
            int idx = u*256+tid;
            int arr = idx>>9, rem = idx&511, row = rem>>3, q = rem&7;
            int gj = j0+row;
            uint32_t dst = kb + arr*FL_KVARR + row*144 + q*16;
            int voff = (arr>=2)? 1536:768;
            const __nv_bfloat16* bsrc = (arr&1)? ql:qh;
            const __nv_bfloat16* src = bsrc + qbase + (size_t)(gj<1025?gj:0)*2304u + voff + q*8;
            cp16(dst, src, gj<1025);
        }
        cp_commit();
    };
    stage_kv(0,0);
    stage_kv(64,1);

    uint32_t qfh[4][4], qfl[4][4];
    float m0=-1e30f, m1=-1e30f, l0=0.f, l1=0.f;
    float o[8][4];
    #pragma unroll
    for (int d=0;d<8;++d){ o[d][0]=0.f;o[d][1]=0.f;o[d][2]=0.f;o[d][3]=0.f; }

    int gi_g = i0 + w*16 + g;
    int gi_h = gi_g + 8;
    const float* brow0 = bias + ((size_t)h*1025u + gi_g)*1025u;
    const float* brow1 = bias + ((size_t)h*1025u + gi_h)*1025u;

    for (int jt=0; jt<17; ++jt){
        if (jt < 16) cp_wait1(); else cp_wait0();
        __syncthreads();
        if (jt == 0){
            #pragma unroll
            for (int kf=0;kf<4;++kf){
                int row = w*16 + lrow + ((lt&1)<<3);
                uint32_t off = (uint32_t)(row*72 + kf*16 + ((lt>>1)<<3))<<1;
                ldsm4(qfh[kf], Qh + off);
                ldsm4(qfl[kf], Ql + off);
            }
        }
        int buf = jt & 1;
        uint32_t Kh = KV + buf*FL_KVBUF;
        uint32_t Kl = Kh + FL_KVARR;
        uint32_t Vh = Kl + FL_KVARR;
        uint32_t Vl = Vh + FL_KVARR;
        int j0 = jt*64;

        float s[8][4];
        #pragma unroll
        for (int nf=0;nf<8;++nf){ s[nf][0]=0.f;s[nf][1]=0.f;s[nf][2]=0.f;s[nf][3]=0.f; }
        #pragma unroll
        for (int kf=0; kf<4; ++kf){
            #pragma unroll
            for (int jp=0; jp<4; ++jp){
                int row = jp*16 + lrow + ((lt>>1)<<3);
                uint32_t off = (uint32_t)(row*72 + kf*16 + ((lt&1)<<3))<<1;
                uint32_t th[4], tl[4];
                ldsm4(th, Kh + off);
                ldsm4(tl, Kl + off);
                uint32_t b0h[2]={th[0],th[1]}, b1h[2]={th[2],th[3]};
                uint32_t b0l[2]={tl[0],tl[1]}, b1l[2]={tl[2],tl[3]};
                mma_bf16(s[jp*2],   qfh[kf], b0h);
                mma_bf16(s[jp*2],   qfh[kf], b0l);
                mma_bf16(s[jp*2],   qfl[kf], b0h);
                mma_bf16(s[jp*2+1], qfh[kf], b1h);
                mma_bf16(s[jp*2+1], qfh[kf], b1l);
                mma_bf16(s[jp*2+1], qfl[kf], b1h);
            }
        }
        #pragma unroll
        for (int nf=0;nf<8;++nf){
            int gj = j0 + nf*8 + tg*2;
            if (gi_g < 1025 && gj   < 1025) s[nf][0] += brow0[gj];   else s[nf][0] = -1e30f;
            if (gi_g < 1025 && gj+1 < 1025) s[nf][1] += brow0[gj+1]; else s[nf][1] = -1e30f;
            if (gi_h < 1025 && gj   < 1025) s[nf][2] += brow1[gj];   else s[nf][2] = -1e30f;
            if (gi_h < 1025 && gj+1 < 1025) s[nf][3] += brow1[gj+1]; else s[nf][3] = -1e30f;
        }
        float rm0 = -1e30f, rm1 = -1e30f;
        #pragma unroll
        for (int nf=0;nf<8;++nf){
            rm0 = fmaxf(rm0, fmaxf(s[nf][0], s[nf][1]));
            rm1 = fmaxf(rm1, fmaxf(s[nf][2], s[nf][3]));
        }
        rm0 = fmaxf(rm0, __shfl_xor_sync(0xffffffffu, rm0, 1));
        rm0 = fmaxf(rm0, __shfl_xor_sync(0xffffffffu, rm0, 2));
        rm1 = fmaxf(rm1, __shfl_xor_sync(0xffffffffu, rm1, 1));
        rm1 = fmaxf(rm1, __shfl_xor_sync(0xffffffffu, rm1, 2));
        float mn0 = fmaxf(m0, rm0), mn1 = fmaxf(m1, rm1);
        float c0 = __expf(m0 - mn0), c1 = __expf(m1 - mn1);
        m0 = mn0; m1 = mn1;
        float sum0 = 0.f, sum1 = 0.f;
        #pragma unroll
        for (int nf=0;nf<8;++nf){
            s[nf][0] = __expf(s[nf][0]-mn0);
            s[nf][1] = __expf(s[nf][1]-mn0);
            s[nf][2] = __expf(s[nf][2]-mn1);
            s[nf][3] = __expf(s[nf][3]-mn1);
            sum0 += s[nf][0] + s[nf][1];
            sum1 += s[nf][2] + s[nf][3];
        }
        sum0 += __shfl_xor_sync(0xffffffffu, sum0, 1);
        sum0 += __shfl_xor_sync(0xffffffffu, sum0, 2);
        sum1 += __shfl_xor_sync(0xffffffffu, sum1, 1);
        sum1 += __shfl_xor_sync(0xffffffffu, sum1, 2);
        l0 = l0*c0 + sum0;
        l1 = l1*c1 + sum1;
        #pragma unroll
        for (int d=0;d<8;++d){ o[d][0]*=c0; o[d][1]*=c0; o[d][2]*=c1; o[d][3]*=c1; }

        #pragma unroll
        for (int kk=0; kk<4; ++kk){
            uint32_t pah[4], pal[4];
            #pragma unroll
            for (int half=0; half<2; ++half){
                int nf = kk*2 + half;
                uint32_t h01,l01,h23,l23;
                split2(s[nf][0], s[nf][1], h01, l01);
                split2(s[nf][2], s[nf][3], h23, l23);
                pah[half*2+0] = h01;
                pah[half*2+1] = h23;
                pal[half*2+0] = l01;
                pal[half*2+1] = l23;
            }
            int mat = lane >> 3, r = lane & 7;
            int jrow = kk*16 + ((mat&1)<<3) + r;
            #pragma unroll
            for (int dp=0; dp<4; ++dp){
                int dcol = dp*16 + ((mat>>1)<<3);
                uint32_t off = (uint32_t)(jrow*72 + dcol)<<1;
                uint32_t tvh[4], tvl[4];
                ldsm4t(tvh, Vh + off);
                ldsm4t(tvl, Vl + off);
                uint32_t b0h[2]={tvh[0],tvh[1]}, b1h[2]={tvh[2],tvh[3]};
                uint32_t b0l[2]={tvl[0],tvl[1]}, b1l[2]={tvl[2],tvl[3]};
                mma_bf16(o[dp*2],   pah, b0h);
                mma_bf16(o[dp*2],   pah, b0l);
                mma_bf16(o[dp*2],   pal, b0h);
                mma_bf16(o[dp*2+1], pah, b1h);
                mma_bf16(o[dp*2+1], pah, b1l);
                mma_bf16(o[dp*2+1], pal, b1h);
            }
        }
        __syncthreads();
        if (jt+2 <= 16) stage_kv((jt+2)*64, buf);
    }

    float inv0 = 1.0f/l0, inv1 = 1.0f/l1;
    #pragma unroll
    for (int df=0; df<8; ++df){
        int d0 = df*8 + tg*2;
        if (gi_g < 1025){
            uint32_t hh, ll;
            split2(o[df][0]*inv0, o[df][1]*inv0, hh, ll);
            size_t ob = (size_t)(bt*1025+gi_g)*768u + h*64 + d0;
            *(uint32_t*)&outH[ob] = hh;
            *(uint32_t*)&outL[ob] = ll;
        }
        if (gi_h < 1025){
            uint32_t hh, ll;
            split2(o[df][2]*inv1, o[df][3]*inv1, hh, ll);
            size_t ob = (size_t)(bt*1025+gi_h)*768u + h*64 + d0;
            *(uint32_t*)&outH[ob] = hh;
            *(uint32_t*)&outL[ob] = ll;
        }
    }
}

// ---------------- layernorm (modes 1,2; bf16 hi/lo output) -----------------
__global__ __launch_bounds__(256) void ln_kernel(
    const float* __restrict__ src, const float* __restrict__ xsrc,
    __nv_bfloat16* __restrict__ dstH, __nv_bfloat16* __restrict__ dstL,
    const float* __restrict__ g, const float* __restrict__ b, int mode)
{
    __shared__ float red[8];
    int r = blockIdx.x;
    int t = threadIdx.x;
    int lane = t & 31, warp = t >> 5;
    const float* in; size_t base;
    if (mode == 0){ in = src; base = (size_t)r*768u; }
    else if (mode == 1){ int bb = r>>12; int j = r & 4095; in = xsrc; base = (size_t)(bb*4097 + 1 + j)*768u; }
    else {
        int bt = r/1025, pos = r - bt*1025;
        int bb = bt>>2, tt = bt&3;
        if (pos == 0){ in = xsrc; base = (size_t)(bb*4097)*768u; }
        else { int n = pos-1; in = src; base = (size_t)(bb*4096 + n*4 + tt)*768u; }
    }
    float v0 = in[base+t], v1 = in[base+t+256], v2 = in[base+t+512];
    float s = v0+v1+v2;
    #pragma unroll
    for (int o=16;o>0;o>>=1) s += __shfl_xor_sync(0xffffffffu, s, o);
    if (lane==0) red[warp]=s;
    __syncthreads();
    if (warp==0){
        float w = red[lane&7];
        #pragma unroll
        for (int o=4;o>0;o>>=1) w += __shfl_xor_sync(0xffffffffu, w, o);
        if (lane==0) red[0]=w;
    }
    __syncthreads();
    float mean = red[0]*(1.0f/768.0f);
    float d0=v0-mean, d1=v1-mean, d2=v2-mean;
    float q = d0*d0+d1*d1+d2*d2;
    #pragma unroll
    for (int o=16;o>0;o>>=1) q += __shfl_xor_sync(0xffffffffu, q, o);
    __syncthreads();
    if (lane==0) red[warp]=q;
    __syncthreads();
    if (warp==0){
        float w = red[lane&7];
        #pragma unroll
        for (int o=4;o>0;o>>=1) w += __shfl_xor_sync(0xffffffffu, w, o);
        if (lane==0) red[0]=w;
    }
    __syncthreads();
    float var = red[0]*(1.0f/768.0f);
    float rstd = rsqrtf(var + 1e-5f);
    size_t ob = (size_t)r*768u;
    #pragma unroll
    for (int p=0;p<3;++p){
        int col = t + p*256;
        float d = (p==0)?d0:((p==1)?d1:d2);
        float val = d*rstd*g[col] + b[col];
        __nv_bfloat16 h = __float2bfloat16(val);
        dstH[ob+col] = h;
        dstL[ob+col] = __float2bfloat16(val - __bfloat162float(h));
    }
}

// ---------------- fused combine + LN (norm2) -------------------------------
__global__ __launch_bounds__(256) void combine_ln_kernel(
    const float* __restrict__ x, const float* __restrict__ xt,
    const float* __restrict__ res_s, float* __restrict__ out,
    __nv_bfloat16* __restrict__ dstH, __nv_bfloat16* __restrict__ dstL,
    const float* __restrict__ g, const float* __restrict__ b)
{
    __shared__ float red[8];
    int r = blockIdx.x;                 // 0..8193
    int t = threadIdx.x;
    int lane = t & 31, warp = t >> 5;
    int bb = r / 4097;
    int rr = r - bb*4097;
    float v[3];
    #pragma unroll
    for (int p=0;p<3;++p){
        int c = t + p*256;
        float val;
        if (rr == 0){
            float s = 0.f;
            #pragma unroll
            for (int t2=0;t2<4;++t2)
                s += res_s[((size_t)((bb*4+t2)*1025))*768u + c];
            val = x[(size_t)r*768u + c] + 0.25f*s;
        } else {
            int qq = rr-1; int n = qq>>2, t2 = qq&3;
            val = xt[((size_t)(bb*4096 + qq))*768u + c]
                + res_s[((size_t)((bb*4+t2)*1025 + 1 + n))*768u + c];
        }
        out[(size_t)r*768u + c] = val;
        v[p] = val;
    }
    float s = v[0]+v[1]+v[2];
    #pragma unroll
    for (int o=16;o>0;o>>=1) s += __shfl_xor_sync(0xffffffffu, s, o);
    if (lane==0) red[warp]=s;
    __syncthreads();
    if (warp==0){
        float w = red[lane&7];
        #pragma unroll
        for (int o=4;o>0;o>>=1) w += __shfl_xor_sync(0xffffffffu, w, o);
        if (lane==0) red[0]=w;
    }
    __syncthreads();
    float mean = red[0]*(1.0f/768.0f);
    float d0=v[0]-mean, d1=v[1]-mean, d2=v[2]-mean;
    float q = d0*d0+d1*d1+d2*d2;
    #pragma unroll
    for (int o=16;o>0;o>>=1) q += __shfl_xor_sync(0xffffffffu, q, o);
    __syncthreads();
    if (lane==0) red[warp]=q;
    __syncthreads();
    if (warp==0){
        float w = red[lane&7];
        #pragma unroll
        for (int o=4;o>0;o>>=1) w += __shfl_xor_sync(0xffffffffu, w, o);
        if (lane==0) red[0]=w;
    }
    __syncthreads();
    float var = red[0]*(1.0f/768.0f);
    float rstd = rsqrtf(var + 1e-5f);
    size_t ob = (size_t)r*768u;
    #pragma unroll
    for (int p=0;p<3;++p){
        int col = t + p*256;
        float d = (p==0)?d0:((p==1)?d1:d2);
        float val = d*rstd*g[col] + b[col];
        __nv_bfloat16 h = __float2bfloat16(val);
        dstH[ob+col] = h;
        dstL[ob+col] = __float2bfloat16(val - __bfloat162float(h));
    }
}

// ---------------- geometry bias (sincos table version) ---------------------
__global__ __launch_bounds__(256) void bias_kernel(
    const float* __restrict__ wg_w, const float* __restrict__ wg_b,
    float* __restrict__ bias)
{
    __shared__ float sw[768];
    __shared__ float sc[12];
    __shared__ float st[32][8];
    __shared__ float ct[32][8];
    int t = threadIdx.x;
    for (int i=t;i<768;i+=256) sw[i]=wg_w[i];
    __syncthreads();
    if (t < 12){
        float s = wg_b[t];
        #pragma unroll
        for (int k=48;k<64;++k) s += sw[t*64+k];
        sc[t] = s;
    }
    {
        const float dm[8] = {1.0f, 0.42169650342f, 0.1778279410f, 0.074989420933f,
                             0.03162277660f, 0.013335214322f, 0.0056234132519f, 0.0023713737057f};
        int d = t >> 3, k = t & 7;
        float fd = (float)d * (1.0f/32.0f);
        float arg = 100.0f * logf(fmaxf(fd*(1.0f/1.03125f), 0.001f)) * dm[k];
        float sv, cv;
        sincosf(arg, &sv, &cv);
        st[d][k] = sv;
        ct[d][k] = cv;
    }
    __syncthreads();
    size_t idx = (size_t)blockIdx.x*256u + t;
    if (idx >= (size_t)1025u*1025u) return;
    int i = (int)(idx/1025u), j = (int)(idx - (size_t)i*1025u);
    if (i==0 || j==0){
        #pragma unroll
        for (int h=0;h<12;++h) bias[(size_t)h*1025u*1025u + idx] = 0.f;
        return;
    }
    int a = i-1, b2 = j-1;
    int dxi = abs((a>>5)-(b2>>5));
    int dyi = abs((a&31)-(b2&31));
    const float* sx = st[dxi];
    const float* cx = ct[dxi];
    const float* sy = st[dyi];
    const float* cy = ct[dyi];
    #pragma unroll
    for (int h=0;h<12;++h){
        const float* w = sw + h*64;
        float acc = sc[h];
        #pragma unroll
        for (int k=0;k<8;++k)
            acc += sx[k]*w[k] + sy[k]*w[8+k] + cx[k]*w[32+k] + cy[k]*w[40+k];
        float wv = fmaxf(acc, 0.0f);
        bias[(size_t)h*1025u*1025u + idx] = logf(fmaxf(wv, 1e-6f));
    }
}

// ---------------- temporal attention (bf16 hi/lo out) ----------------------
__global__ __launch_bounds__(256) void temporal_attn_kernel(
    const float* __restrict__ qkv,
    __nv_bfloat16* __restrict__ outH, __nv_bfloat16* __restrict__ outL)
{
    int gw = (blockIdx.x*256 + threadIdx.x) >> 5;
    int lane = threadIdx.x & 31;
    if (gw >= 2048*12) return;
    int s = gw/12, h = gw - s*12;
    size_t base = (size_t)(s*4)*2304u + h*64 + lane*2;
    float2 q[4],k[4],v[4];
    #pragma unroll
    for (int i=0;i<4;++i){
        q[i] = *(const float2*)(qkv + base + (size_t)i*2304u);
        k[i] = *(const float2*)(qkv + base + (size_t)i*2304u + 768u);
        v[i] = *(const float2*)(qkv + base + (size_t)i*2304u + 1536u);
    }
    float sc[16];
    #pragma unroll
    for (int i=0;i<4;++i)
        #pragma unroll
        for (int j=0;j<4;++j)
            sc[i*4+j] = q[i].x*k[j].x + q[i].y*k[j].y;
    #pragma unroll
    for (int t2=0;t2<16;++t2)
        #pragma unroll
        for (int off=16; off>0; off>>=1)
            sc[t2] += __shfl_xor_sync(0xffffffffu, sc[t2], off);
    #pragma unroll
    for (int i=0;i<4;++i){
        float s0=sc[i*4+0]*0.125f, s1=sc[i*4+1]*0.125f, s2=sc[i*4+2]*0.125f, s3=sc[i*4+3]*0.125f;
        float m = fmaxf(fmaxf(s0,s1),fmaxf(s2,s3));
        float e0=expf(s0-m), e1=expf(s1-m), e2=expf(s2-m), e3=expf(s3-m);
        float inv = 1.0f/(e0+e1+e2+e3);
        float ox = (e0*v[0].x + e1*v[1].x + e2*v[2].x + e3*v[3].x)*inv;
        float oy = (e0*v[0].y + e1*v[1].y + e2*v[2].y + e3*v[3].y)*inv;
        uint32_t hh, ll;
        split2(ox, oy, hh, ll);
        size_t o = (size_t)(s*4+i)*768u + h*64 + lane*2;
        *(uint32_t*)&outH[o] = hh;
        *(uint32_t*)&outL[o] = ll;
    }
}

// ---------------- launcher -------------------------------------------------
extern "C" void kernel_launch(void* const* d_in, const int* in_sizes, int n_in,
                              void* d_out, int out_size)
{
    const float* x       = (const float*)d_in[0];
    const float* norm1_g = (const float*)d_in[1];
    const float* norm1_b = (const float*)d_in[2];
    const float* qkv_w   = (const float*)d_in[3];
    const float* proj_w  = (const float*)d_in[4];
    const float* proj_b  = (const float*)d_in[5];
    const float* wg_w    = (const float*)d_in[6];
    const float* wg_b    = (const float*)d_in[7];
    const float* tnorm1_g= (const float*)d_in[8];
    const float* tnorm1_b= (const float*)d_in[9];
    const float* tqkv_w  = (const float*)d_in[10];
    const float* tproj_w = (const float*)d_in[11];
    const float* tproj_b = (const float*)d_in[12];
    const float* tfc_w   = (const float*)d_in[13];
    const float* tfc_b   = (const float*)d_in[14];
    const float* norm2_g = (const float*)d_in[15];
    const float* norm2_b = (const float*)d_in[16];
    const float* fc1_w   = (const float*)d_in[17];
    const float* fc1_b   = (const float*)d_in[18];
    const float* fc2_w   = (const float*)d_in[19];
    const float* fc2_b   = (const float*)d_in[20];
    float* out = (float*)d_out;

    float* base = nullptr;
    cudaGetSymbolAddress((void**)&base, g_scratch);
    float* p_qkv  = base + OFF_QKV;
    float* p_xt   = base + OFF_XT;
    float* p_res  = base + OFF_RES;
    float* p_bias = base + OFF_BIAS;
    float* p_wcomb= base + OFF_WCOMB;
    float* p_bc   = base + OFF_BC;
    __nv_bfloat16* wb = (__nv_bfloat16*)(base + OFF_WBF);
    __nv_bfloat16* bf = (__nv_bfloat16*)(base + OFF_BF);
    __nv_bfloat16 *lnH = bf+BO_LNH,  *lnL = bf+BO_LNL;
    __nv_bfloat16 *atH = bf+BO_ATTH, *atL = bf+BO_ATTL;
    __nv_bfloat16 *hH  = bf+BO_HH,   *hL  = bf+BO_HL;
    __nv_bfloat16* qbh = (__nv_bfloat16*)(base + OFF_QB);
    __nv_bfloat16* qbl = qbh + 18892800u;
    __nv_bfloat16* wcbH = (__nv_bfloat16*)(base + OFF_WCB);
    __nv_bfloat16* wcbL = wcbH + 589824u;

    cudaFuncSetAttribute(flash_mma_kernel,
                         cudaFuncAttributeMaxDynamicSharedMemorySize, FL_SMEM);
    cudaFuncSetAttribute(tgemm_nt,
                         cudaFuncAttributeMaxDynamicSharedMemorySize, TG_SMEM);

    // fused weight conversion (tproj transposed), then W_comb = tfc @ tproj
    wconv_all<<<2048,256>>>(tqkv_w, qkv_w, tproj_w, proj_w, tfc_w, fc1_w, fc2_w, wb);
    tgemm_nt<<<dim3(6,6),256,TG_SMEM>>>(wb+WO_TFC, wb+WO_TFC+589824u,
        wb+WO_TPROJ, wb+WO_TPROJ+589824u, nullptr, p_wcomb, nullptr, nullptr,
        768, 768, 768, nullptr, 0, 0, 0);
    wcomb_split<<<2304,256>>>(p_wcomb, wcbH, wcbL);
    bias_comb<<<768,256>>>(tfc_w, tproj_b, tfc_b, p_bc);

    // ---- temporal branch (tproj+tfc fused into W_comb) ----
    ln_kernel<<<8192,256>>>(nullptr, x, lnH, lnL, tnorm1_g, tnorm1_b, 1);
    tgemm_nt<<<dim3(18,64),256,TG_SMEM>>>(lnH, lnL, wb+WO_TQKV, wb+WO_TQKV+1769472u,
        nullptr, p_qkv, nullptr, nullptr, 8192, 2304, 768, nullptr, 0, 0, 0);
    temporal_attn_kernel<<<3072,256>>>(p_qkv, atH, atL);
    tgemm_nt<<<dim3(6,64),256,TG_SMEM>>>(atH, atL, wcbH, wcbL,
        p_bc, p_xt, nullptr, nullptr, 8192, 768, 768, x, 2, 0, 0);

    // ---- spatial branch ----
    ln_kernel<<<8200,256>>>(p_xt, x, lnH, lnL, norm1_g, norm1_b, 2);
    bias_kernel<<<4105,256>>>(wg_w, wg_b, p_bias);
    tgemm_nt<<<dim3(18,65),256,TG_SMEM>>>(lnH, lnL, wb+WO_QKV, wb+WO_QKV+1769472u,
        nullptr, nullptr, qbh, qbl, 8200, 2304, 768, nullptr, 0, 0, 1);
    flash_mma_kernel<<<dim3(9,96),256,FL_SMEM>>>(qbh, qbl, p_bias, atH, atL);
    tgemm_nt<<<dim3(6,65),256,TG_SMEM>>>(atH, atL, wb+WO_PROJ, wb+WO_PROJ+589824u,
        proj_b, p_res, nullptr, nullptr, 8200, 768, 768, nullptr, 0, 0, 0);

    // ---- fused combine + LN(norm2), then single-shot MLP ----
    combine_ln_kernel<<<8194,256>>>(x, p_xt, p_res, out, lnH, lnL, norm2_g, norm2_b);
    tgemm_nt<<<dim3(24,65),256,TG_SMEM>>>(lnH, lnL,
        wb+WO_FC1, wb+WO_FC1+2359296u, fc1_b, nullptr, hH, hL,
        8194, 3072, 768, nullptr, 0, 1, 0);
    tgemm_nt<<<dim3(6,65),256,TG_SMEM>>>(hH, hL, wb+WO_FC2, wb+WO_FC2+2359296u,
        fc2_b, out, nullptr, nullptr, 8194, 768, 3072, out, 1, 0, 0);
}